// round 5
// baseline (speedup 1.0000x reference)
#include <cuda_runtime.h>
#include <cuda_bf16.h>
#include <math.h>

#define S 2048
#define DMODEL 1024
#define DFF 2048
#define NH 8
#define DK 128
#define NLAYERS 4

static __device__ __forceinline__ float neg_inf() { return __int_as_float(0xff800000); }
#define SCALE_F 0.08838834764831845f  // 1/sqrt(128)

// ----------------------------- scratch (device globals; no allocation) -----
__device__ float g_x[S * DMODEL];
__device__ float g_q[S * DMODEL];
__device__ float g_k[S * DMODEL];
__device__ float g_v[S * DMODEL];
__device__ float g_ctx[S * DMODEL];
__device__ float g_h[S * DFF];
__device__ float g_y[S * DMODEL];
__device__ float g_vmean[DMODEL];
__device__ int g_isglob[S];
__device__ int g_mask[S];      // 0 pad, 1 local, 2 global
__device__ int g_globlist[64];
__device__ int g_nglob;

// ----------------------------- reductions ----------------------------------
static __device__ __forceinline__ float warpAllSum(float v) {
#pragma unroll
    for (int o = 16; o; o >>= 1) v += __shfl_xor_sync(0xffffffffu, v, o);
    return v;
}
static __device__ __forceinline__ float warpAllMax(float v) {
#pragma unroll
    for (int o = 16; o; o >>= 1) v = fmaxf(v, __shfl_xor_sync(0xffffffffu, v, o));
    return v;
}
static __device__ __forceinline__ float blockSum256(float v) {
    __shared__ float sh[8];
    int lane = threadIdx.x & 31, w = threadIdx.x >> 5;
    v = warpAllSum(v);
    __syncthreads();
    if (lane == 0) sh[w] = v;
    __syncthreads();
    if (w == 0) {
        float t = (lane < 8) ? sh[lane] : 0.f;
        t = warpAllSum(t);
        if (lane == 0) sh[0] = t;
    }
    __syncthreads();
    return sh[0];
}
static __device__ __forceinline__ float blockMax256(float v) {
    __shared__ float sh[8];
    int lane = threadIdx.x & 31, w = threadIdx.x >> 5;
    v = warpAllMax(v);
    __syncthreads();
    if (lane == 0) sh[w] = v;
    __syncthreads();
    if (w == 0) {
        float t = (lane < 8) ? sh[lane] : neg_inf();
        t = warpAllMax(t);
        if (lane == 0) sh[0] = t;
    }
    __syncthreads();
    return sh[0];
}

// ----------------------------- prep: x = 2*enc + sinusoidal PE --------------
__global__ void prep_kernel(const float* __restrict__ enc) {
    int idx = blockIdx.x * 256 + threadIdx.x;
    int s = idx >> 10, d = idx & 1023;
    double div = exp(-((double)(d & ~1)) * (9.210340371976184 / 1024.0));
    double ang = (double)s * div;
    float pe = (d & 1) ? (float)cos(ang) : (float)sin(ang);
    g_x[idx] = 2.0f * enc[idx] + pe;
}

// ----------------------------- mask build ----------------------------------
__global__ void mask_zero_kernel() {
    int i = blockIdx.x * 256 + threadIdx.x;
    if (i < S) g_isglob[i] = 0;
}
__global__ void mask_scatter_kernel(const int* __restrict__ gidx) {
    int t = threadIdx.x;
    if (t < 32) {
        int g = gidx[t] / 15;
        if (g >= 0 && g < S) g_isglob[g] = 1;
    }
}
__global__ void mask_build_kernel(const int* __restrict__ Tp) {
    int i = blockIdx.x * 256 + threadIdx.x;
    if (i < S) {
        int T = *Tp;
        g_mask[i] = g_isglob[i] ? 2 : (i < T ? 1 : 0);
    }
}
__global__ void mask_list_kernel() {  // deterministic, ordered list
    if (threadIdx.x == 0) {
        int c = 0;
        for (int s = 0; s < S; s++)
            if (g_mask[s] == 2) g_globlist[c++] = s;
        g_nglob = c;
    }
}

// ----------------------------- SGEMM: C = A@B (+ReLU), up to 3 per launch ---
// BM=BN=128, BK=8, TM=TN=8, 256 threads.
template <bool RELU>
__global__ __launch_bounds__(256, 2) void sgemm3(
    int M, int N, int K, const float* __restrict__ A,
    const float* __restrict__ B0, const float* __restrict__ B1, const float* __restrict__ B2,
    float* __restrict__ C0, float* __restrict__ C1, float* __restrict__ C2) {
    const float* B;
    float* C;
    int z = blockIdx.z;
    if (z == 0) { B = B0; C = C0; }
    else if (z == 1) { B = B1; C = C1; }
    else { B = B2; C = C2; }

    __shared__ float As[8][128];
    __shared__ float Bs[8][128];
    const int tid = threadIdx.x;
    const int brow = blockIdx.y * 128, bcol = blockIdx.x * 128;
    const int aRow = tid >> 1, aCol = (tid & 1) << 2;
    const int bRow = tid >> 5, bCol = (tid & 31) << 2;
    const float* Ap = A + (size_t)(brow + aRow) * K + aCol;
    const float* Bp = B + (size_t)bRow * N + bcol + bCol;
    const int tr = (tid >> 4) << 3, tc = (tid & 15) << 3;

    float acc[8][8];
#pragma unroll
    for (int i = 0; i < 8; i++)
#pragma unroll
        for (int j = 0; j < 8; j++) acc[i][j] = 0.f;

    for (int k0 = 0; k0 < K; k0 += 8) {
        float4 a4 = *(const float4*)Ap;
        float4 b4 = *(const float4*)Bp;
        Ap += 8;
        Bp += (size_t)8 * N;
        As[aCol + 0][aRow] = a4.x;
        As[aCol + 1][aRow] = a4.y;
        As[aCol + 2][aRow] = a4.z;
        As[aCol + 3][aRow] = a4.w;
        *(float4*)&Bs[bRow][bCol] = b4;
        __syncthreads();
#pragma unroll
        for (int kk = 0; kk < 8; kk++) {
            float rm[8], rn[8];
            *(float4*)&rm[0] = *(const float4*)&As[kk][tr];
            *(float4*)&rm[4] = *(const float4*)&As[kk][tr + 4];
            *(float4*)&rn[0] = *(const float4*)&Bs[kk][tc];
            *(float4*)&rn[4] = *(const float4*)&Bs[kk][tc + 4];
#pragma unroll
            for (int i = 0; i < 8; i++)
#pragma unroll
                for (int j = 0; j < 8; j++) acc[i][j] += rm[i] * rn[j];
        }
        __syncthreads();
    }
#pragma unroll
    for (int i = 0; i < 8; i++) {
        float* Crow = C + (size_t)(brow + tr + i) * N + bcol + tc;
        float4 o0, o1;
        float v;
        v = acc[i][0]; o0.x = RELU ? fmaxf(v, 0.f) : v;
        v = acc[i][1]; o0.y = RELU ? fmaxf(v, 0.f) : v;
        v = acc[i][2]; o0.z = RELU ? fmaxf(v, 0.f) : v;
        v = acc[i][3]; o0.w = RELU ? fmaxf(v, 0.f) : v;
        v = acc[i][4]; o1.x = RELU ? fmaxf(v, 0.f) : v;
        v = acc[i][5]; o1.y = RELU ? fmaxf(v, 0.f) : v;
        v = acc[i][6]; o1.z = RELU ? fmaxf(v, 0.f) : v;
        v = acc[i][7]; o1.w = RELU ? fmaxf(v, 0.f) : v;
        *(float4*)Crow = o0;
        *(float4*)(Crow + 4) = o1;
    }
}

// ----------------------------- LayerNorm: out = LN(y + x) -------------------
__global__ __launch_bounds__(256) void ln_kernel(
    const float* __restrict__ y, const float* __restrict__ xin,
    const float* __restrict__ g, const float* __restrict__ b, float* __restrict__ out) {
    int s = blockIdx.x, tid = threadIdx.x;
    const float* yr = y + (size_t)s * DMODEL;
    const float* xr = xin + (size_t)s * DMODEL;
    float v[4];
    float sum = 0.f;
#pragma unroll
    for (int i = 0; i < 4; i++) {
        int d = tid + (i << 8);
        v[i] = yr[d] + xr[d];
        sum += v[i];
    }
    float mean = blockSum256(sum) * (1.f / 1024.f);
    float sq = 0.f;
#pragma unroll
    for (int i = 0; i < 4; i++) {
        float t = v[i] - mean;
        sq += t * t;
    }
    float var = blockSum256(sq) * (1.f / 1024.f);
    float inv = 1.f / sqrtf(var + 1e-5f);
    float* orow = out + (size_t)s * DMODEL;
#pragma unroll
    for (int i = 0; i < 4; i++) {
        int d = tid + (i << 8);
        orow[d] = g[d] * (v[i] - mean) * inv + b[d];
    }
}

// ----------------------------- attention: V column mean (for pad rows) ------
__global__ void vmean_kernel() {
    int d = blockIdx.x * 256 + threadIdx.x;
    float acc = 0.f;
#pragma unroll 4
    for (int s = 0; s < S; s++) acc += g_v[(size_t)s * DMODEL + d];
    g_vmean[d] = acc * (1.f / (float)S);
}
__global__ void attn_pad_kernel() {
    int s = blockIdx.y;
    if (g_mask[s] != 0) return;
    int d = blockIdx.x * 256 + threadIdx.x;
    g_ctx[(size_t)s * DMODEL + d] = g_vmean[d];
}

// ----------------------------- attention: local rows (windowed+globals) -----
// 32-query tile per (block, head); candidates = window [q0-32,q0+63] (96) +
// globals outside it (<=32) => <=128. Skipping disallowed keys is exactly
// equivalent to the -1e9 mask (expf underflows to 0).
#define SMEM_LOCAL_BYTES (((128 * 129 * 2 + 32 * 128 * 2) * 4) + 128 * 4)
__global__ __launch_bounds__(256) void attn_local_kernel() {
    extern __shared__ float sm[];
    float* Ks = sm;                  // 128 x pitch129
    float* Vs = Ks + 128 * 129;      // 128 x pitch129
    float* Qs = Vs + 128 * 129;      // 32 x 128
    float* probs = Qs + 32 * 128;    // 32 x 128
    int* cand = (int*)(probs + 32 * 128);
    __shared__ int s_nc;

    int tid = threadIdx.x;
    int h = blockIdx.y, q0 = blockIdx.x * 32, base = h * DK;

    if (tid < 96) {
        int k = q0 - 32 + tid;
        cand[tid] = (k >= 0 && k < S) ? k : -1;
    }
    if (tid == 0) {
        int cnt = 96, ng = g_nglob;
        for (int i = 0; i < ng; i++) {
            int g = g_globlist[i];
            if (g < q0 - 32 || g > q0 + 63) cand[cnt++] = g;
        }
        s_nc = cnt;
    }
    __syncthreads();
    int nc = s_nc;

    for (int e = tid; e < 128 * 128; e += 256) {
        int j = e >> 7, d = e & 127;
        int k = (j < nc) ? cand[j] : -1;
        float kv = 0.f, vv = 0.f;
        if (k >= 0) {
            kv = g_k[(size_t)k * DMODEL + base + d];
            vv = g_v[(size_t)k * DMODEL + base + d];
        }
        Ks[j * 129 + d] = kv;
        Vs[j * 129 + d] = vv;
    }
    for (int e = tid; e < 32 * 128; e += 256) {
        int r = e >> 7, d = e & 127;
        Qs[e] = g_q[(size_t)(q0 + r) * DMODEL + base + d];
    }
    __syncthreads();

    int warp = tid >> 5, lane = tid & 31;
    const float NI = neg_inf();
#pragma unroll
    for (int rr = 0; rr < 4; rr++) {
        int r = warp * 4 + rr, q = q0 + r;
        bool active = (g_mask[q] == 1);
        float sv[4];
#pragma unroll
        for (int m = 0; m < 4; m++) {
            int j = lane + (m << 5);
            float val = NI;
            if (active && j < nc) {
                int k = cand[j];
                if (k >= 0) {
                    int mk = g_mask[k];
                    int dd = q - k;
                    if (dd < 0) dd = -dd;
                    bool ok = (mk != 0) && ((j >= 96) || (mk == 2) || (dd <= 32));
                    if (ok) {
                        float sd = 0.f;
                        const float* qp = &Qs[r * 128];
                        const float* kp = &Ks[j * 129];
#pragma unroll 16
                        for (int d = 0; d < 128; d++) sd += qp[d] * kp[d];
                        val = sd * SCALE_F;
                    }
                }
            }
            sv[m] = val;
        }
        float mx = fmaxf(fmaxf(sv[0], sv[1]), fmaxf(sv[2], sv[3]));
#pragma unroll
        for (int o = 16; o; o >>= 1) mx = fmaxf(mx, __shfl_xor_sync(0xffffffffu, mx, o));
        float p[4];
        float sum = 0.f;
#pragma unroll
        for (int m = 0; m < 4; m++) {
            p[m] = (sv[m] == NI) ? 0.f : expf(sv[m] - mx);
            sum += p[m];
        }
#pragma unroll
        for (int o = 16; o; o >>= 1) sum += __shfl_xor_sync(0xffffffffu, sum, o);
        if (active) {
            float inv = 1.f / sum;
#pragma unroll
            for (int m = 0; m < 4; m++) {
                int j = lane + (m << 5);
                probs[r * 128 + j] = p[m] * inv;
            }
        }
    }
    __syncthreads();
    for (int e = tid; e < 32 * 128; e += 256) {
        int r = e >> 7, d = e & 127;
        int q = q0 + r;
        if (g_mask[q] != 1) continue;
        float acc = 0.f;
        const float* pr = &probs[r * 128];
#pragma unroll 4
        for (int j = 0; j < nc; j++) acc += pr[j] * Vs[j * 129 + d];
        g_ctx[(size_t)q * DMODEL + base + d] = acc;
    }
}

// ----------------------------- attention: global rows ----------------------
#define SMEM_GLOBAL_BYTES ((128 * 129 + 128 + 2048) * 4)
__global__ __launch_bounds__(256) void attn_global_kernel() {
    int i = blockIdx.x;
    int ng = g_nglob;
    if (i >= ng) return;
    int q = g_globlist[i], h = blockIdx.y, base = h * DK;

    extern __shared__ float sm[];
    float* Ks = sm;              // 128 x pitch129
    float* qv = Ks + 128 * 129;  // 128
    float* s_all = qv + 128;     // 2048
    int tid = threadIdx.x;
    const float NI = neg_inf();

    if (tid < 128) qv[tid] = g_q[(size_t)q * DMODEL + base + tid];
    __syncthreads();

    for (int kt = 0; kt < 16; kt++) {
        for (int e = tid; e < 128 * 128; e += 256) {
            int j = e >> 7, d = e & 127;
            Ks[j * 129 + d] = g_k[(size_t)(kt * 128 + j) * DMODEL + base + d];
        }
        __syncthreads();
        if (tid < 128) {
            int k = kt * 128 + tid;
            float val = NI;
            if (g_mask[k] != 0) {
                float sd = 0.f;
                const float* kp = &Ks[tid * 129];
#pragma unroll 16
                for (int d = 0; d < 128; d++) sd += qv[d] * kp[d];
                val = sd * SCALE_F;
            }
            s_all[k] = val;
        }
        __syncthreads();
    }
    float mx = NI;
    for (int k = tid; k < S; k += 256) mx = fmaxf(mx, s_all[k]);
    mx = blockMax256(mx);
    float sum = 0.f;
    for (int k = tid; k < S; k += 256) {
        float v2 = s_all[k];
        float p = (v2 == NI) ? 0.f : expf(v2 - mx);
        s_all[k] = p;
        sum += p;
    }
    sum = blockSum256(sum);
    float inv = 1.f / sum;
    if (tid < 128) {
        int d = tid;
        float acc = 0.f;
#pragma unroll 4
        for (int k = 0; k < S; k++) acc += s_all[k] * g_v[(size_t)k * DMODEL + base + d];
        g_ctx[(size_t)q * DMODEL + base + d] = acc * inv;
    }
}

// ----------------------------- driver --------------------------------------
extern "C" void kernel_launch(void* const* d_in, const int* in_sizes, int n_in,
                              void* d_out, int out_size) {
    const int* Tp = (const int*)d_in[0];
    const float* enc = (const float*)d_in[1];
    const int* gidx = (const int*)d_in[2];
    const float* Wq = (const float*)d_in[3];
    const float* Wk = (const float*)d_in[4];
    const float* Wv = (const float*)d_in[5];
    const float* Wo = (const float*)d_in[6];
    const float* ln1g = (const float*)d_in[7];
    const float* ln1b = (const float*)d_in[8];
    const float* W1 = (const float*)d_in[9];
    const float* W2 = (const float*)d_in[10];
    const float* ln2g = (const float*)d_in[11];
    const float* ln2b = (const float*)d_in[12];
    float* out = (float*)d_out;

    cudaFuncSetAttribute(attn_local_kernel, cudaFuncAttributeMaxDynamicSharedMemorySize,
                         SMEM_LOCAL_BYTES);
    cudaFuncSetAttribute(attn_global_kernel, cudaFuncAttributeMaxDynamicSharedMemorySize,
                         SMEM_GLOBAL_BYTES);

    float *px, *pq, *pk, *pv, *pctx, *ph, *py;
    cudaGetSymbolAddress((void**)&px, g_x);
    cudaGetSymbolAddress((void**)&pq, g_q);
    cudaGetSymbolAddress((void**)&pk, g_k);
    cudaGetSymbolAddress((void**)&pv, g_v);
    cudaGetSymbolAddress((void**)&pctx, g_ctx);
    cudaGetSymbolAddress((void**)&ph, g_h);
    cudaGetSymbolAddress((void**)&py, g_y);

    mask_zero_kernel<<<8, 256>>>();
    mask_scatter_kernel<<<1, 32>>>(gidx);
    mask_build_kernel<<<8, 256>>>(Tp);
    mask_list_kernel<<<1, 32>>>();
    prep_kernel<<<(S * DMODEL) / 256, 256>>>(enc);

    for (int l = 0; l < NLAYERS; l++) {
        const float* wq = Wq + (size_t)l * DMODEL * DMODEL;
        const float* wk = Wk + (size_t)l * DMODEL * DMODEL;
        const float* wv = Wv + (size_t)l * DMODEL * DMODEL;
        const float* wo = Wo + (size_t)l * DMODEL * DMODEL;
        const float* w1 = W1 + (size_t)l * DMODEL * DFF;
        const float* w2 = W2 + (size_t)l * DFF * DMODEL;

        // fused Q/K/V projections (z = 3)
        sgemm3<false><<<dim3(DMODEL / 128, S / 128, 3), 256>>>(
            S, DMODEL, DMODEL, px, wq, wk, wv, pq, pk, pv);

        vmean_kernel<<<DMODEL / 256, 256>>>();
        attn_local_kernel<<<dim3(S / 32, NH), 256, SMEM_LOCAL_BYTES>>>();
        attn_global_kernel<<<dim3(32, NH), 256, SMEM_GLOBAL_BYTES>>>();
        attn_pad_kernel<<<dim3(DMODEL / 256, S), 256>>>();

        // output projection + residual LayerNorm
        sgemm3<false><<<dim3(DMODEL / 128, S / 128, 1), 256>>>(
            S, DMODEL, DMODEL, pctx, wo, nullptr, nullptr, py, nullptr, nullptr);
        ln_kernel<<<S, 256>>>(py, px, ln1g + l * DMODEL, ln1b + l * DMODEL, px);

        // FFN with fused ReLU, then residual LayerNorm (last layer writes d_out)
        sgemm3<true><<<dim3(DFF / 128, S / 128, 1), 256>>>(
            S, DFF, DMODEL, px, w1, nullptr, nullptr, ph, nullptr, nullptr);
        sgemm3<false><<<dim3(DMODEL / 128, S / 128, 1), 256>>>(
            S, DMODEL, DFF, ph, w2, nullptr, nullptr, py, nullptr, nullptr);
        ln_kernel<<<S, 256>>>(py, px, ln2g + l * DMODEL, ln2b + l * DMODEL,
                              (l == NLAYERS - 1) ? out : px);
    }
}

// round 7
// speedup vs baseline: 2.1402x; 2.1402x over previous
#include <cuda_runtime.h>
#include <cuda_bf16.h>
#include <math.h>
#include <stdint.h>

#define S 2048
#define DMODEL 1024
#define DFF 2048
#define NH 8
#define DK 128
#define NLAYERS 4

static __device__ __forceinline__ float neg_inf() { return __int_as_float(0xff800000); }
#define SCALE_F 0.08838834764831845f  // 1/sqrt(128)

// ======================= PTX helpers (base sm_80+ features only) ============
__device__ __forceinline__ uint32_t smem_u32(const void* p) {
    uint32_t a;
    asm("{ .reg .u64 t; cvta.to.shared.u64 t, %1; cvt.u32.u64 %0, t; }" : "=r"(a) : "l"(p));
    return a;
}
__device__ __forceinline__ void cp16(uint32_t dst, const void* src) {
    asm volatile("cp.async.cg.shared.global [%0], [%1], 16;" ::"r"(dst), "l"(src));
}
#define CP_COMMIT() asm volatile("cp.async.commit_group;" ::: "memory")
#define CP_WAIT1() asm volatile("cp.async.wait_group 1;" ::: "memory")
#define CP_WAIT0() asm volatile("cp.async.wait_group 0;" ::: "memory")

__device__ __forceinline__ void ldmx4(uint32_t* r, uint32_t addr) {
    asm volatile("ldmatrix.sync.aligned.m8n8.x4.shared.b16 {%0,%1,%2,%3}, [%4];"
                 : "=r"(r[0]), "=r"(r[1]), "=r"(r[2]), "=r"(r[3])
                 : "r"(addr));
}
__device__ __forceinline__ void mma16816(float* d, const uint32_t* a, const uint32_t* b) {
    asm volatile(
        "mma.sync.aligned.m16n8k16.row.col.f32.bf16.bf16.f32 "
        "{%0,%1,%2,%3}, {%4,%5,%6,%7}, {%8,%9}, {%0,%1,%2,%3};"
        : "+f"(d[0]), "+f"(d[1]), "+f"(d[2]), "+f"(d[3])
        : "r"(a[0]), "r"(a[1]), "r"(a[2]), "r"(a[3]), "r"(b[0]), "r"(b[1]));
}

// ============================ scratch globals ===============================
__device__ float g_x[S * DMODEL];
__device__ float g_q[S * DMODEL];
__device__ float g_k[S * DMODEL];
__device__ float g_v[S * DMODEL];
__device__ float g_ctx[S * DMODEL];
__device__ float g_h[S * DFF];
__device__ float g_y[S * DMODEL];
__device__ float g_vmean[DMODEL];
__device__ float g_vpart[16][DMODEL];
__device__ int g_isglob[S];
__device__ int g_mask[S];  // 0 pad, 1 local, 2 global
__device__ int g_globlist[64];
__device__ int g_nglob;
__device__ float g_divhi[512];
__device__ float g_divlo[512];

#define LSTRIDE (8 * 1024 * 1024)  // per-layer transposed-weight stride (elems)
__device__ __nv_bfloat16 g_wt_hi[NLAYERS * LSTRIDE];
__device__ __nv_bfloat16 g_wt_lo[NLAYERS * LSTRIDE];
__device__ __nv_bfloat16 g_ah[S * DFF];
__device__ __nv_bfloat16 g_al[S * DFF];

// ============================ reductions ====================================
static __device__ __forceinline__ float warpAllSum(float v) {
#pragma unroll
    for (int o = 16; o; o >>= 1) v += __shfl_xor_sync(0xffffffffu, v, o);
    return v;
}
static __device__ __forceinline__ float warpAllMax(float v) {
#pragma unroll
    for (int o = 16; o; o >>= 1) v = fmaxf(v, __shfl_xor_sync(0xffffffffu, v, o));
    return v;
}
static __device__ __forceinline__ float blockSum256(float v) {
    __shared__ float sh[8];
    int lane = threadIdx.x & 31, w = threadIdx.x >> 5;
    v = warpAllSum(v);
    __syncthreads();
    if (lane == 0) sh[w] = v;
    __syncthreads();
    if (w == 0) {
        float t = (lane < 8) ? sh[lane] : 0.f;
        t = warpAllSum(t);
        if (lane == 0) sh[0] = t;
    }
    __syncthreads();
    return sh[0];
}
static __device__ __forceinline__ float blockMax256(float v) {
    __shared__ float sh[8];
    int lane = threadIdx.x & 31, w = threadIdx.x >> 5;
    v = warpAllMax(v);
    __syncthreads();
    if (lane == 0) sh[w] = v;
    __syncthreads();
    if (w == 0) {
        float t = (lane < 8) ? sh[lane] : neg_inf();
        t = warpAllMax(t);
        if (lane == 0) sh[0] = t;
    }
    __syncthreads();
    return sh[0];
}

// ============================ prep / mask ===================================
// 512-entry table of exp(-2i * ln(1e4)/1024) in double, split hi/lo fp32.
__global__ void pediv_kernel() {
    int i = blockIdx.x * 256 + threadIdx.x;
    if (i < 512) {
        double dv = exp(-(double)(2 * i) * (9.210340371976184 / 1024.0));
        float h = (float)dv;
        g_divhi[i] = h;
        g_divlo[i] = (float)(dv - (double)h);
    }
}
__global__ void prep_kernel(const float* __restrict__ enc) {
    int idx = blockIdx.x * 256 + threadIdx.x;
    int s = idx >> 10, d = idx & 1023;
    int i = d >> 1;
    float hi = g_divhi[i], lo = g_divlo[i];
    float sf = (float)s;
    float h = sf * hi;
    float e = fmaf(sf, hi, -h);
    float t = fmaf(sf, lo, e);  // angle = h + t (2-float)
    // reduce mod 2*pi
    const float P2HI = 6.28318548202514648f;
    const float P2LO = -1.74845553e-7f;
    float n = rintf(h * 0.15915494309189535f);
    float r = fmaf(-n, P2HI, h);
    r = fmaf(-n, P2LO, r);
    r += t;
    float pe = (d & 1) ? cosf(r) : sinf(r);
    g_x[idx] = 2.0f * enc[idx] + pe;
}
__global__ void mask_zero_kernel() {
    int i = blockIdx.x * 256 + threadIdx.x;
    if (i < S) g_isglob[i] = 0;
}
__global__ void mask_scatter_kernel(const int* __restrict__ gidx) {
    int t = threadIdx.x;
    if (t < 32) {
        int g = gidx[t] / 15;
        if (g >= 0 && g < S) g_isglob[g] = 1;
    }
}
__global__ void mask_build_kernel(const int* __restrict__ Tp) {
    int i = blockIdx.x * 256 + threadIdx.x;
    if (i < S) {
        int T = *Tp;
        g_mask[i] = g_isglob[i] ? 2 : (i < T ? 1 : 0);
    }
}
__global__ void mask_list_kernel() {  // warp-ballot prefix scan, deterministic order
    int lane = threadIdx.x;
    int cnt = 0;
    for (int base = 0; base < S; base += 32) {
        int m = (g_mask[base + lane] == 2);
        unsigned bal = __ballot_sync(0xffffffffu, m);
        if (m) g_globlist[cnt + __popc(bal & ((1u << lane) - 1u))] = base + lane;
        cnt += __popc(bal);
    }
    if (lane == 0) g_nglob = cnt;
}

// ============================ bf16 split / transpose ========================
__global__ void split_kernel(const float* __restrict__ src, __nv_bfloat16* __restrict__ hi,
                             __nv_bfloat16* __restrict__ lo, int n4) {
    int i = blockIdx.x * 256 + threadIdx.x;
    if (i >= n4) return;
    float4 v = ((const float4*)src)[i];
    union { __nv_bfloat16 b[4]; uint2 u; } H, L;
    H.b[0] = __float2bfloat16(v.x);
    H.b[1] = __float2bfloat16(v.y);
    H.b[2] = __float2bfloat16(v.z);
    H.b[3] = __float2bfloat16(v.w);
    L.b[0] = __float2bfloat16(v.x - __bfloat162float(H.b[0]));
    L.b[1] = __float2bfloat16(v.y - __bfloat162float(H.b[1]));
    L.b[2] = __float2bfloat16(v.z - __bfloat162float(H.b[2]));
    L.b[3] = __float2bfloat16(v.w - __bfloat162float(H.b[3]));
    ((uint2*)hi)[i] = H.u;
    ((uint2*)lo)[i] = L.u;
}
// W (K x N) -> WT hi/lo (N x K), split
__global__ void tsplit_kernel(const float* __restrict__ W, __nv_bfloat16* __restrict__ hi,
                              __nv_bfloat16* __restrict__ lo, int K, int N) {
    __shared__ float t[32][33];
    int k0 = blockIdx.y * 32, n0 = blockIdx.x * 32;
    int tx = threadIdx.x, ty = threadIdx.y;
#pragma unroll
    for (int i = 0; i < 32; i += 8) t[ty + i][tx] = W[(size_t)(k0 + ty + i) * N + n0 + tx];
    __syncthreads();
#pragma unroll
    for (int i = 0; i < 32; i += 8) {
        float x = t[tx][ty + i];
        __nv_bfloat16 h = __float2bfloat16(x);
        size_t o = (size_t)(n0 + ty + i) * K + k0 + tx;
        hi[o] = h;
        lo[o] = __float2bfloat16(x - __bfloat162float(h));
    }
}

// ============================ bf16x3 HMMA GEMM ==============================
// C[M,N] = A[M,K] @ W[K,N], A as hi/lo row-major (M x K), B as W^T hi/lo (N x K).
// Tile 128x128, BK=32, double-buffered cp.async, 8 warps (64x32 each).
#define TSTRIDE 80                   // smem bytes per 32-elem bf16 row (padded)
#define TILE_B (128 * TSTRIDE)       // 10240
#define STAGE_B (4 * TILE_B)         // Ah, Al, Bh, Bl
#define GEMM_SMEM (2 * STAGE_B)      // 81920

__global__ __launch_bounds__(256) void gemm_mma(
    int M, int N, int K, const __nv_bfloat16* __restrict__ Ahi,
    const __nv_bfloat16* __restrict__ Alo, const __nv_bfloat16* B0h, const __nv_bfloat16* B0l,
    float* C0, const __nv_bfloat16* B1h, const __nv_bfloat16* B1l, float* C1,
    const __nv_bfloat16* B2h, const __nv_bfloat16* B2l, float* C2, int relu) {
    extern __shared__ char sm[];
    const __nv_bfloat16 *Bh, *Bl;
    float* C;
    int z = blockIdx.z;
    if (z == 0) { Bh = B0h; Bl = B0l; C = C0; }
    else if (z == 1) { Bh = B1h; Bl = B1l; C = C1; }
    else { Bh = B2h; Bl = B2l; C = C2; }

    uint32_t smb = smem_u32(sm);
    int tid = threadIdx.x, wid = tid >> 5, lane = tid & 31;
    int row0 = blockIdx.y * 128, col0 = blockIdx.x * 128;
    int wm = wid >> 2, wn = wid & 3;

    float acc[4][4][4];
#pragma unroll
    for (int a = 0; a < 4; a++)
#pragma unroll
        for (int b = 0; b < 4; b++)
#pragma unroll
            for (int c = 0; c < 4; c++) acc[a][b][c] = 0.f;

    // per-thread load coords (2 16B chunks per tile)
    int cid0 = tid * 2, cid1 = tid * 2 + 1;
    int lr0 = cid0 >> 2, lc0 = (cid0 & 3) * 16;  // smem byte col
    int lr1 = cid1 >> 2, lc1 = (cid1 & 3) * 16;

    const __nv_bfloat16* srcs[4] = {Ahi, Alo, Bh, Bl};
    int rbase[4] = {row0, row0, col0, col0};

    // prologue: load chunk 0 into stage 0
    {
        int k0 = 0;
#pragma unroll
        for (int t = 0; t < 4; t++) {
            const __nv_bfloat16* src = srcs[t];
            uint32_t tb = smb + t * TILE_B;
            cp16(tb + lr0 * TSTRIDE + lc0, src + (size_t)(rbase[t] + lr0) * K + k0 + (lc0 >> 1));
            cp16(tb + lr1 * TSTRIDE + lc1, src + (size_t)(rbase[t] + lr1) * K + k0 + (lc1 >> 1));
        }
        CP_COMMIT();
    }

    const int nch = K / 32;
    for (int c = 0; c < nch; c++) {
        if (c + 1 < nch) {
            int k0 = (c + 1) * 32;
            uint32_t sb = smb + ((c + 1) & 1) * STAGE_B;
#pragma unroll
            for (int t = 0; t < 4; t++) {
                const __nv_bfloat16* src = srcs[t];
                uint32_t tb = sb + t * TILE_B;
                cp16(tb + lr0 * TSTRIDE + lc0,
                     src + (size_t)(rbase[t] + lr0) * K + k0 + (lc0 >> 1));
                cp16(tb + lr1 * TSTRIDE + lc1,
                     src + (size_t)(rbase[t] + lr1) * K + k0 + (lc1 >> 1));
            }
            CP_COMMIT();
            CP_WAIT1();
        } else {
            CP_WAIT0();
        }
        __syncthreads();

        uint32_t base = smb + (c & 1) * STAGE_B;
        uint32_t aH = base, aL = base + TILE_B, bH = base + 2 * TILE_B, bL = base + 3 * TILE_B;
        int arow = wm * 64 + (lane & 15);
        int brow = wn * 32 + (lane & 7) + ((lane >> 4) << 3);
#pragma unroll
        for (int ks = 0; ks < 2; ks++) {
            int k2 = ks * 32;  // byte offset of this k16 block
            int akb = k2 + ((lane >> 4) << 4);
            int bkb = k2 + (((lane >> 3) & 1) << 4);
            uint32_t ah[4][4], al[4][4], bh[4][2], bl[4][2];
#pragma unroll
            for (int mf = 0; mf < 4; mf++)
                ldmx4(ah[mf], aH + (uint32_t)(arow + mf * 16) * TSTRIDE + akb);
#pragma unroll
            for (int mf = 0; mf < 4; mf++)
                ldmx4(al[mf], aL + (uint32_t)(arow + mf * 16) * TSTRIDE + akb);
#pragma unroll
            for (int np = 0; np < 2; np++) {
                uint32_t r4[4];
                ldmx4(r4, bH + (uint32_t)(brow + np * 16) * TSTRIDE + bkb);
                bh[np * 2][0] = r4[0]; bh[np * 2][1] = r4[1];
                bh[np * 2 + 1][0] = r4[2]; bh[np * 2 + 1][1] = r4[3];
                ldmx4(r4, bL + (uint32_t)(brow + np * 16) * TSTRIDE + bkb);
                bl[np * 2][0] = r4[0]; bl[np * 2][1] = r4[1];
                bl[np * 2 + 1][0] = r4[2]; bl[np * 2 + 1][1] = r4[3];
            }
#pragma unroll
            for (int mf = 0; mf < 4; mf++)
#pragma unroll
                for (int nf = 0; nf < 4; nf++) mma16816(acc[mf][nf], ah[mf], bh[nf]);
#pragma unroll
            for (int mf = 0; mf < 4; mf++)
#pragma unroll
                for (int nf = 0; nf < 4; nf++) mma16816(acc[mf][nf], ah[mf], bl[nf]);
#pragma unroll
            for (int mf = 0; mf < 4; mf++)
#pragma unroll
                for (int nf = 0; nf < 4; nf++) mma16816(acc[mf][nf], al[mf], bh[nf]);
        }
        __syncthreads();
    }

    // epilogue
    int gr = row0 + wm * 64 + (lane >> 2);
    int gc = col0 + wn * 32 + (lane & 3) * 2;
#pragma unroll
    for (int mf = 0; mf < 4; mf++) {
#pragma unroll
        for (int nf = 0; nf < 4; nf++) {
            float* a4 = acc[mf][nf];
            if (relu) {
                a4[0] = fmaxf(a4[0], 0.f);
                a4[1] = fmaxf(a4[1], 0.f);
                a4[2] = fmaxf(a4[2], 0.f);
                a4[3] = fmaxf(a4[3], 0.f);
            }
            float2 v0 = {a4[0], a4[1]};
            float2 v1 = {a4[2], a4[3]};
            *(float2*)(C + (size_t)(gr + mf * 16) * N + gc + nf * 8) = v0;
            *(float2*)(C + (size_t)(gr + mf * 16 + 8) * N + gc + nf * 8) = v1;
        }
    }
}

// ============================ LayerNorm =====================================
__global__ __launch_bounds__(256) void ln_kernel(const float* __restrict__ y,
                                                 const float* __restrict__ xin,
                                                 const float* __restrict__ g,
                                                 const float* __restrict__ b,
                                                 float* __restrict__ out) {
    int s = blockIdx.x, tid = threadIdx.x;
    const float* yr = y + (size_t)s * DMODEL;
    const float* xr = xin + (size_t)s * DMODEL;
    float v[4];
    float sum = 0.f;
#pragma unroll
    for (int i = 0; i < 4; i++) {
        int d = tid + (i << 8);
        v[i] = yr[d] + xr[d];
        sum += v[i];
    }
    float mean = blockSum256(sum) * (1.f / 1024.f);
    float sq = 0.f;
#pragma unroll
    for (int i = 0; i < 4; i++) {
        float t = v[i] - mean;
        sq += t * t;
    }
    float var = blockSum256(sq) * (1.f / 1024.f);
    float inv = 1.f / sqrtf(var + 1e-5f);
    float* orow = out + (size_t)s * DMODEL;
#pragma unroll
    for (int i = 0; i < 4; i++) {
        int d = tid + (i << 8);
        orow[d] = g[d] * (v[i] - mean) * inv + b[d];
    }
}

// ============================ attention =====================================
__global__ void vmean_part_kernel() {
    int d = blockIdx.x * 256 + threadIdx.x;
    int slab = blockIdx.y;
    float acc = 0.f;
    for (int s = slab * 128; s < (slab + 1) * 128; s++) acc += g_v[(size_t)s * DMODEL + d];
    g_vpart[slab][d] = acc;
}
__global__ void vmean_reduce_kernel() {
    int d = blockIdx.x * 256 + threadIdx.x;
    float a = 0.f;
#pragma unroll
    for (int i = 0; i < 16; i++) a += g_vpart[i][d];
    g_vmean[d] = a * (1.f / (float)S);
}
__global__ void attn_pad_kernel() {
    int s = blockIdx.y;
    if (g_mask[s] != 0) return;
    int d = blockIdx.x * 256 + threadIdx.x;
    g_ctx[(size_t)s * DMODEL + d] = g_vmean[d];
}

#define SMEM_LOCAL_BYTES (((128 * 129 * 2 + 32 * 128 * 2) * 4) + 128 * 4)
__global__ __launch_bounds__(256) void attn_local_kernel() {
    extern __shared__ float smf[];
    float* Ks = smf;
    float* Vs = Ks + 128 * 129;
    float* Qs = Vs + 128 * 129;
    float* probs = Qs + 32 * 128;
    int* cand = (int*)(probs + 32 * 128);
    __shared__ int s_nc;

    int tid = threadIdx.x;
    int h = blockIdx.y, q0 = blockIdx.x * 32, base = h * DK;

    if (tid < 96) {
        int k = q0 - 32 + tid;
        cand[tid] = (k >= 0 && k < S) ? k : -1;
    }
    if (tid == 0) {
        int cnt = 96, ng = g_nglob;
        for (int i = 0; i < ng; i++) {
            int g = g_globlist[i];
            if (g < q0 - 32 || g > q0 + 63) cand[cnt++] = g;
        }
        s_nc = cnt;
    }
    __syncthreads();
    int nc = s_nc;

    for (int e = tid; e < 128 * 128; e += 256) {
        int j = e >> 7, d = e & 127;
        int k = (j < nc) ? cand[j] : -1;
        float kv = 0.f, vv = 0.f;
        if (k >= 0) {
            kv = g_k[(size_t)k * DMODEL + base + d];
            vv = g_v[(size_t)k * DMODEL + base + d];
        }
        Ks[j * 129 + d] = kv;
        Vs[j * 129 + d] = vv;
    }
    for (int e = tid; e < 32 * 128; e += 256) {
        int r = e >> 7, d = e & 127;
        Qs[e] = g_q[(size_t)(q0 + r) * DMODEL + base + d];
    }
    __syncthreads();

    int warp = tid >> 5, lane = tid & 31;
    const float NI = neg_inf();
#pragma unroll
    for (int rr = 0; rr < 4; rr++) {
        int r = warp * 4 + rr, q = q0 + r;
        bool active = (g_mask[q] == 1);
        float sv[4];
#pragma unroll
        for (int m = 0; m < 4; m++) {
            int j = lane + (m << 5);
            float val = NI;
            if (active && j < nc) {
                int k = cand[j];
                if (k >= 0) {
                    int mk = g_mask[k];
                    int dd = q - k;
                    if (dd < 0) dd = -dd;
                    bool ok = (mk != 0) && ((j >= 96) || (mk == 2) || (dd <= 32));
                    if (ok) {
                        float sd = 0.f;
                        const float* qp = &Qs[r * 128];
                        const float* kp = &Ks[j * 129];
#pragma unroll 16
                        for (int d = 0; d < 128; d++) sd += qp[d] * kp[d];
                        val = sd * SCALE_F;
                    }
                }
            }
            sv[m] = val;
        }
        float mx = fmaxf(fmaxf(sv[0], sv[1]), fmaxf(sv[2], sv[3]));
#pragma unroll
        for (int o = 16; o; o >>= 1) mx = fmaxf(mx, __shfl_xor_sync(0xffffffffu, mx, o));
        float p[4];
        float sum = 0.f;
#pragma unroll
        for (int m = 0; m < 4; m++) {
            p[m] = (sv[m] == NI) ? 0.f : expf(sv[m] - mx);
            sum += p[m];
        }
#pragma unroll
        for (int o = 16; o; o >>= 1) sum += __shfl_xor_sync(0xffffffffu, sum, o);
        if (active) {
            float inv = 1.f / sum;
#pragma unroll
            for (int m = 0; m < 4; m++) {
                int j = lane + (m << 5);
                probs[r * 128 + j] = p[m] * inv;
            }
        }
    }
    __syncthreads();
    for (int e = tid; e < 32 * 128; e += 256) {
        int r = e >> 7, d = e & 127;
        int q = q0 + r;
        if (g_mask[q] != 1) continue;
        float acc = 0.f;
        const float* pr = &probs[r * 128];
#pragma unroll 4
        for (int j = 0; j < nc; j++) acc += pr[j] * Vs[j * 129 + d];
        g_ctx[(size_t)q * DMODEL + base + d] = acc;
    }
}

#define SMEM_GLOBAL_BYTES ((128 * 129 + 128 + 2048) * 4)
__global__ __launch_bounds__(256) void attn_global_kernel() {
    int i = blockIdx.x;
    int ng = g_nglob;
    if (i >= ng) return;
    int q = g_globlist[i], h = blockIdx.y, base = h * DK;

    extern __shared__ float smf[];
    float* Ks = smf;
    float* qv = Ks + 128 * 129;
    float* s_all = qv + 128;
    int tid = threadIdx.x;
    const float NI = neg_inf();

    if (tid < 128) qv[tid] = g_q[(size_t)q * DMODEL + base + tid];
    __syncthreads();

    for (int kt = 0; kt < 16; kt++) {
        for (int e = tid; e < 128 * 128; e += 256) {
            int j = e >> 7, d = e & 127;
            Ks[j * 129 + d] = g_k[(size_t)(kt * 128 + j) * DMODEL + base + d];
        }
        __syncthreads();
        if (tid < 128) {
            int k = kt * 128 + tid;
            float val = NI;
            if (g_mask[k] != 0) {
                float sd = 0.f;
                const float* kp = &Ks[tid * 129];
#pragma unroll 16
                for (int d = 0; d < 128; d++) sd += qv[d] * kp[d];
                val = sd * SCALE_F;
            }
            s_all[k] = val;
        }
        __syncthreads();
    }
    float mx = NI;
    for (int k = tid; k < S; k += 256) mx = fmaxf(mx, s_all[k]);
    mx = blockMax256(mx);
    float sum = 0.f;
    for (int k = tid; k < S; k += 256) {
        float v2 = s_all[k];
        float p = (v2 == NI) ? 0.f : expf(v2 - mx);
        s_all[k] = p;
        sum += p;
    }
    sum = blockSum256(sum);
    float inv = 1.f / sum;
    if (tid < 128) {
        int d = tid;
        float acc = 0.f;
#pragma unroll 4
        for (int k = 0; k < S; k++) acc += s_all[k] * g_v[(size_t)k * DMODEL + base + d];
        g_ctx[(size_t)q * DMODEL + base + d] = acc * inv;
    }
}

// ============================ driver ========================================
extern "C" void kernel_launch(void* const* d_in, const int* in_sizes, int n_in,
                              void* d_out, int out_size) {
    const int* Tp = (const int*)d_in[0];
    const float* enc = (const float*)d_in[1];
    const int* gidx = (const int*)d_in[2];
    const float* Wq = (const float*)d_in[3];
    const float* Wk = (const float*)d_in[4];
    const float* Wv = (const float*)d_in[5];
    const float* Wo = (const float*)d_in[6];
    const float* ln1g = (const float*)d_in[7];
    const float* ln1b = (const float*)d_in[8];
    const float* W1 = (const float*)d_in[9];
    const float* W2 = (const float*)d_in[10];
    const float* ln2g = (const float*)d_in[11];
    const float* ln2b = (const float*)d_in[12];
    float* out = (float*)d_out;

    cudaFuncSetAttribute(attn_local_kernel, cudaFuncAttributeMaxDynamicSharedMemorySize,
                         SMEM_LOCAL_BYTES);
    cudaFuncSetAttribute(attn_global_kernel, cudaFuncAttributeMaxDynamicSharedMemorySize,
                         SMEM_GLOBAL_BYTES);
    cudaFuncSetAttribute(gemm_mma, cudaFuncAttributeMaxDynamicSharedMemorySize, GEMM_SMEM);

    float *px, *pq, *pk, *pv, *pctx, *ph, *py;
    __nv_bfloat16 *pwh, *pwl, *pah, *pal;
    cudaGetSymbolAddress((void**)&px, g_x);
    cudaGetSymbolAddress((void**)&pq, g_q);
    cudaGetSymbolAddress((void**)&pk, g_k);
    cudaGetSymbolAddress((void**)&pv, g_v);
    cudaGetSymbolAddress((void**)&pctx, g_ctx);
    cudaGetSymbolAddress((void**)&ph, g_h);
    cudaGetSymbolAddress((void**)&py, g_y);
    cudaGetSymbolAddress((void**)&pwh, g_wt_hi);
    cudaGetSymbolAddress((void**)&pwl, g_wt_lo);
    cudaGetSymbolAddress((void**)&pah, g_ah);
    cudaGetSymbolAddress((void**)&pal, g_al);

    mask_zero_kernel<<<8, 256>>>();
    mask_scatter_kernel<<<1, 32>>>(gidx);
    mask_build_kernel<<<8, 256>>>(Tp);
    mask_list_kernel<<<1, 32>>>();
    pediv_kernel<<<2, 256>>>();
    prep_kernel<<<(S * DMODEL) / 256, 256>>>(enc);

    // weight transpose + split
    dim3 tb(32, 8);
    for (int l = 0; l < NLAYERS; l++) {
        size_t wo_ = (size_t)l * LSTRIDE;
        const size_t M1 = 1024u * 1024u;
        tsplit_kernel<<<dim3(32, 32), tb>>>(Wq + l * M1, pwh + wo_, pwl + wo_, 1024, 1024);
        tsplit_kernel<<<dim3(32, 32), tb>>>(Wk + l * M1, pwh + wo_ + M1, pwl + wo_ + M1, 1024, 1024);
        tsplit_kernel<<<dim3(32, 32), tb>>>(Wv + l * M1, pwh + wo_ + 2 * M1, pwl + wo_ + 2 * M1, 1024, 1024);
        tsplit_kernel<<<dim3(32, 32), tb>>>(Wo + l * M1, pwh + wo_ + 3 * M1, pwl + wo_ + 3 * M1, 1024, 1024);
        tsplit_kernel<<<dim3(64, 32), tb>>>(W1 + l * 2 * M1, pwh + wo_ + 4 * M1, pwl + wo_ + 4 * M1, 1024, 2048);
        tsplit_kernel<<<dim3(32, 64), tb>>>(W2 + l * 2 * M1, pwh + wo_ + 6 * M1, pwl + wo_ + 6 * M1, 2048, 1024);
    }

    for (int l = 0; l < NLAYERS; l++) {
        size_t wo_ = (size_t)l * LSTRIDE;
        const size_t M1 = 1024u * 1024u;
        const __nv_bfloat16 *qh = pwh + wo_, *ql = pwl + wo_;
        const __nv_bfloat16 *kh = pwh + wo_ + M1, *kl = pwl + wo_ + M1;
        const __nv_bfloat16 *vh = pwh + wo_ + 2 * M1, *vl = pwl + wo_ + 2 * M1;
        const __nv_bfloat16 *oh = pwh + wo_ + 3 * M1, *ol = pwl + wo_ + 3 * M1;
        const __nv_bfloat16 *w1h = pwh + wo_ + 4 * M1, *w1l = pwl + wo_ + 4 * M1;
        const __nv_bfloat16 *w2h = pwh + wo_ + 6 * M1, *w2l = pwl + wo_ + 6 * M1;

        // QKV projections (fused via grid.z = 3)
        split_kernel<<<(S * DMODEL / 4) / 256, 256>>>(px, pah, pal, S * DMODEL / 4);
        gemm_mma<<<dim3(DMODEL / 128, S / 128, 3), 256, GEMM_SMEM>>>(
            S, DMODEL, DMODEL, pah, pal, qh, ql, pq, kh, kl, pk, vh, vl, pv, 0);

        vmean_part_kernel<<<dim3(DMODEL / 256, 16), 256>>>();
        vmean_reduce_kernel<<<DMODEL / 256, 256>>>();
        attn_local_kernel<<<dim3(S / 32, NH), 256, SMEM_LOCAL_BYTES>>>();
        attn_global_kernel<<<dim3(32, NH), 256, SMEM_GLOBAL_BYTES>>>();
        attn_pad_kernel<<<dim3(DMODEL / 256, S), 256>>>();

        // output projection + residual LN
        split_kernel<<<(S * DMODEL / 4) / 256, 256>>>(pctx, pah, pal, S * DMODEL / 4);
        gemm_mma<<<dim3(DMODEL / 128, S / 128, 1), 256, GEMM_SMEM>>>(
            S, DMODEL, DMODEL, pah, pal, oh, ol, py, nullptr, nullptr, nullptr, nullptr,
            nullptr, nullptr, 0);
        ln_kernel<<<S, 256>>>(py, px, ln1g + l * DMODEL, ln1b + l * DMODEL, px);

        // FFN
        split_kernel<<<(S * DMODEL / 4) / 256, 256>>>(px, pah, pal, S * DMODEL / 4);
        gemm_mma<<<dim3(DFF / 128, S / 128, 1), 256, GEMM_SMEM>>>(
            S, DFF, DMODEL, pah, pal, w1h, w1l, ph, nullptr, nullptr, nullptr, nullptr,
            nullptr, nullptr, 1);
        split_kernel<<<(S * DFF / 4) / 256, 256>>>(ph, pah, pal, S * DFF / 4);
        gemm_mma<<<dim3(DMODEL / 128, S / 128, 1), 256, GEMM_SMEM>>>(
            S, DMODEL, DFF, pah, pal, w2h, w2l, py, nullptr, nullptr, nullptr, nullptr,
            nullptr, nullptr, 0);
        ln_kernel<<<S, 256>>>(py, px, ln2g + l * DMODEL, ln2b + l * DMODEL,
                              (l == NLAYERS - 1) ? out : px);
    }
}

// round 8
// speedup vs baseline: 2.1630x; 1.0107x over previous
#include <cuda_runtime.h>
#include <cuda_bf16.h>
#include <math.h>
#include <stdint.h>

#define S 2048
#define DMODEL 1024
#define DFF 2048
#define NH 8
#define DK 128
#define NLAYERS 4

static __device__ __forceinline__ float neg_inf() { return __int_as_float(0xff800000); }
#define SCALE_F 0.08838834764831845f  // 1/sqrt(128)

// ======================= PTX helpers (base sm_80+ features only) ============
__device__ __forceinline__ uint32_t smem_u32(const void* p) {
    uint32_t a;
    asm("{ .reg .u64 t; cvta.to.shared.u64 t, %1; cvt.u32.u64 %0, t; }" : "=r"(a) : "l"(p));
    return a;
}
__device__ __forceinline__ void cp16(uint32_t dst, const void* src) {
    asm volatile("cp.async.cg.shared.global [%0], [%1], 16;" ::"r"(dst), "l"(src));
}
#define CP_COMMIT() asm volatile("cp.async.commit_group;" ::: "memory")
#define CP_WAIT1() asm volatile("cp.async.wait_group 1;" ::: "memory")
#define CP_WAIT0() asm volatile("cp.async.wait_group 0;" ::: "memory")

__device__ __forceinline__ void ldmx4(uint32_t* r, uint32_t addr) {
    asm volatile("ldmatrix.sync.aligned.m8n8.x4.shared.b16 {%0,%1,%2,%3}, [%4];"
                 : "=r"(r[0]), "=r"(r[1]), "=r"(r[2]), "=r"(r[3])
                 : "r"(addr));
}
__device__ __forceinline__ void mma16816(float* d, const uint32_t* a, const uint32_t* b) {
    asm volatile(
        "mma.sync.aligned.m16n8k16.row.col.f32.bf16.bf16.f32 "
        "{%0,%1,%2,%3}, {%4,%5,%6,%7}, {%8,%9}, {%0,%1,%2,%3};"
        : "+f"(d[0]), "+f"(d[1]), "+f"(d[2]), "+f"(d[3])
        : "r"(a[0]), "r"(a[1]), "r"(a[2]), "r"(a[3]), "r"(b[0]), "r"(b[1]));
}
__device__ __forceinline__ void store_hl2(__nv_bfloat16* Hh, __nv_bfloat16* Hl, size_t off,
                                          float x, float y) {
    __nv_bfloat16 hx = __float2bfloat16(x), hy = __float2bfloat16(y);
    __nv_bfloat162 h;
    h.x = hx;
    h.y = hy;
    __nv_bfloat162 l;
    l.x = __float2bfloat16(x - __bfloat162float(hx));
    l.y = __float2bfloat16(y - __bfloat162float(hy));
    *(__nv_bfloat162*)(Hh + off) = h;
    *(__nv_bfloat162*)(Hl + off) = l;
}
__device__ __forceinline__ void store_hl1(__nv_bfloat16* Hh, __nv_bfloat16* Hl, size_t off,
                                          float x) {
    __nv_bfloat16 hx = __float2bfloat16(x);
    Hh[off] = hx;
    Hl[off] = __float2bfloat16(x - __bfloat162float(hx));
}

// ============================ scratch globals ===============================
__device__ float g_x[S * DMODEL];
__device__ float g_q[S * DMODEL];
__device__ float g_k[S * DMODEL];
__device__ float g_v[S * DMODEL];
__device__ float g_y[S * DMODEL];
__device__ float g_vmean[DMODEL];
__device__ float g_vpart[16][DMODEL];
__device__ int g_isglob[S];
__device__ int g_mask[S];  // 0 pad, 1 local, 2 global
__device__ int g_globlist[64];
__device__ int g_nglob;
__device__ float g_divhi[512];
__device__ float g_divlo[512];

#define LSTRIDE (8 * 1024 * 1024)
__device__ __nv_bfloat16 g_wt_hi[NLAYERS * LSTRIDE];
__device__ __nv_bfloat16 g_wt_lo[NLAYERS * LSTRIDE];
__device__ __nv_bfloat16 g_ah[S * DMODEL];  // x / ctx hi
__device__ __nv_bfloat16 g_al[S * DMODEL];  // x / ctx lo
__device__ __nv_bfloat16 g_hh[S * DFF];     // ffn hidden hi
__device__ __nv_bfloat16 g_hl[S * DFF];     // ffn hidden lo

// ============================ reductions ====================================
static __device__ __forceinline__ float warpAllSum(float v) {
#pragma unroll
    for (int o = 16; o; o >>= 1) v += __shfl_xor_sync(0xffffffffu, v, o);
    return v;
}
static __device__ __forceinline__ float warpAllMax(float v) {
#pragma unroll
    for (int o = 16; o; o >>= 1) v = fmaxf(v, __shfl_xor_sync(0xffffffffu, v, o));
    return v;
}
static __device__ __forceinline__ float blockSum256(float v) {
    __shared__ float sh[8];
    int lane = threadIdx.x & 31, w = threadIdx.x >> 5;
    v = warpAllSum(v);
    __syncthreads();
    if (lane == 0) sh[w] = v;
    __syncthreads();
    if (w == 0) {
        float t = (lane < 8) ? sh[lane] : 0.f;
        t = warpAllSum(t);
        if (lane == 0) sh[0] = t;
    }
    __syncthreads();
    return sh[0];
}
static __device__ __forceinline__ float blockMax256(float v) {
    __shared__ float sh[8];
    int lane = threadIdx.x & 31, w = threadIdx.x >> 5;
    v = warpAllMax(v);
    __syncthreads();
    if (lane == 0) sh[w] = v;
    __syncthreads();
    if (w == 0) {
        float t = (lane < 8) ? sh[lane] : neg_inf();
        t = warpAllMax(t);
        if (lane == 0) sh[0] = t;
    }
    __syncthreads();
    return sh[0];
}

// ============================ prep / mask ===================================
__global__ void pediv_kernel() {
    int i = blockIdx.x * 256 + threadIdx.x;
    if (i < 512) {
        double dv = exp(-(double)(2 * i) * (9.210340371976184 / 1024.0));
        float h = (float)dv;
        g_divhi[i] = h;
        g_divlo[i] = (float)(dv - (double)h);
    }
}
// x = 2*enc + PE; also emit bf16 hi/lo split
__global__ void prep_kernel(const float* __restrict__ enc) {
    int idx = blockIdx.x * 256 + threadIdx.x;
    int s = idx >> 10, d = idx & 1023;
    int i = d >> 1;
    float hi = g_divhi[i], lo = g_divlo[i];
    float sf = (float)s;
    float h = sf * hi;
    float e = fmaf(sf, hi, -h);
    float t = fmaf(sf, lo, e);
    const float P2HI = 6.28318548202514648f;
    const float P2LO = -1.74845553e-7f;
    float n = rintf(h * 0.15915494309189535f);
    float r = fmaf(-n, P2HI, h);
    r = fmaf(-n, P2LO, r);
    r += t;
    float pe = (d & 1) ? cosf(r) : sinf(r);
    float x = 2.0f * enc[idx] + pe;
    g_x[idx] = x;
    store_hl1(g_ah, g_al, idx, x);
}
__global__ void mask_zero_kernel() {
    int i = blockIdx.x * 256 + threadIdx.x;
    if (i < S) g_isglob[i] = 0;
}
__global__ void mask_scatter_kernel(const int* __restrict__ gidx) {
    int t = threadIdx.x;
    if (t < 32) {
        int g = gidx[t] / 15;
        if (g >= 0 && g < S) g_isglob[g] = 1;
    }
}
__global__ void mask_build_kernel(const int* __restrict__ Tp) {
    int i = blockIdx.x * 256 + threadIdx.x;
    if (i < S) {
        int T = *Tp;
        g_mask[i] = g_isglob[i] ? 2 : (i < T ? 1 : 0);
    }
}
__global__ void mask_list_kernel() {
    int lane = threadIdx.x;
    int cnt = 0;
    for (int base = 0; base < S; base += 32) {
        int m = (g_mask[base + lane] == 2);
        unsigned bal = __ballot_sync(0xffffffffu, m);
        if (m) g_globlist[cnt + __popc(bal & ((1u << lane) - 1u))] = base + lane;
        cnt += __popc(bal);
    }
    if (lane == 0) g_nglob = cnt;
}

// ============================ weight transpose/split ========================
// W (K x N) -> WT hi/lo (N x K)
__global__ void tsplit_kernel(const float* __restrict__ W, __nv_bfloat16* __restrict__ hi,
                              __nv_bfloat16* __restrict__ lo, int K, int N) {
    __shared__ float t[32][33];
    int k0 = blockIdx.y * 32, n0 = blockIdx.x * 32;
    int tx = threadIdx.x, ty = threadIdx.y;
#pragma unroll
    for (int i = 0; i < 32; i += 8) t[ty + i][tx] = W[(size_t)(k0 + ty + i) * N + n0 + tx];
    __syncthreads();
#pragma unroll
    for (int i = 0; i < 32; i += 8) {
        float x = t[tx][ty + i];
        __nv_bfloat16 h = __float2bfloat16(x);
        size_t o = (size_t)(n0 + ty + i) * K + k0 + tx;
        hi[o] = h;
        lo[o] = __float2bfloat16(x - __bfloat162float(h));
    }
}

// ============================ bf16x3 HMMA GEMM ==============================
// C = A@W; A hi/lo row-major (MxK); B = W^T hi/lo (NxK). 128x128 tile, BK=32,
// 2-stage cp.async, 8 warps (64x32), 3-pass frag loading for 2 CTAs/SM.
// If Hh != null: write ReLU'd bf16 hi/lo instead of fp32 C.
#define TSTRIDE 80
#define TILE_B (128 * TSTRIDE)
#define STAGE_B (4 * TILE_B)
#define GEMM_SMEM (2 * STAGE_B)  // 81920

__global__ __launch_bounds__(256, 2) void gemm_mma(
    int M, int N, int K, const __nv_bfloat16* __restrict__ Ahi,
    const __nv_bfloat16* __restrict__ Alo, const __nv_bfloat16* B0h, const __nv_bfloat16* B0l,
    float* C0, const __nv_bfloat16* B1h, const __nv_bfloat16* B1l, float* C1,
    const __nv_bfloat16* B2h, const __nv_bfloat16* B2l, float* C2, int relu,
    __nv_bfloat16* Hh, __nv_bfloat16* Hl) {
    extern __shared__ char sm[];
    const __nv_bfloat16 *Bh, *Bl;
    float* C;
    int z = blockIdx.z;
    if (z == 0) { Bh = B0h; Bl = B0l; C = C0; }
    else if (z == 1) { Bh = B1h; Bl = B1l; C = C1; }
    else { Bh = B2h; Bl = B2l; C = C2; }

    uint32_t smb = smem_u32(sm);
    int tid = threadIdx.x, wid = tid >> 5, lane = tid & 31;
    int row0 = blockIdx.y * 128, col0 = blockIdx.x * 128;
    int wm = wid >> 2, wn = wid & 3;

    float acc[4][4][4];
#pragma unroll
    for (int a = 0; a < 4; a++)
#pragma unroll
        for (int b = 0; b < 4; b++)
#pragma unroll
            for (int c = 0; c < 4; c++) acc[a][b][c] = 0.f;

    int cid0 = tid * 2, cid1 = tid * 2 + 1;
    int lr0 = cid0 >> 2, lc0 = (cid0 & 3) * 16;
    int lr1 = cid1 >> 2, lc1 = (cid1 & 3) * 16;

    const __nv_bfloat16* srcs[4] = {Ahi, Alo, Bh, Bl};
    int rbase[4] = {row0, row0, col0, col0};

    {
#pragma unroll
        for (int t = 0; t < 4; t++) {
            const __nv_bfloat16* src = srcs[t];
            uint32_t tb = smb + t * TILE_B;
            cp16(tb + lr0 * TSTRIDE + lc0, src + (size_t)(rbase[t] + lr0) * K + (lc0 >> 1));
            cp16(tb + lr1 * TSTRIDE + lc1, src + (size_t)(rbase[t] + lr1) * K + (lc1 >> 1));
        }
        CP_COMMIT();
    }

    const int nch = K / 32;
    for (int c = 0; c < nch; c++) {
        if (c + 1 < nch) {
            int k0 = (c + 1) * 32;
            uint32_t sb = smb + ((c + 1) & 1) * STAGE_B;
#pragma unroll
            for (int t = 0; t < 4; t++) {
                const __nv_bfloat16* src = srcs[t];
                uint32_t tb = sb + t * TILE_B;
                cp16(tb + lr0 * TSTRIDE + lc0,
                     src + (size_t)(rbase[t] + lr0) * K + k0 + (lc0 >> 1));
                cp16(tb + lr1 * TSTRIDE + lc1,
                     src + (size_t)(rbase[t] + lr1) * K + k0 + (lc1 >> 1));
            }
            CP_COMMIT();
            CP_WAIT1();
        } else {
            CP_WAIT0();
        }
        __syncthreads();

        uint32_t base = smb + (c & 1) * STAGE_B;
        uint32_t aH = base, aL = base + TILE_B, bH = base + 2 * TILE_B, bL = base + 3 * TILE_B;
        int arow = wm * 64 + (lane & 15);
        int brow = wn * 32 + (lane & 7) + ((lane >> 4) << 3);
#pragma unroll
        for (int ks = 0; ks < 2; ks++) {
            int akb = ks * 32 + ((lane >> 4) << 4);
            int bkb = ks * 32 + (((lane >> 3) & 1) << 4);
            // pass 1: Ahi x Bhi
            uint32_t ah[4][4], bh[4][2];
#pragma unroll
            for (int mf = 0; mf < 4; mf++)
                ldmx4(ah[mf], aH + (uint32_t)(arow + mf * 16) * TSTRIDE + akb);
#pragma unroll
            for (int np = 0; np < 2; np++) {
                uint32_t r4[4];
                ldmx4(r4, bH + (uint32_t)(brow + np * 16) * TSTRIDE + bkb);
                bh[np * 2][0] = r4[0]; bh[np * 2][1] = r4[1];
                bh[np * 2 + 1][0] = r4[2]; bh[np * 2 + 1][1] = r4[3];
            }
#pragma unroll
            for (int mf = 0; mf < 4; mf++)
#pragma unroll
                for (int nf = 0; nf < 4; nf++) mma16816(acc[mf][nf], ah[mf], bh[nf]);
            // pass 2: Ahi x Blo (reuse ah)
            {
                uint32_t bl[4][2];
#pragma unroll
                for (int np = 0; np < 2; np++) {
                    uint32_t r4[4];
                    ldmx4(r4, bL + (uint32_t)(brow + np * 16) * TSTRIDE + bkb);
                    bl[np * 2][0] = r4[0]; bl[np * 2][1] = r4[1];
                    bl[np * 2 + 1][0] = r4[2]; bl[np * 2 + 1][1] = r4[3];
                }
#pragma unroll
                for (int mf = 0; mf < 4; mf++)
#pragma unroll
                    for (int nf = 0; nf < 4; nf++) mma16816(acc[mf][nf], ah[mf], bl[nf]);
            }
            // pass 3: Alo x Bhi (ah dead; al may reuse its regs)
            {
                uint32_t al[4][4];
#pragma unroll
                for (int mf = 0; mf < 4; mf++)
                    ldmx4(al[mf], aL + (uint32_t)(arow + mf * 16) * TSTRIDE + akb);
#pragma unroll
                for (int mf = 0; mf < 4; mf++)
#pragma unroll
                    for (int nf = 0; nf < 4; nf++) mma16816(acc[mf][nf], al[mf], bh[nf]);
            }
        }
        __syncthreads();
    }

    int gr = row0 + wm * 64 + (lane >> 2);
    int gc = col0 + wn * 32 + (lane & 3) * 2;
#pragma unroll
    for (int mf = 0; mf < 4; mf++) {
#pragma unroll
        for (int nf = 0; nf < 4; nf++) {
            float* a4 = acc[mf][nf];
            if (relu) {
                a4[0] = fmaxf(a4[0], 0.f);
                a4[1] = fmaxf(a4[1], 0.f);
                a4[2] = fmaxf(a4[2], 0.f);
                a4[3] = fmaxf(a4[3], 0.f);
            }
            size_t o0 = (size_t)(gr + mf * 16) * N + gc + nf * 8;
            size_t o1 = (size_t)(gr + mf * 16 + 8) * N + gc + nf * 8;
            if (Hh) {
                store_hl2(Hh, Hl, o0, a4[0], a4[1]);
                store_hl2(Hh, Hl, o1, a4[2], a4[3]);
            } else {
                float2 v0 = {a4[0], a4[1]};
                float2 v1 = {a4[2], a4[3]};
                *(float2*)(C + o0) = v0;
                *(float2*)(C + o1) = v1;
            }
        }
    }
}

// ============================ LayerNorm (fused split out) ===================
__global__ __launch_bounds__(256) void ln_kernel(const float* __restrict__ y,
                                                 const float* __restrict__ xin,
                                                 const float* __restrict__ g,
                                                 const float* __restrict__ b,
                                                 float* __restrict__ out,
                                                 __nv_bfloat16* __restrict__ oh,
                                                 __nv_bfloat16* __restrict__ ol) {
    int s = blockIdx.x, tid = threadIdx.x;
    const float* yr = y + (size_t)s * DMODEL;
    const float* xr = xin + (size_t)s * DMODEL;
    float v[4];
    float sum = 0.f;
#pragma unroll
    for (int i = 0; i < 4; i++) {
        int d = tid + (i << 8);
        v[i] = yr[d] + xr[d];
        sum += v[i];
    }
    float mean = blockSum256(sum) * (1.f / 1024.f);
    float sq = 0.f;
#pragma unroll
    for (int i = 0; i < 4; i++) {
        float t = v[i] - mean;
        sq += t * t;
    }
    float var = blockSum256(sq) * (1.f / 1024.f);
    float inv = 1.f / sqrtf(var + 1e-5f);
    float* orow = out + (size_t)s * DMODEL;
#pragma unroll
    for (int i = 0; i < 4; i++) {
        int d = tid + (i << 8);
        float o = g[d] * (v[i] - mean) * inv + b[d];
        orow[d] = o;
        store_hl1(oh, ol, (size_t)s * DMODEL + d, o);
    }
}

// ============================ attention =====================================
__global__ void vmean_part_kernel() {
    int d = blockIdx.x * 256 + threadIdx.x;
    int slab = blockIdx.y;
    float acc = 0.f;
    for (int s = slab * 128; s < (slab + 1) * 128; s++) acc += g_v[(size_t)s * DMODEL + d];
    g_vpart[slab][d] = acc;
}
__global__ void vmean_reduce_kernel() {
    int d = blockIdx.x * 256 + threadIdx.x;
    float a = 0.f;
#pragma unroll
    for (int i = 0; i < 16; i++) a += g_vpart[i][d];
    g_vmean[d] = a * (1.f / (float)S);
}
__global__ void attn_pad_kernel(__nv_bfloat16* __restrict__ ch, __nv_bfloat16* __restrict__ cl) {
    int s = blockIdx.y;
    if (g_mask[s] != 0) return;
    int d = blockIdx.x * 256 + threadIdx.x;
    store_hl1(ch, cl, (size_t)s * DMODEL + d, g_vmean[d]);
}

#define SMEM_LOCAL_BYTES (((128 * 129 * 2 + 32 * 128 * 2) * 4) + 128 * 4)
__global__ __launch_bounds__(256) void attn_local_kernel(__nv_bfloat16* __restrict__ ch,
                                                         __nv_bfloat16* __restrict__ cl) {
    extern __shared__ float smf[];
    float* Ks = smf;
    float* Vs = Ks + 128 * 129;
    float* Qs = Vs + 128 * 129;
    float* probs = Qs + 32 * 128;
    int* cand = (int*)(probs + 32 * 128);
    __shared__ int s_nc;

    int tid = threadIdx.x;
    int h = blockIdx.y, q0 = blockIdx.x * 32, base = h * DK;

    if (tid < 96) {
        int k = q0 - 32 + tid;
        cand[tid] = (k >= 0 && k < S) ? k : -1;
    }
    if (tid == 0) {
        int cnt = 96, ng = g_nglob;
        for (int i = 0; i < ng; i++) {
            int g = g_globlist[i];
            if (g < q0 - 32 || g > q0 + 63) cand[cnt++] = g;
        }
        s_nc = cnt;
    }
    __syncthreads();
    int nc = s_nc;

    for (int e = tid; e < 128 * 128; e += 256) {
        int j = e >> 7, d = e & 127;
        int k = (j < nc) ? cand[j] : -1;
        float kv = 0.f, vv = 0.f;
        if (k >= 0) {
            kv = g_k[(size_t)k * DMODEL + base + d];
            vv = g_v[(size_t)k * DMODEL + base + d];
        }
        Ks[j * 129 + d] = kv;
        Vs[j * 129 + d] = vv;
    }
    for (int e = tid; e < 32 * 128; e += 256) {
        int r = e >> 7, d = e & 127;
        Qs[e] = g_q[(size_t)(q0 + r) * DMODEL + base + d];
    }
    __syncthreads();

    int warp = tid >> 5, lane = tid & 31;
    const float NI = neg_inf();
#pragma unroll
    for (int rr = 0; rr < 4; rr++) {
        int r = warp * 4 + rr, q = q0 + r;
        bool active = (g_mask[q] == 1);
        float sv[4];
#pragma unroll
        for (int m = 0; m < 4; m++) {
            int j = lane + (m << 5);
            float val = NI;
            if (active && j < nc) {
                int k = cand[j];
                if (k >= 0) {
                    int mk = g_mask[k];
                    int dd = q - k;
                    if (dd < 0) dd = -dd;
                    bool ok = (mk != 0) && ((j >= 96) || (mk == 2) || (dd <= 32));
                    if (ok) {
                        float sd = 0.f;
                        const float* qp = &Qs[r * 128];
                        const float* kp = &Ks[j * 129];
#pragma unroll 16
                        for (int d = 0; d < 128; d++) sd += qp[d] * kp[d];
                        val = sd * SCALE_F;
                    }
                }
            }
            sv[m] = val;
        }
        float mx = fmaxf(fmaxf(sv[0], sv[1]), fmaxf(sv[2], sv[3]));
#pragma unroll
        for (int o = 16; o; o >>= 1) mx = fmaxf(mx, __shfl_xor_sync(0xffffffffu, mx, o));
        float p[4];
        float sum = 0.f;
#pragma unroll
        for (int m = 0; m < 4; m++) {
            p[m] = (sv[m] == NI) ? 0.f : expf(sv[m] - mx);
            sum += p[m];
        }
#pragma unroll
        for (int o = 16; o; o >>= 1) sum += __shfl_xor_sync(0xffffffffu, sum, o);
        if (active) {
            float inv = 1.f / sum;
#pragma unroll
            for (int m = 0; m < 4; m++) {
                int j = lane + (m << 5);
                probs[r * 128 + j] = p[m] * inv;
            }
        }
    }
    __syncthreads();
    for (int e = tid; e < 32 * 128; e += 256) {
        int r = e >> 7, d = e & 127;
        int q = q0 + r;
        if (g_mask[q] != 1) continue;
        float acc = 0.f;
        const float* pr = &probs[r * 128];
#pragma unroll 4
        for (int j = 0; j < nc; j++) acc += pr[j] * Vs[j * 129 + d];
        store_hl1(ch, cl, (size_t)q * DMODEL + base + d, acc);
    }
}

#define SMEM_GLOBAL_BYTES ((128 * 129 + 128 + 2048) * 4)
__global__ __launch_bounds__(256) void attn_global_kernel(__nv_bfloat16* __restrict__ ch,
                                                          __nv_bfloat16* __restrict__ cl) {
    int i = blockIdx.x;
    int ng = g_nglob;
    if (i >= ng) return;
    int q = g_globlist[i], h = blockIdx.y, base = h * DK;

    extern __shared__ float smf[];
    float* Ks = smf;
    float* qv = Ks + 128 * 129;
    float* s_all = qv + 128;
    int tid = threadIdx.x;
    const float NI = neg_inf();

    if (tid < 128) qv[tid] = g_q[(size_t)q * DMODEL + base + tid];
    __syncthreads();

    for (int kt = 0; kt < 16; kt++) {
        for (int e = tid; e < 128 * 128; e += 256) {
            int j = e >> 7, d = e & 127;
            Ks[j * 129 + d] = g_k[(size_t)(kt * 128 + j) * DMODEL + base + d];
        }
        __syncthreads();
        if (tid < 128) {
            int k = kt * 128 + tid;
            float val = NI;
            if (g_mask[k] != 0) {
                float sd = 0.f;
                const float* kp = &Ks[tid * 129];
#pragma unroll 16
                for (int d = 0; d < 128; d++) sd += qv[d] * kp[d];
                val = sd * SCALE_F;
            }
            s_all[k] = val;
        }
        __syncthreads();
    }
    float mx = NI;
    for (int k = tid; k < S; k += 256) mx = fmaxf(mx, s_all[k]);
    mx = blockMax256(mx);
    float sum = 0.f;
    for (int k = tid; k < S; k += 256) {
        float v2 = s_all[k];
        float p = (v2 == NI) ? 0.f : expf(v2 - mx);
        s_all[k] = p;
        sum += p;
    }
    sum = blockSum256(sum);
    float inv = 1.f / sum;
    if (tid < 128) {
        int d = tid;
        float acc = 0.f;
#pragma unroll 4
        for (int k = 0; k < S; k++) acc += s_all[k] * g_v[(size_t)k * DMODEL + base + d];
        store_hl1(ch, cl, (size_t)q * DMODEL + base + d, acc * inv);
    }
}

// ============================ driver ========================================
extern "C" void kernel_launch(void* const* d_in, const int* in_sizes, int n_in,
                              void* d_out, int out_size) {
    const int* Tp = (const int*)d_in[0];
    const float* enc = (const float*)d_in[1];
    const int* gidx = (const int*)d_in[2];
    const float* Wq = (const float*)d_in[3];
    const float* Wk = (const float*)d_in[4];
    const float* Wv = (const float*)d_in[5];
    const float* Wo = (const float*)d_in[6];
    const float* ln1g = (const float*)d_in[7];
    const float* ln1b = (const float*)d_in[8];
    const float* W1 = (const float*)d_in[9];
    const float* W2 = (const float*)d_in[10];
    const float* ln2g = (const float*)d_in[11];
    const float* ln2b = (const float*)d_in[12];
    float* out = (float*)d_out;

    cudaFuncSetAttribute(attn_local_kernel, cudaFuncAttributeMaxDynamicSharedMemorySize,
                         SMEM_LOCAL_BYTES);
    cudaFuncSetAttribute(attn_global_kernel, cudaFuncAttributeMaxDynamicSharedMemorySize,
                         SMEM_GLOBAL_BYTES);
    cudaFuncSetAttribute(gemm_mma, cudaFuncAttributeMaxDynamicSharedMemorySize, GEMM_SMEM);

    float *px, *pq, *pk, *pv, *py;
    __nv_bfloat16 *pwh, *pwl, *pah, *pal, *phh, *phl;
    cudaGetSymbolAddress((void**)&px, g_x);
    cudaGetSymbolAddress((void**)&pq, g_q);
    cudaGetSymbolAddress((void**)&pk, g_k);
    cudaGetSymbolAddress((void**)&pv, g_v);
    cudaGetSymbolAddress((void**)&py, g_y);
    cudaGetSymbolAddress((void**)&pwh, g_wt_hi);
    cudaGetSymbolAddress((void**)&pwl, g_wt_lo);
    cudaGetSymbolAddress((void**)&pah, g_ah);
    cudaGetSymbolAddress((void**)&pal, g_al);
    cudaGetSymbolAddress((void**)&phh, g_hh);
    cudaGetSymbolAddress((void**)&phl, g_hl);

    const size_t M1 = 1024u * 1024u;
    dim3 tb(32, 8);

    // Launch order: 5 launches before the first gemm so ncu (-s 5 -c 1)
    // profiles the layer-0 QKV gemm.
    pediv_kernel<<<2, 256>>>();                         // 0
    prep_kernel<<<(S * DMODEL) / 256, 256>>>(enc);      // 1
    {
        size_t wo_ = 0;
        tsplit_kernel<<<dim3(32, 32), tb>>>(Wq, pwh + wo_, pwl + wo_, 1024, 1024);          // 2
        tsplit_kernel<<<dim3(32, 32), tb>>>(Wk, pwh + wo_ + M1, pwl + wo_ + M1, 1024, 1024);  // 3
        tsplit_kernel<<<dim3(32, 32), tb>>>(Wv, pwh + wo_ + 2 * M1, pwl + wo_ + 2 * M1, 1024,
                                            1024);  // 4
    }

    mask_zero_kernel<<<8, 256>>>();
    mask_scatter_kernel<<<1, 32>>>(gidx);
    mask_build_kernel<<<8, 256>>>(Tp);
    mask_list_kernel<<<1, 32>>>();

    for (int l = 0; l < NLAYERS; l++) {
        size_t wo_ = (size_t)l * LSTRIDE;
        if (l > 0) {
            tsplit_kernel<<<dim3(32, 32), tb>>>(Wq + l * M1, pwh + wo_, pwl + wo_, 1024, 1024);
            tsplit_kernel<<<dim3(32, 32), tb>>>(Wk + l * M1, pwh + wo_ + M1, pwl + wo_ + M1,
                                                1024, 1024);
            tsplit_kernel<<<dim3(32, 32), tb>>>(Wv + l * M1, pwh + wo_ + 2 * M1,
                                                pwl + wo_ + 2 * M1, 1024, 1024);
        }
        const __nv_bfloat16 *qh = pwh + wo_, *ql = pwl + wo_;
        const __nv_bfloat16 *kh = pwh + wo_ + M1, *kl = pwl + wo_ + M1;
        const __nv_bfloat16 *vh = pwh + wo_ + 2 * M1, *vl = pwl + wo_ + 2 * M1;

        // QKV projections (fused via grid.z = 3); launch index 5 for l==0
        gemm_mma<<<dim3(DMODEL / 128, S / 128, 3), 256, GEMM_SMEM>>>(
            S, DMODEL, DMODEL, pah, pal, qh, ql, pq, kh, kl, pk, vh, vl, pv, 0, nullptr,
            nullptr);

        vmean_part_kernel<<<dim3(DMODEL / 256, 16), 256>>>();
        vmean_reduce_kernel<<<DMODEL / 256, 256>>>();
        attn_local_kernel<<<dim3(S / 32, NH), 256, SMEM_LOCAL_BYTES>>>(pah, pal);
        attn_global_kernel<<<dim3(32, NH), 256, SMEM_GLOBAL_BYTES>>>(pah, pal);
        attn_pad_kernel<<<dim3(DMODEL / 256, S), 256>>>(pah, pal);

        // output projection + residual LN (LN emits next hi/lo into pah/pal)
        tsplit_kernel<<<dim3(32, 32), tb>>>(Wo + l * M1, pwh + wo_ + 3 * M1, pwl + wo_ + 3 * M1,
                                            1024, 1024);
        gemm_mma<<<dim3(DMODEL / 128, S / 128, 1), 256, GEMM_SMEM>>>(
            S, DMODEL, DMODEL, pah, pal, pwh + wo_ + 3 * M1, pwl + wo_ + 3 * M1, py, nullptr,
            nullptr, nullptr, nullptr, nullptr, nullptr, 0, nullptr, nullptr);
        ln_kernel<<<S, 256>>>(py, px, ln1g + l * DMODEL, ln1b + l * DMODEL, px, pah, pal);

        // FFN: FFN1 writes ReLU'd hi/lo bf16 directly; FFN2 -> fp32 + LN
        tsplit_kernel<<<dim3(64, 32), tb>>>(W1 + l * 2 * M1, pwh + wo_ + 4 * M1,
                                            pwl + wo_ + 4 * M1, 1024, 2048);
        gemm_mma<<<dim3(DFF / 128, S / 128, 1), 256, GEMM_SMEM>>>(
            S, DFF, DMODEL, pah, pal, pwh + wo_ + 4 * M1, pwl + wo_ + 4 * M1, nullptr, nullptr,
            nullptr, nullptr, nullptr, nullptr, nullptr, 1, phh, phl);
        tsplit_kernel<<<dim3(32, 64), tb>>>(W2 + l * 2 * M1, pwh + wo_ + 6 * M1,
                                            pwl + wo_ + 6 * M1, 2048, 1024);
        gemm_mma<<<dim3(DMODEL / 128, S / 128, 1), 256, GEMM_SMEM>>>(
            S, DMODEL, DFF, phh, phl, pwh + wo_ + 6 * M1, pwl + wo_ + 6 * M1, py, nullptr,
            nullptr, nullptr, nullptr, nullptr, nullptr, 0, nullptr, nullptr);
        ln_kernel<<<S, 256>>>(py, px, ln2g + l * DMODEL, ln2b + l * DMODEL,
                              (l == NLAYERS - 1) ? out : px, pah, pal);
    }
}

// round 9
// speedup vs baseline: 2.4849x; 1.1488x over previous
#include <cuda_runtime.h>
#include <cuda_bf16.h>
#include <math.h>
#include <stdint.h>

#define S 2048
#define DMODEL 1024
#define DFF 2048
#define NH 8
#define DK 128
#define NLAYERS 4

static __device__ __forceinline__ float neg_inf() { return __int_as_float(0xff800000); }
#define SCALE_F 0.08838834764831845f  // 1/sqrt(128)

// ======================= PTX helpers (base sm_80+ features only) ============
__device__ __forceinline__ uint32_t smem_u32(const void* p) {
    uint32_t a;
    asm("{ .reg .u64 t; cvta.to.shared.u64 t, %1; cvt.u32.u64 %0, t; }" : "=r"(a) : "l"(p));
    return a;
}
__device__ __forceinline__ void cp16(uint32_t dst, const void* src) {
    asm volatile("cp.async.cg.shared.global [%0], [%1], 16;" ::"r"(dst), "l"(src));
}
#define CP_COMMIT() asm volatile("cp.async.commit_group;" ::: "memory")
#define CP_WAIT2() asm volatile("cp.async.wait_group 2;" ::: "memory")
#define CP_WAIT1() asm volatile("cp.async.wait_group 1;" ::: "memory")
#define CP_WAIT0() asm volatile("cp.async.wait_group 0;" ::: "memory")

__device__ __forceinline__ void ldmx4(uint32_t* r, uint32_t addr) {
    asm volatile("ldmatrix.sync.aligned.m8n8.x4.shared.b16 {%0,%1,%2,%3}, [%4];"
                 : "=r"(r[0]), "=r"(r[1]), "=r"(r[2]), "=r"(r[3])
                 : "r"(addr));
}
__device__ __forceinline__ void mma16816(float* d, const uint32_t* a, const uint32_t* b) {
    asm volatile(
        "mma.sync.aligned.m16n8k16.row.col.f32.bf16.bf16.f32 "
        "{%0,%1,%2,%3}, {%4,%5,%6,%7}, {%8,%9}, {%0,%1,%2,%3};"
        : "+f"(d[0]), "+f"(d[1]), "+f"(d[2]), "+f"(d[3])
        : "r"(a[0]), "r"(a[1]), "r"(a[2]), "r"(a[3]), "r"(b[0]), "r"(b[1]));
}
__device__ __forceinline__ void store_hl2(__nv_bfloat16* Hh, __nv_bfloat16* Hl, size_t off,
                                          float x, float y) {
    __nv_bfloat16 hx = __float2bfloat16(x), hy = __float2bfloat16(y);
    __nv_bfloat162 h;
    h.x = hx;
    h.y = hy;
    __nv_bfloat162 l;
    l.x = __float2bfloat16(x - __bfloat162float(hx));
    l.y = __float2bfloat16(y - __bfloat162float(hy));
    *(__nv_bfloat162*)(Hh + off) = h;
    *(__nv_bfloat162*)(Hl + off) = l;
}
__device__ __forceinline__ void store_hl1(__nv_bfloat16* Hh, __nv_bfloat16* Hl, size_t off,
                                          float x) {
    __nv_bfloat16 hx = __float2bfloat16(x);
    Hh[off] = hx;
    Hl[off] = __float2bfloat16(x - __bfloat162float(hx));
}

// ============================ scratch globals ===============================
__device__ float g_x[S * DMODEL];
__device__ float g_q[S * DMODEL];
__device__ float g_k[S * DMODEL];
__device__ float g_v[S * DMODEL];
__device__ float g_y[S * DMODEL];
__device__ float g_vmean[DMODEL];
__device__ float g_vpart[16][DMODEL];
__device__ int g_isglob[S];
__device__ int g_mask[S];  // 0 pad, 1 local, 2 global
__device__ int g_globlist[64];
__device__ int g_nglob;
__device__ float g_divhi[512];
__device__ float g_divlo[512];
__device__ float g_gsc[NH * 32 * S];             // global-q scores -> probs (2MB)
__device__ float g_gpart[16 * NH * 32 * DK];     // global-q partial AV (2MB)

#define LSTRIDE (8 * 1024 * 1024)
__device__ __nv_bfloat16 g_wt_hi[NLAYERS * LSTRIDE];
__device__ __nv_bfloat16 g_wt_lo[NLAYERS * LSTRIDE];
__device__ __nv_bfloat16 g_ah[S * DMODEL];  // x / ctx hi
__device__ __nv_bfloat16 g_al[S * DMODEL];  // x / ctx lo
__device__ __nv_bfloat16 g_hh[S * DFF];     // ffn hidden hi
__device__ __nv_bfloat16 g_hl[S * DFF];     // ffn hidden lo

// ============================ reductions ====================================
static __device__ __forceinline__ float warpAllSum(float v) {
#pragma unroll
    for (int o = 16; o; o >>= 1) v += __shfl_xor_sync(0xffffffffu, v, o);
    return v;
}
static __device__ __forceinline__ float warpAllMax(float v) {
#pragma unroll
    for (int o = 16; o; o >>= 1) v = fmaxf(v, __shfl_xor_sync(0xffffffffu, v, o));
    return v;
}
static __device__ __forceinline__ float blockSum256(float v) {
    __shared__ float sh[8];
    int lane = threadIdx.x & 31, w = threadIdx.x >> 5;
    v = warpAllSum(v);
    __syncthreads();
    if (lane == 0) sh[w] = v;
    __syncthreads();
    if (w == 0) {
        float t = (lane < 8) ? sh[lane] : 0.f;
        t = warpAllSum(t);
        if (lane == 0) sh[0] = t;
    }
    __syncthreads();
    return sh[0];
}
static __device__ __forceinline__ float blockMax256(float v) {
    __shared__ float sh[8];
    int lane = threadIdx.x & 31, w = threadIdx.x >> 5;
    v = warpAllMax(v);
    __syncthreads();
    if (lane == 0) sh[w] = v;
    __syncthreads();
    if (w == 0) {
        float t = (lane < 8) ? sh[lane] : neg_inf();
        t = warpAllMax(t);
        if (lane == 0) sh[0] = t;
    }
    __syncthreads();
    return sh[0];
}

// ============================ prep / mask ===================================
__global__ void pediv_kernel() {
    int i = blockIdx.x * 256 + threadIdx.x;
    if (i < 512) {
        double dv = exp(-(double)(2 * i) * (9.210340371976184 / 1024.0));
        float h = (float)dv;
        g_divhi[i] = h;
        g_divlo[i] = (float)(dv - (double)h);
    }
}
__global__ void prep_kernel(const float* __restrict__ enc) {
    int idx = blockIdx.x * 256 + threadIdx.x;
    int s = idx >> 10, d = idx & 1023;
    int i = d >> 1;
    float hi = g_divhi[i], lo = g_divlo[i];
    float sf = (float)s;
    float h = sf * hi;
    float e = fmaf(sf, hi, -h);
    float t = fmaf(sf, lo, e);
    const float P2HI = 6.28318548202514648f;
    const float P2LO = -1.74845553e-7f;
    float n = rintf(h * 0.15915494309189535f);
    float r = fmaf(-n, P2HI, h);
    r = fmaf(-n, P2LO, r);
    r += t;
    float pe = (d & 1) ? cosf(r) : sinf(r);
    float x = 2.0f * enc[idx] + pe;
    g_x[idx] = x;
    store_hl1(g_ah, g_al, idx, x);
}
__global__ void mask_zero_kernel() {
    int i = blockIdx.x * 256 + threadIdx.x;
    if (i < S) g_isglob[i] = 0;
}
__global__ void mask_scatter_kernel(const int* __restrict__ gidx) {
    int t = threadIdx.x;
    if (t < 32) {
        int g = gidx[t] / 15;
        if (g >= 0 && g < S) g_isglob[g] = 1;
    }
}
__global__ void mask_build_kernel(const int* __restrict__ Tp) {
    int i = blockIdx.x * 256 + threadIdx.x;
    if (i < S) {
        int T = *Tp;
        g_mask[i] = g_isglob[i] ? 2 : (i < T ? 1 : 0);
    }
}
__global__ void mask_list_kernel() {
    int lane = threadIdx.x;
    int cnt = 0;
    for (int base = 0; base < S; base += 32) {
        int m = (g_mask[base + lane] == 2);
        unsigned bal = __ballot_sync(0xffffffffu, m);
        if (m) g_globlist[cnt + __popc(bal & ((1u << lane) - 1u))] = base + lane;
        cnt += __popc(bal);
    }
    if (lane == 0) g_nglob = cnt;
}

// ============================ fused weight transpose/split ==================
// All 24 weight matrices in one launch. z: l = z/6, m = z%6.
__global__ void tsplit_all_kernel(const float* __restrict__ Wq, const float* __restrict__ Wk,
                                  const float* __restrict__ Wv, const float* __restrict__ Wo,
                                  const float* __restrict__ W1, const float* __restrict__ W2,
                                  __nv_bfloat16* __restrict__ hi, __nv_bfloat16* __restrict__ lo) {
    const size_t M1 = 1024u * 1024u;
    int z = blockIdx.z;
    int l = z / 6, m = z % 6;
    const float* W;
    int K, N;
    size_t doff = (size_t)l * LSTRIDE;
    if (m == 0) { W = Wq + l * M1; K = 1024; N = 1024; }
    else if (m == 1) { W = Wk + l * M1; K = 1024; N = 1024; doff += M1; }
    else if (m == 2) { W = Wv + l * M1; K = 1024; N = 1024; doff += 2 * M1; }
    else if (m == 3) { W = Wo + l * M1; K = 1024; N = 1024; doff += 3 * M1; }
    else if (m == 4) { W = W1 + l * 2 * M1; K = 1024; N = 2048; doff += 4 * M1; }
    else { W = W2 + l * 2 * M1; K = 2048; N = 1024; doff += 6 * M1; }
    int n0 = blockIdx.x * 32, k0 = blockIdx.y * 32;
    if (n0 >= N || k0 >= K) return;
    __shared__ float t[32][33];
    int tx = threadIdx.x, ty = threadIdx.y;
#pragma unroll
    for (int i = 0; i < 32; i += 8) t[ty + i][tx] = W[(size_t)(k0 + ty + i) * N + n0 + tx];
    __syncthreads();
#pragma unroll
    for (int i = 0; i < 32; i += 8) {
        float x = t[tx][ty + i];
        __nv_bfloat16 h = __float2bfloat16(x);
        size_t o = doff + (size_t)(n0 + ty + i) * K + k0 + tx;
        hi[o] = h;
        lo[o] = __float2bfloat16(x - __bfloat162float(h));
    }
}

// ============================ bf16x3 HMMA GEMM ==============================
// 128x128 tile, BK=32, 3-stage cp.async pipeline, 8 warps (64x32 each).
#define TSTRIDE 80
#define TILE_B (128 * TSTRIDE)
#define STAGE_B (4 * TILE_B)
#define GEMM_SMEM (3 * STAGE_B)  // 122880

__global__ __launch_bounds__(256) void gemm_mma(
    int M, int N, int K, const __nv_bfloat16* __restrict__ Ahi,
    const __nv_bfloat16* __restrict__ Alo, const __nv_bfloat16* B0h, const __nv_bfloat16* B0l,
    float* C0, const __nv_bfloat16* B1h, const __nv_bfloat16* B1l, float* C1,
    const __nv_bfloat16* B2h, const __nv_bfloat16* B2l, float* C2, int relu,
    __nv_bfloat16* Hh, __nv_bfloat16* Hl) {
    extern __shared__ char sm[];
    const __nv_bfloat16 *Bh, *Bl;
    float* C;
    int z = blockIdx.z;
    if (z == 0) { Bh = B0h; Bl = B0l; C = C0; }
    else if (z == 1) { Bh = B1h; Bl = B1l; C = C1; }
    else { Bh = B2h; Bl = B2l; C = C2; }

    uint32_t smb = smem_u32(sm);
    int tid = threadIdx.x, wid = tid >> 5, lane = tid & 31;
    int row0 = blockIdx.y * 128, col0 = blockIdx.x * 128;
    int wm = wid >> 2, wn = wid & 3;

    float acc[4][4][4];
#pragma unroll
    for (int a = 0; a < 4; a++)
#pragma unroll
        for (int b = 0; b < 4; b++)
#pragma unroll
            for (int c = 0; c < 4; c++) acc[a][b][c] = 0.f;

    int cid0 = tid * 2, cid1 = tid * 2 + 1;
    int lr0 = cid0 >> 2, lc0 = (cid0 & 3) * 16;
    int lr1 = cid1 >> 2, lc1 = (cid1 & 3) * 16;

    const __nv_bfloat16* srcs[4] = {Ahi, Alo, Bh, Bl};
    int rbase[4] = {row0, row0, col0, col0};
    const int nch = K / 32;

    // prologue: chunks 0, 1 into stages 0, 1
#pragma unroll
    for (int pc = 0; pc < 2; pc++) {
        uint32_t sb = smb + pc * STAGE_B;
        int k0 = pc * 32;
#pragma unroll
        for (int t = 0; t < 4; t++) {
            const __nv_bfloat16* src = srcs[t];
            uint32_t tb = sb + t * TILE_B;
            cp16(tb + lr0 * TSTRIDE + lc0, src + (size_t)(rbase[t] + lr0) * K + k0 + (lc0 >> 1));
            cp16(tb + lr1 * TSTRIDE + lc1, src + (size_t)(rbase[t] + lr1) * K + k0 + (lc1 >> 1));
        }
        CP_COMMIT();
    }

    for (int c = 0; c < nch; c++) {
        if (c + 2 < nch) {
            int k0 = (c + 2) * 32;
            uint32_t sb = smb + ((c + 2) % 3) * STAGE_B;
#pragma unroll
            for (int t = 0; t < 4; t++) {
                const __nv_bfloat16* src = srcs[t];
                uint32_t tb = sb + t * TILE_B;
                cp16(tb + lr0 * TSTRIDE + lc0,
                     src + (size_t)(rbase[t] + lr0) * K + k0 + (lc0 >> 1));
                cp16(tb + lr1 * TSTRIDE + lc1,
                     src + (size_t)(rbase[t] + lr1) * K + k0 + (lc1 >> 1));
            }
            CP_COMMIT();
            CP_WAIT2();
        } else if (c + 1 < nch) {
            CP_WAIT1();
        } else {
            CP_WAIT0();
        }
        __syncthreads();

        uint32_t base = smb + (c % 3) * STAGE_B;
        uint32_t aH = base, aL = base + TILE_B, bH = base + 2 * TILE_B, bL = base + 3 * TILE_B;
        int arow = wm * 64 + (lane & 15);
        int brow = wn * 32 + (lane & 7) + ((lane >> 4) << 3);
#pragma unroll
        for (int ks = 0; ks < 2; ks++) {
            int akb = ks * 32 + ((lane >> 4) << 4);
            int bkb = ks * 32 + (((lane >> 3) & 1) << 4);
            uint32_t ah[4][4], al[4][4], bh[4][2], bl[4][2];
#pragma unroll
            for (int mf = 0; mf < 4; mf++)
                ldmx4(ah[mf], aH + (uint32_t)(arow + mf * 16) * TSTRIDE + akb);
#pragma unroll
            for (int np = 0; np < 2; np++) {
                uint32_t r4[4];
                ldmx4(r4, bH + (uint32_t)(brow + np * 16) * TSTRIDE + bkb);
                bh[np * 2][0] = r4[0]; bh[np * 2][1] = r4[1];
                bh[np * 2 + 1][0] = r4[2]; bh[np * 2 + 1][1] = r4[3];
                ldmx4(r4, bL + (uint32_t)(brow + np * 16) * TSTRIDE + bkb);
                bl[np * 2][0] = r4[0]; bl[np * 2][1] = r4[1];
                bl[np * 2 + 1][0] = r4[2]; bl[np * 2 + 1][1] = r4[3];
            }
#pragma unroll
            for (int mf = 0; mf < 4; mf++)
                ldmx4(al[mf], aL + (uint32_t)(arow + mf * 16) * TSTRIDE + akb);
#pragma unroll
            for (int mf = 0; mf < 4; mf++)
#pragma unroll
                for (int nf = 0; nf < 4; nf++) mma16816(acc[mf][nf], ah[mf], bh[nf]);
#pragma unroll
            for (int mf = 0; mf < 4; mf++)
#pragma unroll
                for (int nf = 0; nf < 4; nf++) mma16816(acc[mf][nf], ah[mf], bl[nf]);
#pragma unroll
            for (int mf = 0; mf < 4; mf++)
#pragma unroll
                for (int nf = 0; nf < 4; nf++) mma16816(acc[mf][nf], al[mf], bh[nf]);
        }
        __syncthreads();
    }

    int gr = row0 + wm * 64 + (lane >> 2);
    int gc = col0 + wn * 32 + (lane & 3) * 2;
#pragma unroll
    for (int mf = 0; mf < 4; mf++) {
#pragma unroll
        for (int nf = 0; nf < 4; nf++) {
            float* a4 = acc[mf][nf];
            if (relu) {
                a4[0] = fmaxf(a4[0], 0.f);
                a4[1] = fmaxf(a4[1], 0.f);
                a4[2] = fmaxf(a4[2], 0.f);
                a4[3] = fmaxf(a4[3], 0.f);
            }
            size_t o0 = (size_t)(gr + mf * 16) * N + gc + nf * 8;
            size_t o1 = (size_t)(gr + mf * 16 + 8) * N + gc + nf * 8;
            if (Hh) {
                store_hl2(Hh, Hl, o0, a4[0], a4[1]);
                store_hl2(Hh, Hl, o1, a4[2], a4[3]);
            } else {
                float2 v0 = {a4[0], a4[1]};
                float2 v1 = {a4[2], a4[3]};
                *(float2*)(C + o0) = v0;
                *(float2*)(C + o1) = v1;
            }
        }
    }
}

// ============================ LayerNorm =====================================
__global__ __launch_bounds__(256) void ln_kernel(const float* __restrict__ y,
                                                 const float* __restrict__ xin,
                                                 const float* __restrict__ g,
                                                 const float* __restrict__ b,
                                                 float* __restrict__ out,
                                                 __nv_bfloat16* __restrict__ oh,
                                                 __nv_bfloat16* __restrict__ ol) {
    int s = blockIdx.x, tid = threadIdx.x;
    const float* yr = y + (size_t)s * DMODEL;
    const float* xr = xin + (size_t)s * DMODEL;
    float v[4];
    float sum = 0.f;
#pragma unroll
    for (int i = 0; i < 4; i++) {
        int d = tid + (i << 8);
        v[i] = yr[d] + xr[d];
        sum += v[i];
    }
    float mean = blockSum256(sum) * (1.f / 1024.f);
    float sq = 0.f;
#pragma unroll
    for (int i = 0; i < 4; i++) {
        float t = v[i] - mean;
        sq += t * t;
    }
    float var = blockSum256(sq) * (1.f / 1024.f);
    float inv = 1.f / sqrtf(var + 1e-5f);
    float* orow = out + (size_t)s * DMODEL;
#pragma unroll
    for (int i = 0; i < 4; i++) {
        int d = tid + (i << 8);
        float o = g[d] * (v[i] - mean) * inv + b[d];
        orow[d] = o;
        store_hl1(oh, ol, (size_t)s * DMODEL + d, o);
    }
}

// ============================ attention: pad rows ===========================
__global__ void vmean_part_kernel() {
    int d = blockIdx.x * 256 + threadIdx.x;
    int slab = blockIdx.y;
    float acc = 0.f;
    for (int s = slab * 128; s < (slab + 1) * 128; s++) acc += g_v[(size_t)s * DMODEL + d];
    g_vpart[slab][d] = acc;
}
__global__ void vmean_reduce_kernel() {
    int d = blockIdx.x * 256 + threadIdx.x;
    float a = 0.f;
#pragma unroll
    for (int i = 0; i < 16; i++) a += g_vpart[i][d];
    g_vmean[d] = a * (1.f / (float)S);
}
__global__ void attn_pad_kernel(__nv_bfloat16* __restrict__ ch, __nv_bfloat16* __restrict__ cl) {
    int s = blockIdx.y;
    if (g_mask[s] != 0) return;
    int d = blockIdx.x * 256 + threadIdx.x;
    store_hl1(ch, cl, (size_t)s * DMODEL + d, g_vmean[d]);
}

// ============================ attention: local rows =========================
#define SMEM_LOCAL_BYTES (((128 * 129 * 2 + 32 * 128 * 2) * 4) + 128 * 4)
__global__ __launch_bounds__(256) void attn_local_kernel(__nv_bfloat16* __restrict__ ch,
                                                         __nv_bfloat16* __restrict__ cl) {
    extern __shared__ float smf[];
    float* Ks = smf;
    float* Vs = Ks + 128 * 129;
    float* Qs = Vs + 128 * 129;
    float* probs = Qs + 32 * 128;
    int* cand = (int*)(probs + 32 * 128);
    __shared__ int s_nc;

    int tid = threadIdx.x;
    int h = blockIdx.y, q0 = blockIdx.x * 32, base = h * DK;

    if (tid < 96) {
        int k = q0 - 32 + tid;
        cand[tid] = (k >= 0 && k < S) ? k : -1;
    }
    if (tid == 0) {
        int cnt = 96, ng = g_nglob;
        for (int i = 0; i < ng; i++) {
            int g = g_globlist[i];
            if (g < q0 - 32 || g > q0 + 63) cand[cnt++] = g;
        }
        s_nc = cnt;
    }
    __syncthreads();
    int nc = s_nc;

    for (int e = tid; e < 128 * 128; e += 256) {
        int j = e >> 7, d = e & 127;
        int k = (j < nc) ? cand[j] : -1;
        float kv = 0.f, vv = 0.f;
        if (k >= 0) {
            kv = g_k[(size_t)k * DMODEL + base + d];
            vv = g_v[(size_t)k * DMODEL + base + d];
        }
        Ks[j * 129 + d] = kv;
        Vs[j * 129 + d] = vv;
    }
    for (int e = tid; e < 32 * 128; e += 256) {
        int r = e >> 7, d = e & 127;
        Qs[e] = g_q[(size_t)(q0 + r) * DMODEL + base + d];
    }
    __syncthreads();

    int warp = tid >> 5, lane = tid & 31;
    const float NI = neg_inf();
#pragma unroll
    for (int rr = 0; rr < 4; rr++) {
        int r = warp * 4 + rr, q = q0 + r;
        bool active = (g_mask[q] == 1);
        float sv[4];
#pragma unroll
        for (int m = 0; m < 4; m++) {
            int j = lane + (m << 5);
            float val = NI;
            if (active && j < nc) {
                int k = cand[j];
                if (k >= 0) {
                    int mk = g_mask[k];
                    int dd = q - k;
                    if (dd < 0) dd = -dd;
                    bool ok = (mk != 0) && ((j >= 96) || (mk == 2) || (dd <= 32));
                    if (ok) {
                        float sd = 0.f;
                        const float* qp = &Qs[r * 128];
                        const float* kp = &Ks[j * 129];
#pragma unroll 16
                        for (int d = 0; d < 128; d++) sd += qp[d] * kp[d];
                        val = sd * SCALE_F;
                    }
                }
            }
            sv[m] = val;
        }
        float mx = fmaxf(fmaxf(sv[0], sv[1]), fmaxf(sv[2], sv[3]));
#pragma unroll
        for (int o = 16; o; o >>= 1) mx = fmaxf(mx, __shfl_xor_sync(0xffffffffu, mx, o));
        float p[4];
        float sum = 0.f;
#pragma unroll
        for (int m = 0; m < 4; m++) {
            p[m] = (sv[m] == NI) ? 0.f : expf(sv[m] - mx);
            sum += p[m];
        }
#pragma unroll
        for (int o = 16; o; o >>= 1) sum += __shfl_xor_sync(0xffffffffu, sum, o);
        if (active) {
            float inv = 1.f / sum;
#pragma unroll
            for (int m = 0; m < 4; m++) {
                int j = lane + (m << 5);
                probs[r * 128 + j] = p[m] * inv;
            }
        }
    }
    __syncthreads();
    for (int e = tid; e < 32 * 128; e += 256) {
        int r = e >> 7, d = e & 127;
        int q = q0 + r;
        if (g_mask[q] != 1) continue;
        float acc = 0.f;
        const float* pr = &probs[r * 128];
#pragma unroll 4
        for (int j = 0; j < nc; j++) acc += pr[j] * Vs[j * 129 + d];
        store_hl1(ch, cl, (size_t)q * DMODEL + base + d, acc);
    }
}

// ============================ attention: global rows (slab-parallel) ========
// Phase A: scores[h][qi][k] for k in slab. grid(16 slabs, 8 heads).
#define SMEM_GA ((128 * 129 + 32 * 128) * 4)
__global__ __launch_bounds__(256) void ga_scores_kernel() {
    extern __shared__ float smf[];
    float* Ks = smf;                 // 128 x 129
    float* Qs = Ks + 128 * 129;      // 32 x 128
    int slab = blockIdx.x, h = blockIdx.y, tid = threadIdx.x;
    int ng = g_nglob;
    for (int e = tid; e < 128 * 128; e += 256) {
        int j = e >> 7, d = e & 127;
        Ks[j * 129 + d] = g_k[(size_t)(slab * 128 + j) * DMODEL + h * DK + d];
    }
    for (int e = tid; e < 32 * 128; e += 256) {
        int r = e >> 7, d = e & 127;
        Qs[e] = (r < ng) ? g_q[(size_t)g_globlist[r] * DMODEL + h * DK + d] : 0.f;
    }
    __syncthreads();
    int kk = tid & 127, half = tid >> 7;
    int k = slab * 128 + kk;
    bool nonpad = (g_mask[k] != 0);
    for (int qi = half; qi < ng; qi += 2) {
        float sd = 0.f;
        const float* qp = &Qs[qi * 128];
        const float* kp = &Ks[kk * 129];
#pragma unroll 16
        for (int d = 0; d < 128; d++) sd += qp[d] * kp[d];
        g_gsc[((size_t)h * 32 + qi) * S + k] = nonpad ? sd * SCALE_F : neg_inf();
    }
}
// Phase B: softmax over full row. grid(32, 8).
__global__ __launch_bounds__(256) void ga_softmax_kernel() {
    int qi = blockIdx.x, h = blockIdx.y, tid = threadIdx.x;
    if (qi >= g_nglob) return;
    float* row = g_gsc + ((size_t)h * 32 + qi) * S;
    const float NI = neg_inf();
    float mx = NI;
    for (int k = tid; k < S; k += 256) mx = fmaxf(mx, row[k]);
    mx = blockMax256(mx);
    float sum = 0.f;
    for (int k = tid; k < S; k += 256) {
        float v = row[k];
        float p = (v == NI) ? 0.f : expf(v - mx);
        row[k] = p;
        sum += p;
    }
    sum = blockSum256(sum);
    float inv = 1.f / sum;
    for (int k = tid; k < S; k += 256) row[k] *= inv;
}
// Phase C: partial AV per slab. grid(16, 8).
__global__ __launch_bounds__(256) void ga_av_kernel() {
    extern __shared__ float smf[];
    float* Vs = smf;                 // 128 x 129
    float* Ps = Vs + 128 * 129;      // 32 x 128
    int slab = blockIdx.x, h = blockIdx.y, tid = threadIdx.x;
    int ng = g_nglob;
    for (int e = tid; e < 128 * 128; e += 256) {
        int j = e >> 7, d = e & 127;
        Vs[j * 129 + d] = g_v[(size_t)(slab * 128 + j) * DMODEL + h * DK + d];
    }
    for (int e = tid; e < 32 * 128; e += 256) {
        int r = e >> 7, kk = e & 127;
        Ps[e] = (r < ng) ? g_gsc[((size_t)h * 32 + r) * S + slab * 128 + kk] : 0.f;
    }
    __syncthreads();
    int d = tid & 127, half = tid >> 7;
    for (int qi = half; qi < ng; qi += 2) {
        float acc = 0.f;
        const float* pp = &Ps[qi * 128];
#pragma unroll 16
        for (int kk = 0; kk < 128; kk++) acc += pp[kk] * Vs[kk * 129 + d];
        g_gpart[(((size_t)slab * NH + h) * 32 + qi) * DK + d] = acc;
    }
}
// Phase D: reduce 16 slabs + store ctx hi/lo. grid(32, 8), 128 threads.
__global__ __launch_bounds__(128) void ga_out_kernel(__nv_bfloat16* __restrict__ ch,
                                                     __nv_bfloat16* __restrict__ cl) {
    int qi = blockIdx.x, h = blockIdx.y, d = threadIdx.x;
    if (qi >= g_nglob) return;
    float s = 0.f;
#pragma unroll
    for (int slab = 0; slab < 16; slab++)
        s += g_gpart[(((size_t)slab * NH + h) * 32 + qi) * DK + d];
    int q = g_globlist[qi];
    store_hl1(ch, cl, (size_t)q * DMODEL + h * DK + d, s);
}

// ============================ driver ========================================
extern "C" void kernel_launch(void* const* d_in, const int* in_sizes, int n_in,
                              void* d_out, int out_size) {
    const int* Tp = (const int*)d_in[0];
    const float* enc = (const float*)d_in[1];
    const int* gidx = (const int*)d_in[2];
    const float* Wq = (const float*)d_in[3];
    const float* Wk = (const float*)d_in[4];
    const float* Wv = (const float*)d_in[5];
    const float* Wo = (const float*)d_in[6];
    const float* ln1g = (const float*)d_in[7];
    const float* ln1b = (const float*)d_in[8];
    const float* W1 = (const float*)d_in[9];
    const float* W2 = (const float*)d_in[10];
    const float* ln2g = (const float*)d_in[11];
    const float* ln2b = (const float*)d_in[12];
    float* out = (float*)d_out;

    cudaFuncSetAttribute(attn_local_kernel, cudaFuncAttributeMaxDynamicSharedMemorySize,
                         SMEM_LOCAL_BYTES);
    cudaFuncSetAttribute(ga_scores_kernel, cudaFuncAttributeMaxDynamicSharedMemorySize, SMEM_GA);
    cudaFuncSetAttribute(ga_av_kernel, cudaFuncAttributeMaxDynamicSharedMemorySize, SMEM_GA);
    cudaFuncSetAttribute(gemm_mma, cudaFuncAttributeMaxDynamicSharedMemorySize, GEMM_SMEM);

    float *px, *pq, *pk, *pv, *py;
    __nv_bfloat16 *pwh, *pwl, *pah, *pal, *phh, *phl;
    cudaGetSymbolAddress((void**)&px, g_x);
    cudaGetSymbolAddress((void**)&pq, g_q);
    cudaGetSymbolAddress((void**)&pk, g_k);
    cudaGetSymbolAddress((void**)&pv, g_v);
    cudaGetSymbolAddress((void**)&py, g_y);
    cudaGetSymbolAddress((void**)&pwh, g_wt_hi);
    cudaGetSymbolAddress((void**)&pwl, g_wt_lo);
    cudaGetSymbolAddress((void**)&pah, g_ah);
    cudaGetSymbolAddress((void**)&pal, g_al);
    cudaGetSymbolAddress((void**)&phh, g_hh);
    cudaGetSymbolAddress((void**)&phl, g_hl);

    const size_t M1 = 1024u * 1024u;

    // launch order: pediv(0), prep(1), tsplit_all(2), QKV gemm(3) — so the
    // profiler's early-launch window lands on the HMMA gemm.
    pediv_kernel<<<2, 256>>>();
    prep_kernel<<<(S * DMODEL) / 256, 256>>>(enc);
    tsplit_all_kernel<<<dim3(64, 64, 24), dim3(32, 8)>>>(Wq, Wk, Wv, Wo, W1, W2, pwh, pwl);
    gemm_mma<<<dim3(DMODEL / 128, S / 128, 3), 256, GEMM_SMEM>>>(
        S, DMODEL, DMODEL, pah, pal, pwh, pwl, pq, pwh + M1, pwl + M1, pk, pwh + 2 * M1,
        pwl + 2 * M1, pv, 0, nullptr, nullptr);

    mask_zero_kernel<<<8, 256>>>();
    mask_scatter_kernel<<<1, 32>>>(gidx);
    mask_build_kernel<<<8, 256>>>(Tp);
    mask_list_kernel<<<1, 32>>>();

    for (int l = 0; l < NLAYERS; l++) {
        size_t wo_ = (size_t)l * LSTRIDE;
        if (l > 0) {
            gemm_mma<<<dim3(DMODEL / 128, S / 128, 3), 256, GEMM_SMEM>>>(
                S, DMODEL, DMODEL, pah, pal, pwh + wo_, pwl + wo_, pq, pwh + wo_ + M1,
                pwl + wo_ + M1, pk, pwh + wo_ + 2 * M1, pwl + wo_ + 2 * M1, pv, 0, nullptr,
                nullptr);
        }

        vmean_part_kernel<<<dim3(DMODEL / 256, 16), 256>>>();
        vmean_reduce_kernel<<<DMODEL / 256, 256>>>();
        attn_local_kernel<<<dim3(S / 32, NH), 256, SMEM_LOCAL_BYTES>>>(pah, pal);
        ga_scores_kernel<<<dim3(16, NH), 256, SMEM_GA>>>();
        ga_softmax_kernel<<<dim3(32, NH), 256>>>();
        ga_av_kernel<<<dim3(16, NH), 256, SMEM_GA>>>();
        ga_out_kernel<<<dim3(32, NH), 128>>>(pah, pal);
        attn_pad_kernel<<<dim3(DMODEL / 256, S), 256>>>(pah, pal);

        // output projection + residual LN
        gemm_mma<<<dim3(DMODEL / 128, S / 128, 1), 256, GEMM_SMEM>>>(
            S, DMODEL, DMODEL, pah, pal, pwh + wo_ + 3 * M1, pwl + wo_ + 3 * M1, py, nullptr,
            nullptr, nullptr, nullptr, nullptr, nullptr, 0, nullptr, nullptr);
        ln_kernel<<<S, 256>>>(py, px, ln1g + l * DMODEL, ln1b + l * DMODEL, px, pah, pal);

        // FFN
        gemm_mma<<<dim3(DFF / 128, S / 128, 1), 256, GEMM_SMEM>>>(
            S, DFF, DMODEL, pah, pal, pwh + wo_ + 4 * M1, pwl + wo_ + 4 * M1, nullptr, nullptr,
            nullptr, nullptr, nullptr, nullptr, nullptr, 1, phh, phl);
        gemm_mma<<<dim3(DMODEL / 128, S / 128, 1), 256, GEMM_SMEM>>>(
            S, DMODEL, DFF, phh, phl, pwh + wo_ + 6 * M1, pwl + wo_ + 6 * M1, py, nullptr,
            nullptr, nullptr, nullptr, nullptr, nullptr, 0, nullptr, nullptr);
        ln_kernel<<<S, 256>>>(py, px, ln2g + l * DMODEL, ln2b + l * DMODEL,
                              (l == NLAYERS - 1) ? out : px, pah, pal);
    }
}

// round 10
// speedup vs baseline: 2.6343x; 1.0601x over previous
#include <cuda_runtime.h>
#include <cuda_bf16.h>
#include <math.h>
#include <stdint.h>

#define S 2048
#define DMODEL 1024
#define DFF 2048
#define NH 8
#define DK 128
#define NLAYERS 4

static __device__ __forceinline__ float neg_inf() { return __int_as_float(0xff800000); }
#define SCALE_F 0.08838834764831845f  // 1/sqrt(128)

// ======================= PTX helpers (base sm_80+ features only) ============
__device__ __forceinline__ uint32_t smem_u32(const void* p) {
    uint32_t a;
    asm("{ .reg .u64 t; cvta.to.shared.u64 t, %1; cvt.u32.u64 %0, t; }" : "=r"(a) : "l"(p));
    return a;
}
__device__ __forceinline__ void cp16(uint32_t dst, const void* src) {
    asm volatile("cp.async.cg.shared.global [%0], [%1], 16;" ::"r"(dst), "l"(src));
}
#define CP_COMMIT() asm volatile("cp.async.commit_group;" ::: "memory")
#define CP_WAIT1() asm volatile("cp.async.wait_group 1;" ::: "memory")
#define CP_WAIT0() asm volatile("cp.async.wait_group 0;" ::: "memory")

__device__ __forceinline__ void ldmx4(uint32_t* r, uint32_t addr) {
    asm volatile("ldmatrix.sync.aligned.m8n8.x4.shared.b16 {%0,%1,%2,%3}, [%4];"
                 : "=r"(r[0]), "=r"(r[1]), "=r"(r[2]), "=r"(r[3])
                 : "r"(addr));
}
__device__ __forceinline__ void mma16816(float* d, const uint32_t* a, const uint32_t* b) {
    asm volatile(
        "mma.sync.aligned.m16n8k16.row.col.f32.bf16.bf16.f32 "
        "{%0,%1,%2,%3}, {%4,%5,%6,%7}, {%8,%9}, {%0,%1,%2,%3};"
        : "+f"(d[0]), "+f"(d[1]), "+f"(d[2]), "+f"(d[3])
        : "r"(a[0]), "r"(a[1]), "r"(a[2]), "r"(a[3]), "r"(b[0]), "r"(b[1]));
}
__device__ __forceinline__ void store_hl2(__nv_bfloat16* Hh, __nv_bfloat16* Hl, size_t off,
                                          float x, float y) {
    __nv_bfloat16 hx = __float2bfloat16(x), hy = __float2bfloat16(y);
    __nv_bfloat162 h;
    h.x = hx;
    h.y = hy;
    __nv_bfloat162 l;
    l.x = __float2bfloat16(x - __bfloat162float(hx));
    l.y = __float2bfloat16(y - __bfloat162float(hy));
    *(__nv_bfloat162*)(Hh + off) = h;
    *(__nv_bfloat162*)(Hl + off) = l;
}
__device__ __forceinline__ void store_hl1(__nv_bfloat16* Hh, __nv_bfloat16* Hl, size_t off,
                                          float x) {
    __nv_bfloat16 hx = __float2bfloat16(x);
    Hh[off] = hx;
    Hl[off] = __float2bfloat16(x - __bfloat162float(hx));
}

// ============================ scratch globals ===============================
__device__ float g_x[S * DMODEL];
__device__ float g_q[S * DMODEL];
__device__ float g_k[S * DMODEL];
__device__ float g_v[S * DMODEL];
__device__ float g_y[S * DMODEL];
__device__ float g_vmean[DMODEL];
__device__ float g_vpart[16][DMODEL];
__device__ int g_isglob[S];
__device__ int g_mask[S];  // 0 pad, 1 local, 2 global
__device__ int g_globlist[64];
__device__ int g_nglob;
__device__ float g_divhi[512];
__device__ float g_divlo[512];
__device__ float g_gsc[NH * 32 * S];          // global-q scores -> probs
__device__ float g_gpart[16 * NH * 32 * DK];  // global-q partial AV

#define LSTRIDE (8 * 1024 * 1024)
__device__ __nv_bfloat16 g_wt_hi[NLAYERS * LSTRIDE];
__device__ __nv_bfloat16 g_wt_lo[NLAYERS * LSTRIDE];
__device__ __nv_bfloat16 g_ah[S * DMODEL];
__device__ __nv_bfloat16 g_al[S * DMODEL];
__device__ __nv_bfloat16 g_hh[S * DFF];
__device__ __nv_bfloat16 g_hl[S * DFF];

// ============================ reductions ====================================
static __device__ __forceinline__ float warpAllSum(float v) {
#pragma unroll
    for (int o = 16; o; o >>= 1) v += __shfl_xor_sync(0xffffffffu, v, o);
    return v;
}
static __device__ __forceinline__ float warpAllMax(float v) {
#pragma unroll
    for (int o = 16; o; o >>= 1) v = fmaxf(v, __shfl_xor_sync(0xffffffffu, v, o));
    return v;
}
static __device__ __forceinline__ float blockSum256(float v) {
    __shared__ float sh[8];
    int lane = threadIdx.x & 31, w = threadIdx.x >> 5;
    v = warpAllSum(v);
    __syncthreads();
    if (lane == 0) sh[w] = v;
    __syncthreads();
    if (w == 0) {
        float t = (lane < 8) ? sh[lane] : 0.f;
        t = warpAllSum(t);
        if (lane == 0) sh[0] = t;
    }
    __syncthreads();
    return sh[0];
}
static __device__ __forceinline__ float blockMax256(float v) {
    __shared__ float sh[8];
    int lane = threadIdx.x & 31, w = threadIdx.x >> 5;
    v = warpAllMax(v);
    __syncthreads();
    if (lane == 0) sh[w] = v;
    __syncthreads();
    if (w == 0) {
        float t = (lane < 8) ? sh[lane] : neg_inf();
        t = warpAllMax(t);
        if (lane == 0) sh[0] = t;
    }
    __syncthreads();
    return sh[0];
}

// ============================ prep / mask ===================================
__global__ void pediv_kernel() {
    int i = blockIdx.x * 256 + threadIdx.x;
    if (i < 512) {
        double dv = exp(-(double)(2 * i) * (9.210340371976184 / 1024.0));
        float h = (float)dv;
        g_divhi[i] = h;
        g_divlo[i] = (float)(dv - (double)h);
    }
}
__global__ void prep_kernel(const float* __restrict__ enc) {
    int idx = blockIdx.x * 256 + threadIdx.x;
    int s = idx >> 10, d = idx & 1023;
    int i = d >> 1;
    float hi = g_divhi[i], lo = g_divlo[i];
    float sf = (float)s;
    float h = sf * hi;
    float e = fmaf(sf, hi, -h);
    float t = fmaf(sf, lo, e);
    const float P2HI = 6.28318548202514648f;
    const float P2LO = -1.74845553e-7f;
    float n = rintf(h * 0.15915494309189535f);
    float r = fmaf(-n, P2HI, h);
    r = fmaf(-n, P2LO, r);
    r += t;
    float pe = (d & 1) ? cosf(r) : sinf(r);
    float x = 2.0f * enc[idx] + pe;
    g_x[idx] = x;
    store_hl1(g_ah, g_al, idx, x);
}
__global__ void mask_zero_kernel() {
    int i = blockIdx.x * 256 + threadIdx.x;
    if (i < S) g_isglob[i] = 0;
}
__global__ void mask_scatter_kernel(const int* __restrict__ gidx) {
    int t = threadIdx.x;
    if (t < 32) {
        int g = gidx[t] / 15;
        if (g >= 0 && g < S) g_isglob[g] = 1;
    }
}
__global__ void mask_build_kernel(const int* __restrict__ Tp) {
    int i = blockIdx.x * 256 + threadIdx.x;
    if (i < S) {
        int T = *Tp;
        g_mask[i] = g_isglob[i] ? 2 : (i < T ? 1 : 0);
    }
}
__global__ void mask_list_kernel() {
    int lane = threadIdx.x;
    int cnt = 0;
    for (int base = 0; base < S; base += 32) {
        int m = (g_mask[base + lane] == 2);
        unsigned bal = __ballot_sync(0xffffffffu, m);
        if (m) g_globlist[cnt + __popc(bal & ((1u << lane) - 1u))] = base + lane;
        cnt += __popc(bal);
    }
    if (lane == 0) g_nglob = cnt;
}

// ============================ fused weight transpose/split ==================
__global__ void tsplit_all_kernel(const float* __restrict__ Wq, const float* __restrict__ Wk,
                                  const float* __restrict__ Wv, const float* __restrict__ Wo,
                                  const float* __restrict__ W1, const float* __restrict__ W2,
                                  __nv_bfloat16* __restrict__ hi, __nv_bfloat16* __restrict__ lo) {
    const size_t M1 = 1024u * 1024u;
    int z = blockIdx.z;
    int l = z / 6, m = z % 6;
    const float* W;
    int K, N;
    size_t doff = (size_t)l * LSTRIDE;
    if (m == 0) { W = Wq + l * M1; K = 1024; N = 1024; }
    else if (m == 1) { W = Wk + l * M1; K = 1024; N = 1024; doff += M1; }
    else if (m == 2) { W = Wv + l * M1; K = 1024; N = 1024; doff += 2 * M1; }
    else if (m == 3) { W = Wo + l * M1; K = 1024; N = 1024; doff += 3 * M1; }
    else if (m == 4) { W = W1 + l * 2 * M1; K = 1024; N = 2048; doff += 4 * M1; }
    else { W = W2 + l * 2 * M1; K = 2048; N = 1024; doff += 6 * M1; }
    int n0 = blockIdx.x * 32, k0 = blockIdx.y * 32;
    if (n0 >= N || k0 >= K) return;
    __shared__ float t[32][33];
    int tx = threadIdx.x, ty = threadIdx.y;
#pragma unroll
    for (int i = 0; i < 32; i += 8) t[ty + i][tx] = W[(size_t)(k0 + ty + i) * N + n0 + tx];
    __syncthreads();
#pragma unroll
    for (int i = 0; i < 32; i += 8) {
        float x = t[tx][ty + i];
        __nv_bfloat16 h = __float2bfloat16(x);
        size_t o = doff + (size_t)(n0 + ty + i) * K + k0 + tx;
        hi[o] = h;
        lo[o] = __float2bfloat16(x - __bfloat162float(h));
    }
}

// ============================ bf16x3 HMMA GEMM ==============================
// 128x128 tile, BK=32, 2-stage cp.async, 8 warps, 2 CTAs/SM (regs<=128).
#define TSTRIDE 80
#define TILE_B (128 * TSTRIDE)
#define STAGE_B (4 * TILE_B)
#define GEMM_SMEM (2 * STAGE_B)  // 81920

__global__ __launch_bounds__(256, 2) void gemm_mma(
    int M, int N, int K, const __nv_bfloat16* __restrict__ Ahi,
    const __nv_bfloat16* __restrict__ Alo, const __nv_bfloat16* B0h, const __nv_bfloat16* B0l,
    float* C0, const __nv_bfloat16* B1h, const __nv_bfloat16* B1l, float* C1,
    const __nv_bfloat16* B2h, const __nv_bfloat16* B2l, float* C2, int relu,
    __nv_bfloat16* Hh, __nv_bfloat16* Hl) {
    extern __shared__ char sm[];
    const __nv_bfloat16 *Bh, *Bl;
    float* C;
    int z = blockIdx.z;
    if (z == 0) { Bh = B0h; Bl = B0l; C = C0; }
    else if (z == 1) { Bh = B1h; Bl = B1l; C = C1; }
    else { Bh = B2h; Bl = B2l; C = C2; }

    uint32_t smb = smem_u32(sm);
    int tid = threadIdx.x, wid = tid >> 5, lane = tid & 31;
    int row0 = blockIdx.y * 128, col0 = blockIdx.x * 128;
    int wm = wid >> 2, wn = wid & 3;

    float acc[4][4][4];
#pragma unroll
    for (int a = 0; a < 4; a++)
#pragma unroll
        for (int b = 0; b < 4; b++)
#pragma unroll
            for (int c = 0; c < 4; c++) acc[a][b][c] = 0.f;

    int cid0 = tid * 2, cid1 = tid * 2 + 1;
    int lr0 = cid0 >> 2, lc0 = (cid0 & 3) * 16;
    int lr1 = cid1 >> 2, lc1 = (cid1 & 3) * 16;

    const __nv_bfloat16* srcs[4] = {Ahi, Alo, Bh, Bl};
    int rbase[4] = {row0, row0, col0, col0};
    const int nch = K / 32;

    // prologue: chunk 0 -> stage 0
    {
#pragma unroll
        for (int t = 0; t < 4; t++) {
            const __nv_bfloat16* src = srcs[t];
            uint32_t tb = smb + t * TILE_B;
            cp16(tb + lr0 * TSTRIDE + lc0, src + (size_t)(rbase[t] + lr0) * K + (lc0 >> 1));
            cp16(tb + lr1 * TSTRIDE + lc1, src + (size_t)(rbase[t] + lr1) * K + (lc1 >> 1));
        }
        CP_COMMIT();
    }

    for (int c = 0; c < nch; c++) {
        if (c + 1 < nch) {
            int k0 = (c + 1) * 32;
            uint32_t sb = smb + ((c + 1) & 1) * STAGE_B;
#pragma unroll
            for (int t = 0; t < 4; t++) {
                const __nv_bfloat16* src = srcs[t];
                uint32_t tb = sb + t * TILE_B;
                cp16(tb + lr0 * TSTRIDE + lc0,
                     src + (size_t)(rbase[t] + lr0) * K + k0 + (lc0 >> 1));
                cp16(tb + lr1 * TSTRIDE + lc1,
                     src + (size_t)(rbase[t] + lr1) * K + k0 + (lc1 >> 1));
            }
            CP_COMMIT();
            CP_WAIT1();
        } else {
            CP_WAIT0();
        }
        __syncthreads();

        uint32_t base = smb + (c & 1) * STAGE_B;
        uint32_t aH = base, aL = base + TILE_B, bH = base + 2 * TILE_B, bL = base + 3 * TILE_B;
        int arow = wm * 64 + (lane & 15);
        int brow = wn * 32 + (lane & 7) + ((lane >> 4) << 3);
#pragma unroll
        for (int ks = 0; ks < 2; ks++) {
            int akb = ks * 32 + ((lane >> 4) << 4);
            int bkb = ks * 32 + (((lane >> 3) & 1) << 4);
            uint32_t ah[4][4], al[4][4], bh[4][2], bl[4][2];
#pragma unroll
            for (int mf = 0; mf < 4; mf++)
                ldmx4(ah[mf], aH + (uint32_t)(arow + mf * 16) * TSTRIDE + akb);
#pragma unroll
            for (int np = 0; np < 2; np++) {
                uint32_t r4[4];
                ldmx4(r4, bH + (uint32_t)(brow + np * 16) * TSTRIDE + bkb);
                bh[np * 2][0] = r4[0]; bh[np * 2][1] = r4[1];
                bh[np * 2 + 1][0] = r4[2]; bh[np * 2 + 1][1] = r4[3];
                ldmx4(r4, bL + (uint32_t)(brow + np * 16) * TSTRIDE + bkb);
                bl[np * 2][0] = r4[0]; bl[np * 2][1] = r4[1];
                bl[np * 2 + 1][0] = r4[2]; bl[np * 2 + 1][1] = r4[3];
            }
#pragma unroll
            for (int mf = 0; mf < 4; mf++)
                ldmx4(al[mf], aL + (uint32_t)(arow + mf * 16) * TSTRIDE + akb);
#pragma unroll
            for (int mf = 0; mf < 4; mf++)
#pragma unroll
                for (int nf = 0; nf < 4; nf++) mma16816(acc[mf][nf], ah[mf], bh[nf]);
#pragma unroll
            for (int mf = 0; mf < 4; mf++)
#pragma unroll
                for (int nf = 0; nf < 4; nf++) mma16816(acc[mf][nf], ah[mf], bl[nf]);
#pragma unroll
            for (int mf = 0; mf < 4; mf++)
#pragma unroll
                for (int nf = 0; nf < 4; nf++) mma16816(acc[mf][nf], al[mf], bh[nf]);
        }
        __syncthreads();
    }

    int gr = row0 + wm * 64 + (lane >> 2);
    int gc = col0 + wn * 32 + (lane & 3) * 2;
#pragma unroll
    for (int mf = 0; mf < 4; mf++) {
#pragma unroll
        for (int nf = 0; nf < 4; nf++) {
            float* a4 = acc[mf][nf];
            if (relu) {
                a4[0] = fmaxf(a4[0], 0.f);
                a4[1] = fmaxf(a4[1], 0.f);
                a4[2] = fmaxf(a4[2], 0.f);
                a4[3] = fmaxf(a4[3], 0.f);
            }
            size_t o0 = (size_t)(gr + mf * 16) * N + gc + nf * 8;
            size_t o1 = (size_t)(gr + mf * 16 + 8) * N + gc + nf * 8;
            if (Hh) {
                store_hl2(Hh, Hl, o0, a4[0], a4[1]);
                store_hl2(Hh, Hl, o1, a4[2], a4[3]);
            } else {
                float2 v0 = {a4[0], a4[1]};
                float2 v1 = {a4[2], a4[3]};
                *(float2*)(C + o0) = v0;
                *(float2*)(C + o1) = v1;
            }
        }
    }
}

// ============================ LayerNorm =====================================
__global__ __launch_bounds__(256) void ln_kernel(const float* __restrict__ y,
                                                 const float* __restrict__ xin,
                                                 const float* __restrict__ g,
                                                 const float* __restrict__ b,
                                                 float* __restrict__ out,
                                                 __nv_bfloat16* __restrict__ oh,
                                                 __nv_bfloat16* __restrict__ ol) {
    int s = blockIdx.x, tid = threadIdx.x;
    const float* yr = y + (size_t)s * DMODEL;
    const float* xr = xin + (size_t)s * DMODEL;
    float v[4];
    float sum = 0.f;
#pragma unroll
    for (int i = 0; i < 4; i++) {
        int d = tid + (i << 8);
        v[i] = yr[d] + xr[d];
        sum += v[i];
    }
    float mean = blockSum256(sum) * (1.f / 1024.f);
    float sq = 0.f;
#pragma unroll
    for (int i = 0; i < 4; i++) {
        float t = v[i] - mean;
        sq += t * t;
    }
    float var = blockSum256(sq) * (1.f / 1024.f);
    float inv = 1.f / sqrtf(var + 1e-5f);
    float* orow = out + (size_t)s * DMODEL;
#pragma unroll
    for (int i = 0; i < 4; i++) {
        int d = tid + (i << 8);
        float o = g[d] * (v[i] - mean) * inv + b[d];
        orow[d] = o;
        store_hl1(oh, ol, (size_t)s * DMODEL + d, o);
    }
}

// ============================ attention: pad rows ===========================
__global__ void vmean_part_kernel() {
    int d = blockIdx.x * 256 + threadIdx.x;
    int slab = blockIdx.y;
    float acc = 0.f;
    for (int s = slab * 128; s < (slab + 1) * 128; s++) acc += g_v[(size_t)s * DMODEL + d];
    g_vpart[slab][d] = acc;
}
__global__ void vmean_reduce_kernel() {
    int d = blockIdx.x * 256 + threadIdx.x;
    float a = 0.f;
#pragma unroll
    for (int i = 0; i < 16; i++) a += g_vpart[i][d];
    g_vmean[d] = a * (1.f / (float)S);
}
__global__ void attn_pad_kernel(__nv_bfloat16* __restrict__ ch, __nv_bfloat16* __restrict__ cl) {
    int s = blockIdx.y;
    if (g_mask[s] != 0) return;
    int d = blockIdx.x * 256 + threadIdx.x;
    store_hl1(ch, cl, (size_t)s * DMODEL + d, g_vmean[d]);
}

// ============================ attention: local rows =========================
#define SMEM_LOCAL_BYTES (((128 * 129 * 2 + 32 * 128 * 2) * 4) + 128 * 4)
__global__ __launch_bounds__(256) void attn_local_kernel(__nv_bfloat16* __restrict__ ch,
                                                         __nv_bfloat16* __restrict__ cl) {
    extern __shared__ float smf[];
    float* Ks = smf;
    float* Vs = Ks + 128 * 129;
    float* Qs = Vs + 128 * 129;
    float* probs = Qs + 32 * 128;
    int* cand = (int*)(probs + 32 * 128);
    __shared__ int s_nc;

    int tid = threadIdx.x;
    int h = blockIdx.y, q0 = blockIdx.x * 32, base = h * DK;

    if (tid < 96) {
        int k = q0 - 32 + tid;
        cand[tid] = (k >= 0 && k < S) ? k : -1;
    }
    if (tid == 0) {
        int cnt = 96, ng = g_nglob;
        for (int i = 0; i < 96 && i < ng; i++) {}
        cnt = 96;
        for (int i = 0; i < ng; i++) {
            int g = g_globlist[i];
            if (g < q0 - 32 || g > q0 + 63) cand[cnt++] = g;
        }
        s_nc = cnt;
    }
    __syncthreads();
    int nc = s_nc;

    for (int e = tid; e < 128 * 128; e += 256) {
        int j = e >> 7, d = e & 127;
        int k = (j < nc) ? cand[j] : -1;
        float kv = 0.f, vv = 0.f;
        if (k >= 0) {
            kv = g_k[(size_t)k * DMODEL + base + d];
            vv = g_v[(size_t)k * DMODEL + base + d];
        }
        Ks[j * 129 + d] = kv;
        Vs[j * 129 + d] = vv;
    }
    for (int e = tid; e < 32 * 128; e += 256) {
        int r = e >> 7, d = e & 127;
        Qs[e] = g_q[(size_t)(q0 + r) * DMODEL + base + d];
    }
    __syncthreads();

    int warp = tid >> 5, lane = tid & 31;
    int r0 = warp * 4;
    const float NI = neg_inf();

    // scores with K-register reuse: each lane loads K[j][d] once, FMAs
    // against 4 broadcast Q rows. Per-accumulator d-order unchanged.
    bool act[4];
#pragma unroll
    for (int rr = 0; rr < 4; rr++) act[rr] = (g_mask[q0 + r0 + rr] == 1);

    float sv[4][4];  // [m][r]
#pragma unroll
    for (int m = 0; m < 4; m++) {
        int j = lane + (m << 5);
        int k = (j < nc) ? cand[j] : -1;
        float a0 = 0.f, a1 = 0.f, a2 = 0.f, a3 = 0.f;
        if (k >= 0) {
            const float* kp = &Ks[j * 129];
            const float* q0p = &Qs[(r0 + 0) * 128];
            const float* q1p = &Qs[(r0 + 1) * 128];
            const float* q2p = &Qs[(r0 + 2) * 128];
            const float* q3p = &Qs[(r0 + 3) * 128];
#pragma unroll 8
            for (int d = 0; d < 128; d++) {
                float kv = kp[d];
                a0 = fmaf(kv, q0p[d], a0);
                a1 = fmaf(kv, q1p[d], a1);
                a2 = fmaf(kv, q2p[d], a2);
                a3 = fmaf(kv, q3p[d], a3);
            }
        }
        int mk = (k >= 0) ? g_mask[k] : 0;
        float av[4] = {a0, a1, a2, a3};
#pragma unroll
        for (int rr = 0; rr < 4; rr++) {
            int q = q0 + r0 + rr;
            int dd = q - k;
            if (dd < 0) dd = -dd;
            bool ok = act[rr] && (k >= 0) && (mk != 0) && ((j >= 96) || (mk == 2) || (dd <= 32));
            sv[m][rr] = ok ? av[rr] * SCALE_F : NI;
        }
    }
#pragma unroll
    for (int rr = 0; rr < 4; rr++) {
        int r = r0 + rr;
        float mx = fmaxf(fmaxf(sv[0][rr], sv[1][rr]), fmaxf(sv[2][rr], sv[3][rr]));
#pragma unroll
        for (int o = 16; o; o >>= 1) mx = fmaxf(mx, __shfl_xor_sync(0xffffffffu, mx, o));
        float p[4];
        float sum = 0.f;
#pragma unroll
        for (int m = 0; m < 4; m++) {
            p[m] = (sv[m][rr] == NI) ? 0.f : expf(sv[m][rr] - mx);
            sum += p[m];
        }
#pragma unroll
        for (int o = 16; o; o >>= 1) sum += __shfl_xor_sync(0xffffffffu, sum, o);
        if (act[rr]) {
            float inv = 1.f / sum;
#pragma unroll
            for (int m = 0; m < 4; m++) {
                int j = lane + (m << 5);
                probs[r * 128 + j] = p[m] * inv;
            }
        }
    }
    __syncthreads();
    for (int e = tid; e < 32 * 128; e += 256) {
        int r = e >> 7, d = e & 127;
        int q = q0 + r;
        if (g_mask[q] != 1) continue;
        float acc = 0.f;
        const float* pr = &probs[r * 128];
#pragma unroll 4
        for (int j = 0; j < nc; j++) acc += pr[j] * Vs[j * 129 + d];
        store_hl1(ch, cl, (size_t)q * DMODEL + base + d, acc);
    }
}

// ============================ attention: global rows (slab-parallel) ========
#define SMEM_GA ((128 * 129 + 32 * 128) * 4)
__global__ __launch_bounds__(256) void ga_scores_kernel() {
    extern __shared__ float smf[];
    float* Ks = smf;
    float* Qs = Ks + 128 * 129;
    int slab = blockIdx.x, h = blockIdx.y, tid = threadIdx.x;
    int ng = g_nglob;
    for (int e = tid; e < 128 * 128; e += 256) {
        int j = e >> 7, d = e & 127;
        Ks[j * 129 + d] = g_k[(size_t)(slab * 128 + j) * DMODEL + h * DK + d];
    }
    for (int e = tid; e < 32 * 128; e += 256) {
        int r = e >> 7, d = e & 127;
        Qs[e] = (r < ng) ? g_q[(size_t)g_globlist[r] * DMODEL + h * DK + d] : 0.f;
    }
    __syncthreads();
    int kk = tid & 127, half = tid >> 7;
    int k = slab * 128 + kk;
    bool nonpad = (g_mask[k] != 0);
    for (int qi = half; qi < ng; qi += 2) {
        float sd = 0.f;
        const float* qp = &Qs[qi * 128];
        const float* kp = &Ks[kk * 129];
#pragma unroll 16
        for (int d = 0; d < 128; d++) sd += qp[d] * kp[d];
        g_gsc[((size_t)h * 32 + qi) * S + k] = nonpad ? sd * SCALE_F : neg_inf();
    }
}
__global__ __launch_bounds__(256) void ga_softmax_kernel() {
    int qi = blockIdx.x, h = blockIdx.y, tid = threadIdx.x;
    if (qi >= g_nglob) return;
    float* row = g_gsc + ((size_t)h * 32 + qi) * S;
    const float NI = neg_inf();
    float mx = NI;
    for (int k = tid; k < S; k += 256) mx = fmaxf(mx, row[k]);
    mx = blockMax256(mx);
    float sum = 0.f;
    for (int k = tid; k < S; k += 256) {
        float v = row[k];
        float p = (v == NI) ? 0.f : expf(v - mx);
        row[k] = p;
        sum += p;
    }
    sum = blockSum256(sum);
    float inv = 1.f / sum;
    for (int k = tid; k < S; k += 256) row[k] *= inv;
}
__global__ __launch_bounds__(256) void ga_av_kernel() {
    extern __shared__ float smf[];
    float* Vs = smf;
    float* Ps = Vs + 128 * 129;
    int slab = blockIdx.x, h = blockIdx.y, tid = threadIdx.x;
    int ng = g_nglob;
    for (int e = tid; e < 128 * 128; e += 256) {
        int j = e >> 7, d = e & 127;
        Vs[j * 129 + d] = g_v[(size_t)(slab * 128 + j) * DMODEL + h * DK + d];
    }
    for (int e = tid; e < 32 * 128; e += 256) {
        int r = e >> 7, kk = e & 127;
        Ps[e] = (r < ng) ? g_gsc[((size_t)h * 32 + r) * S + slab * 128 + kk] : 0.f;
    }
    __syncthreads();
    int d = tid & 127, half = tid >> 7;
    for (int qi = half; qi < ng; qi += 2) {
        float acc = 0.f;
        const float* pp = &Ps[qi * 128];
#pragma unroll 16
        for (int kk = 0; kk < 128; kk++) acc += pp[kk] * Vs[kk * 129 + d];
        g_gpart[(((size_t)slab * NH + h) * 32 + qi) * DK + d] = acc;
    }
}
__global__ __launch_bounds__(128) void ga_out_kernel(__nv_bfloat16* __restrict__ ch,
                                                     __nv_bfloat16* __restrict__ cl) {
    int qi = blockIdx.x, h = blockIdx.y, d = threadIdx.x;
    if (qi >= g_nglob) return;
    float s = 0.f;
#pragma unroll
    for (int slab = 0; slab < 16; slab++)
        s += g_gpart[(((size_t)slab * NH + h) * 32 + qi) * DK + d];
    int q = g_globlist[qi];
    store_hl1(ch, cl, (size_t)q * DMODEL + h * DK + d, s);
}

// ============================ driver ========================================
extern "C" void kernel_launch(void* const* d_in, const int* in_sizes, int n_in,
                              void* d_out, int out_size) {
    const int* Tp = (const int*)d_in[0];
    const float* enc = (const float*)d_in[1];
    const int* gidx = (const int*)d_in[2];
    const float* Wq = (const float*)d_in[3];
    const float* Wk = (const float*)d_in[4];
    const float* Wv = (const float*)d_in[5];
    const float* Wo = (const float*)d_in[6];
    const float* ln1g = (const float*)d_in[7];
    const float* ln1b = (const float*)d_in[8];
    const float* W1 = (const float*)d_in[9];
    const float* W2 = (const float*)d_in[10];
    const float* ln2g = (const float*)d_in[11];
    const float* ln2b = (const float*)d_in[12];
    float* out = (float*)d_out;

    cudaFuncSetAttribute(attn_local_kernel, cudaFuncAttributeMaxDynamicSharedMemorySize,
                         SMEM_LOCAL_BYTES);
    cudaFuncSetAttribute(ga_scores_kernel, cudaFuncAttributeMaxDynamicSharedMemorySize, SMEM_GA);
    cudaFuncSetAttribute(ga_av_kernel, cudaFuncAttributeMaxDynamicSharedMemorySize, SMEM_GA);
    cudaFuncSetAttribute(gemm_mma, cudaFuncAttributeMaxDynamicSharedMemorySize, GEMM_SMEM);

    float *px, *pq, *pk, *pv, *py;
    __nv_bfloat16 *pwh, *pwl, *pah, *pal, *phh, *phl;
    cudaGetSymbolAddress((void**)&px, g_x);
    cudaGetSymbolAddress((void**)&pq, g_q);
    cudaGetSymbolAddress((void**)&pk, g_k);
    cudaGetSymbolAddress((void**)&pv, g_v);
    cudaGetSymbolAddress((void**)&py, g_y);
    cudaGetSymbolAddress((void**)&pwh, g_wt_hi);
    cudaGetSymbolAddress((void**)&pwl, g_wt_lo);
    cudaGetSymbolAddress((void**)&pah, g_ah);
    cudaGetSymbolAddress((void**)&pal, g_al);
    cudaGetSymbolAddress((void**)&phh, g_hh);
    cudaGetSymbolAddress((void**)&phl, g_hl);

    const size_t M1 = 1024u * 1024u;

    // pediv(0), prep(1), tsplit_all(2), QKV gemm(3): profiler window -> gemm.
    pediv_kernel<<<2, 256>>>();
    prep_kernel<<<(S * DMODEL) / 256, 256>>>(enc);
    tsplit_all_kernel<<<dim3(64, 64, 24), dim3(32, 8)>>>(Wq, Wk, Wv, Wo, W1, W2, pwh, pwl);
    gemm_mma<<<dim3(DMODEL / 128, S / 128, 3), 256, GEMM_SMEM>>>(
        S, DMODEL, DMODEL, pah, pal, pwh, pwl, pq, pwh + M1, pwl + M1, pk, pwh + 2 * M1,
        pwl + 2 * M1, pv, 0, nullptr, nullptr);

    mask_zero_kernel<<<8, 256>>>();
    mask_scatter_kernel<<<1, 32>>>(gidx);
    mask_build_kernel<<<8, 256>>>(Tp);
    mask_list_kernel<<<1, 32>>>();

    for (int l = 0; l < NLAYERS; l++) {
        size_t wo_ = (size_t)l * LSTRIDE;
        if (l > 0) {
            gemm_mma<<<dim3(DMODEL / 128, S / 128, 3), 256, GEMM_SMEM>>>(
                S, DMODEL, DMODEL, pah, pal, pwh + wo_, pwl + wo_, pq, pwh + wo_ + M1,
                pwl + wo_ + M1, pk, pwh + wo_ + 2 * M1, pwl + wo_ + 2 * M1, pv, 0, nullptr,
                nullptr);
        }

        vmean_part_kernel<<<dim3(DMODEL / 256, 16), 256>>>();
        vmean_reduce_kernel<<<DMODEL / 256, 256>>>();
        attn_local_kernel<<<dim3(S / 32, NH), 256, SMEM_LOCAL_BYTES>>>(pah, pal);
        ga_scores_kernel<<<dim3(16, NH), 256, SMEM_GA>>>();
        ga_softmax_kernel<<<dim3(32, NH), 256>>>();
        ga_av_kernel<<<dim3(16, NH), 256, SMEM_GA>>>();
        ga_out_kernel<<<dim3(32, NH), 128>>>(pah, pal);
        attn_pad_kernel<<<dim3(DMODEL / 256, S), 256>>>(pah, pal);

        gemm_mma<<<dim3(DMODEL / 128, S / 128, 1), 256, GEMM_SMEM>>>(
            S, DMODEL, DMODEL, pah, pal, pwh + wo_ + 3 * M1, pwl + wo_ + 3 * M1, py, nullptr,
            nullptr, nullptr, nullptr, nullptr, nullptr, 0, nullptr, nullptr);
        ln_kernel<<<S, 256>>>(py, px, ln1g + l * DMODEL, ln1b + l * DMODEL, px, pah, pal);

        gemm_mma<<<dim3(DFF / 128, S / 128, 1), 256, GEMM_SMEM>>>(
            S, DFF, DMODEL, pah, pal, pwh + wo_ + 4 * M1, pwl + wo_ + 4 * M1, nullptr, nullptr,
            nullptr, nullptr, nullptr, nullptr, nullptr, 1, phh, phl);
        gemm_mma<<<dim3(DMODEL / 128, S / 128, 1), 256, GEMM_SMEM>>>(
            S, DMODEL, DFF, phh, phl, pwh + wo_ + 6 * M1, pwl + wo_ + 6 * M1, py, nullptr,
            nullptr, nullptr, nullptr, nullptr, nullptr, 0, nullptr, nullptr);
        ln_kernel<<<S, 256>>>(py, px, ln2g + l * DMODEL, ln2b + l * DMODEL,
                              (l == NLAYERS - 1) ? out : px, pah, pal);
    }
}

// round 11
// speedup vs baseline: 2.8629x; 1.0867x over previous
#include <cuda_runtime.h>
#include <cuda_bf16.h>
#include <math.h>
#include <stdint.h>

#define S 2048
#define DMODEL 1024
#define DFF 2048
#define NH 8
#define DK 128
#define NLAYERS 4

static __device__ __forceinline__ float neg_inf() { return __int_as_float(0xff800000); }
#define SCALE_F 0.08838834764831845f  // 1/sqrt(128)

// ======================= PTX helpers (base sm_80+ features only) ============
__device__ __forceinline__ uint32_t smem_u32(const void* p) {
    uint32_t a;
    asm("{ .reg .u64 t; cvta.to.shared.u64 t, %1; cvt.u32.u64 %0, t; }" : "=r"(a) : "l"(p));
    return a;
}
__device__ __forceinline__ void cp16(uint32_t dst, const void* src) {
    asm volatile("cp.async.cg.shared.global [%0], [%1], 16;" ::"r"(dst), "l"(src));
}
#define CP_COMMIT() asm volatile("cp.async.commit_group;" ::: "memory")
#define CP_WAIT1() asm volatile("cp.async.wait_group 1;" ::: "memory")
#define CP_WAIT0() asm volatile("cp.async.wait_group 0;" ::: "memory")

__device__ __forceinline__ void ldmx4(uint32_t* r, uint32_t addr) {
    asm volatile("ldmatrix.sync.aligned.m8n8.x4.shared.b16 {%0,%1,%2,%3}, [%4];"
                 : "=r"(r[0]), "=r"(r[1]), "=r"(r[2]), "=r"(r[3])
                 : "r"(addr));
}
__device__ __forceinline__ void mma16816(float* d, const uint32_t* a, const uint32_t* b) {
    asm volatile(
        "mma.sync.aligned.m16n8k16.row.col.f32.bf16.bf16.f32 "
        "{%0,%1,%2,%3}, {%4,%5,%6,%7}, {%8,%9}, {%0,%1,%2,%3};"
        : "+f"(d[0]), "+f"(d[1]), "+f"(d[2]), "+f"(d[3])
        : "r"(a[0]), "r"(a[1]), "r"(a[2]), "r"(a[3]), "r"(b[0]), "r"(b[1]));
}
__device__ __forceinline__ void store_hl2(__nv_bfloat16* Hh, __nv_bfloat16* Hl, size_t off,
                                          float x, float y) {
    __nv_bfloat16 hx = __float2bfloat16(x), hy = __float2bfloat16(y);
    __nv_bfloat162 h;
    h.x = hx;
    h.y = hy;
    __nv_bfloat162 l;
    l.x = __float2bfloat16(x - __bfloat162float(hx));
    l.y = __float2bfloat16(y - __bfloat162float(hy));
    *(__nv_bfloat162*)(Hh + off) = h;
    *(__nv_bfloat162*)(Hl + off) = l;
}
__device__ __forceinline__ void store_hl1(__nv_bfloat16* Hh, __nv_bfloat16* Hl, size_t off,
                                          float x) {
    __nv_bfloat16 hx = __float2bfloat16(x);
    Hh[off] = hx;
    Hl[off] = __float2bfloat16(x - __bfloat162float(hx));
}

// ============================ scratch globals ===============================
__device__ float g_x[S * DMODEL];
__device__ float g_q[S * DMODEL];
__device__ float g_k[S * DMODEL];
__device__ float g_v[S * DMODEL];
__device__ float g_y[2 * S * DMODEL];  // split-K partial outputs
__device__ float g_vmean[DMODEL];
__device__ float g_vpart[16][DMODEL];
__device__ int g_isglob[S];
__device__ int g_mask[S];  // 0 pad, 1 local, 2 global
__device__ int g_globlist[64];
__device__ int g_nglob;
__device__ float g_divhi[512];
__device__ float g_divlo[512];
__device__ float g_gsc[NH * 32 * S];
__device__ float g_gpart[16 * NH * 32 * DK];

#define LSTRIDE (8 * 1024 * 1024)
__device__ __nv_bfloat16 g_wt_hi[NLAYERS * LSTRIDE];
__device__ __nv_bfloat16 g_wt_lo[NLAYERS * LSTRIDE];
__device__ __nv_bfloat16 g_ah[S * DMODEL];
__device__ __nv_bfloat16 g_al[S * DMODEL];
__device__ __nv_bfloat16 g_hh[S * DFF];
__device__ __nv_bfloat16 g_hl[S * DFF];

// ============================ reductions ====================================
static __device__ __forceinline__ float warpAllSum(float v) {
#pragma unroll
    for (int o = 16; o; o >>= 1) v += __shfl_xor_sync(0xffffffffu, v, o);
    return v;
}
static __device__ __forceinline__ float warpAllMax(float v) {
#pragma unroll
    for (int o = 16; o; o >>= 1) v = fmaxf(v, __shfl_xor_sync(0xffffffffu, v, o));
    return v;
}
static __device__ __forceinline__ float blockSum256(float v) {
    __shared__ float sh[8];
    int lane = threadIdx.x & 31, w = threadIdx.x >> 5;
    v = warpAllSum(v);
    __syncthreads();
    if (lane == 0) sh[w] = v;
    __syncthreads();
    if (w == 0) {
        float t = (lane < 8) ? sh[lane] : 0.f;
        t = warpAllSum(t);
        if (lane == 0) sh[0] = t;
    }
    __syncthreads();
    return sh[0];
}
static __device__ __forceinline__ float blockMax256(float v) {
    __shared__ float sh[8];
    int lane = threadIdx.x & 31, w = threadIdx.x >> 5;
    v = warpAllMax(v);
    __syncthreads();
    if (lane == 0) sh[w] = v;
    __syncthreads();
    if (w == 0) {
        float t = (lane < 8) ? sh[lane] : neg_inf();
        t = warpAllMax(t);
        if (lane == 0) sh[0] = t;
    }
    __syncthreads();
    return sh[0];
}

// ============================ prep / mask ===================================
__global__ void pediv_kernel() {
    int i = blockIdx.x * 256 + threadIdx.x;
    if (i < 512) {
        double dv = exp(-(double)(2 * i) * (9.210340371976184 / 1024.0));
        float h = (float)dv;
        g_divhi[i] = h;
        g_divlo[i] = (float)(dv - (double)h);
    }
}
__global__ void prep_kernel(const float* __restrict__ enc) {
    int idx = blockIdx.x * 256 + threadIdx.x;
    int s = idx >> 10, d = idx & 1023;
    int i = d >> 1;
    float hi = g_divhi[i], lo = g_divlo[i];
    float sf = (float)s;
    float h = sf * hi;
    float e = fmaf(sf, hi, -h);
    float t = fmaf(sf, lo, e);
    const float P2HI = 6.28318548202514648f;
    const float P2LO = -1.74845553e-7f;
    float n = rintf(h * 0.15915494309189535f);
    float r = fmaf(-n, P2HI, h);
    r = fmaf(-n, P2LO, r);
    r += t;
    float pe = (d & 1) ? cosf(r) : sinf(r);
    float x = 2.0f * enc[idx] + pe;
    g_x[idx] = x;
    store_hl1(g_ah, g_al, idx, x);
}
__global__ void mask_zero_kernel() {
    int i = blockIdx.x * 256 + threadIdx.x;
    if (i < S) g_isglob[i] = 0;
}
__global__ void mask_scatter_kernel(const int* __restrict__ gidx) {
    int t = threadIdx.x;
    if (t < 32) {
        int g = gidx[t] / 15;
        if (g >= 0 && g < S) g_isglob[g] = 1;
    }
}
__global__ void mask_build_kernel(const int* __restrict__ Tp) {
    int i = blockIdx.x * 256 + threadIdx.x;
    if (i < S) {
        int T = *Tp;
        g_mask[i] = g_isglob[i] ? 2 : (i < T ? 1 : 0);
    }
}
__global__ void mask_list_kernel() {
    int lane = threadIdx.x;
    int cnt = 0;
    for (int base = 0; base < S; base += 32) {
        int m = (g_mask[base + lane] == 2);
        unsigned bal = __ballot_sync(0xffffffffu, m);
        if (m) g_globlist[cnt + __popc(bal & ((1u << lane) - 1u))] = base + lane;
        cnt += __popc(bal);
    }
    if (lane == 0) g_nglob = cnt;
}

// ============================ fused weight transpose/split ==================
__global__ void tsplit_all_kernel(const float* __restrict__ Wq, const float* __restrict__ Wk,
                                  const float* __restrict__ Wv, const float* __restrict__ Wo,
                                  const float* __restrict__ W1, const float* __restrict__ W2,
                                  __nv_bfloat16* __restrict__ hi, __nv_bfloat16* __restrict__ lo) {
    const size_t M1 = 1024u * 1024u;
    int z = blockIdx.z;
    int l = z / 6, m = z % 6;
    const float* W;
    int K, N;
    size_t doff = (size_t)l * LSTRIDE;
    if (m == 0) { W = Wq + l * M1; K = 1024; N = 1024; }
    else if (m == 1) { W = Wk + l * M1; K = 1024; N = 1024; doff += M1; }
    else if (m == 2) { W = Wv + l * M1; K = 1024; N = 1024; doff += 2 * M1; }
    else if (m == 3) { W = Wo + l * M1; K = 1024; N = 1024; doff += 3 * M1; }
    else if (m == 4) { W = W1 + l * 2 * M1; K = 1024; N = 2048; doff += 4 * M1; }
    else { W = W2 + l * 2 * M1; K = 2048; N = 1024; doff += 6 * M1; }
    int n0 = blockIdx.x * 32, k0 = blockIdx.y * 32;
    if (n0 >= N || k0 >= K) return;
    __shared__ float t[32][33];
    int tx = threadIdx.x, ty = threadIdx.y;
#pragma unroll
    for (int i = 0; i < 32; i += 8) t[ty + i][tx] = W[(size_t)(k0 + ty + i) * N + n0 + tx];
    __syncthreads();
#pragma unroll
    for (int i = 0; i < 32; i += 8) {
        float x = t[tx][ty + i];
        __nv_bfloat16 h = __float2bfloat16(x);
        size_t o = doff + (size_t)(n0 + ty + i) * K + k0 + tx;
        hi[o] = h;
        lo[o] = __float2bfloat16(x - __bfloat162float(h));
    }
}

// ============================ bf16x3 HMMA GEMM ==============================
// 128x128 tile, BK=32, 2-stage cp.async, 8 warps, 2 CTAs/SM (regs<=128).
// ksplit: blockIdx.z selects K-half; C = C0 + z*M*N.
#define TSTRIDE 80
#define TILE_B (128 * TSTRIDE)
#define STAGE_B (4 * TILE_B)
#define GEMM_SMEM (2 * STAGE_B)  // 81920

__global__ __launch_bounds__(256, 2) void gemm_mma(
    int M, int N, int K, const __nv_bfloat16* __restrict__ Ahi,
    const __nv_bfloat16* __restrict__ Alo, const __nv_bfloat16* B0h, const __nv_bfloat16* B0l,
    float* C0, const __nv_bfloat16* B1h, const __nv_bfloat16* B1l, float* C1,
    const __nv_bfloat16* B2h, const __nv_bfloat16* B2l, float* C2, int relu,
    __nv_bfloat16* Hh, __nv_bfloat16* Hl, int ksplit) {
    extern __shared__ char sm[];
    const __nv_bfloat16 *Bh, *Bl;
    float* C;
    int z = blockIdx.z;
    int kbeg = 0, Keff = K;
    if (ksplit) {
        Bh = B0h;
        Bl = B0l;
        Keff = K >> 1;
        kbeg = z * Keff;
        C = C0 + (size_t)z * M * N;
    } else if (z == 0) { Bh = B0h; Bl = B0l; C = C0; }
    else if (z == 1) { Bh = B1h; Bl = B1l; C = C1; }
    else { Bh = B2h; Bl = B2l; C = C2; }

    uint32_t smb = smem_u32(sm);
    int tid = threadIdx.x, wid = tid >> 5, lane = tid & 31;
    int row0 = blockIdx.y * 128, col0 = blockIdx.x * 128;
    int wm = wid >> 2, wn = wid & 3;

    float acc[4][4][4];
#pragma unroll
    for (int a = 0; a < 4; a++)
#pragma unroll
        for (int b = 0; b < 4; b++)
#pragma unroll
            for (int c = 0; c < 4; c++) acc[a][b][c] = 0.f;

    int cid0 = tid * 2, cid1 = tid * 2 + 1;
    int lr0 = cid0 >> 2, lc0 = (cid0 & 3) * 16;
    int lr1 = cid1 >> 2, lc1 = (cid1 & 3) * 16;

    const __nv_bfloat16* srcs[4] = {Ahi, Alo, Bh, Bl};
    int rbase[4] = {row0, row0, col0, col0};
    const int nch = Keff / 32;

    {
#pragma unroll
        for (int t = 0; t < 4; t++) {
            const __nv_bfloat16* src = srcs[t];
            uint32_t tb = smb + t * TILE_B;
            cp16(tb + lr0 * TSTRIDE + lc0, src + (size_t)(rbase[t] + lr0) * K + kbeg + (lc0 >> 1));
            cp16(tb + lr1 * TSTRIDE + lc1, src + (size_t)(rbase[t] + lr1) * K + kbeg + (lc1 >> 1));
        }
        CP_COMMIT();
    }

    for (int c = 0; c < nch; c++) {
        if (c + 1 < nch) {
            int k0 = kbeg + (c + 1) * 32;
            uint32_t sb = smb + ((c + 1) & 1) * STAGE_B;
#pragma unroll
            for (int t = 0; t < 4; t++) {
                const __nv_bfloat16* src = srcs[t];
                uint32_t tb = sb + t * TILE_B;
                cp16(tb + lr0 * TSTRIDE + lc0,
                     src + (size_t)(rbase[t] + lr0) * K + k0 + (lc0 >> 1));
                cp16(tb + lr1 * TSTRIDE + lc1,
                     src + (size_t)(rbase[t] + lr1) * K + k0 + (lc1 >> 1));
            }
            CP_COMMIT();
            CP_WAIT1();
        } else {
            CP_WAIT0();
        }
        __syncthreads();

        uint32_t base = smb + (c & 1) * STAGE_B;
        uint32_t aH = base, aL = base + TILE_B, bH = base + 2 * TILE_B, bL = base + 3 * TILE_B;
        int arow = wm * 64 + (lane & 15);
        int brow = wn * 32 + (lane & 7) + ((lane >> 4) << 3);
#pragma unroll
        for (int ks = 0; ks < 2; ks++) {
            int akb = ks * 32 + ((lane >> 4) << 4);
            int bkb = ks * 32 + (((lane >> 3) & 1) << 4);
            uint32_t ah[4][4], al[4][4], bh[4][2], bl[4][2];
#pragma unroll
            for (int mf = 0; mf < 4; mf++)
                ldmx4(ah[mf], aH + (uint32_t)(arow + mf * 16) * TSTRIDE + akb);
#pragma unroll
            for (int np = 0; np < 2; np++) {
                uint32_t r4[4];
                ldmx4(r4, bH + (uint32_t)(brow + np * 16) * TSTRIDE + bkb);
                bh[np * 2][0] = r4[0]; bh[np * 2][1] = r4[1];
                bh[np * 2 + 1][0] = r4[2]; bh[np * 2 + 1][1] = r4[3];
                ldmx4(r4, bL + (uint32_t)(brow + np * 16) * TSTRIDE + bkb);
                bl[np * 2][0] = r4[0]; bl[np * 2][1] = r4[1];
                bl[np * 2 + 1][0] = r4[2]; bl[np * 2 + 1][1] = r4[3];
            }
#pragma unroll
            for (int mf = 0; mf < 4; mf++)
                ldmx4(al[mf], aL + (uint32_t)(arow + mf * 16) * TSTRIDE + akb);
#pragma unroll
            for (int mf = 0; mf < 4; mf++)
#pragma unroll
                for (int nf = 0; nf < 4; nf++) mma16816(acc[mf][nf], ah[mf], bh[nf]);
#pragma unroll
            for (int mf = 0; mf < 4; mf++)
#pragma unroll
                for (int nf = 0; nf < 4; nf++) mma16816(acc[mf][nf], ah[mf], bl[nf]);
#pragma unroll
            for (int mf = 0; mf < 4; mf++)
#pragma unroll
                for (int nf = 0; nf < 4; nf++) mma16816(acc[mf][nf], al[mf], bh[nf]);
        }
        __syncthreads();
    }

    int gr = row0 + wm * 64 + (lane >> 2);
    int gc = col0 + wn * 32 + (lane & 3) * 2;
#pragma unroll
    for (int mf = 0; mf < 4; mf++) {
#pragma unroll
        for (int nf = 0; nf < 4; nf++) {
            float* a4 = acc[mf][nf];
            if (relu) {
                a4[0] = fmaxf(a4[0], 0.f);
                a4[1] = fmaxf(a4[1], 0.f);
                a4[2] = fmaxf(a4[2], 0.f);
                a4[3] = fmaxf(a4[3], 0.f);
            }
            size_t o0 = (size_t)(gr + mf * 16) * N + gc + nf * 8;
            size_t o1 = (size_t)(gr + mf * 16 + 8) * N + gc + nf * 8;
            if (Hh) {
                store_hl2(Hh, Hl, o0, a4[0], a4[1]);
                store_hl2(Hh, Hl, o1, a4[2], a4[3]);
            } else {
                float2 v0 = {a4[0], a4[1]};
                float2 v1 = {a4[2], a4[3]};
                *(float2*)(C + o0) = v0;
                *(float2*)(C + o1) = v1;
            }
        }
    }
}

// ============================ LayerNorm (sums two partial ys) ===============
__global__ __launch_bounds__(256) void ln_kernel(const float* __restrict__ y0,
                                                 const float* __restrict__ y1,
                                                 const float* __restrict__ xin,
                                                 const float* __restrict__ g,
                                                 const float* __restrict__ b,
                                                 float* __restrict__ out,
                                                 __nv_bfloat16* __restrict__ oh,
                                                 __nv_bfloat16* __restrict__ ol) {
    int s = blockIdx.x, tid = threadIdx.x;
    const float* y0r = y0 + (size_t)s * DMODEL;
    const float* y1r = y1 + (size_t)s * DMODEL;
    const float* xr = xin + (size_t)s * DMODEL;
    float v[4];
    float sum = 0.f;
#pragma unroll
    for (int i = 0; i < 4; i++) {
        int d = tid + (i << 8);
        v[i] = (y0r[d] + y1r[d]) + xr[d];
        sum += v[i];
    }
    float mean = blockSum256(sum) * (1.f / 1024.f);
    float sq = 0.f;
#pragma unroll
    for (int i = 0; i < 4; i++) {
        float t = v[i] - mean;
        sq += t * t;
    }
    float var = blockSum256(sq) * (1.f / 1024.f);
    float inv = 1.f / sqrtf(var + 1e-5f);
    float* orow = out + (size_t)s * DMODEL;
#pragma unroll
    for (int i = 0; i < 4; i++) {
        int d = tid + (i << 8);
        float o = g[d] * (v[i] - mean) * inv + b[d];
        orow[d] = o;
        store_hl1(oh, ol, (size_t)s * DMODEL + d, o);
    }
}

// ============================ attention: pad rows ===========================
__global__ void vmean_part_kernel() {
    int d = blockIdx.x * 256 + threadIdx.x;
    int slab = blockIdx.y;
    float acc = 0.f;
    for (int s = slab * 128; s < (slab + 1) * 128; s++) acc += g_v[(size_t)s * DMODEL + d];
    g_vpart[slab][d] = acc;
}
__global__ void vmean_reduce_kernel() {
    int d = blockIdx.x * 256 + threadIdx.x;
    float a = 0.f;
#pragma unroll
    for (int i = 0; i < 16; i++) a += g_vpart[i][d];
    g_vmean[d] = a * (1.f / (float)S);
}
__global__ void attn_pad_kernel(__nv_bfloat16* __restrict__ ch, __nv_bfloat16* __restrict__ cl) {
    int s = blockIdx.y;
    if (g_mask[s] != 0) return;
    int d = blockIdx.x * 256 + threadIdx.x;
    store_hl1(ch, cl, (size_t)s * DMODEL + d, g_vmean[d]);
}

// ============================ attention: local rows =========================
// Ks pitch 129 (scalar), Vs/probs pitch 132 (float4-aligned, conflict-free).
#define SMEM_LOCAL_BYTES ((128 * 129 + 128 * 132 + 32 * 128 + 32 * 132) * 4 + 128 * 4)
__global__ __launch_bounds__(256) void attn_local_kernel(__nv_bfloat16* __restrict__ ch,
                                                         __nv_bfloat16* __restrict__ cl) {
    extern __shared__ float smf[];
    float* Ks = smf;                    // 128 x 129
    float* Vs = Ks + 128 * 129;         // 128 x 132
    float* Qs = Vs + 128 * 132;         // 32 x 128
    float* probs = Qs + 32 * 128;       // 32 x 132
    int* cand = (int*)(probs + 32 * 132);
    __shared__ int s_nc;

    int tid = threadIdx.x;
    int h = blockIdx.y, q0 = blockIdx.x * 32, base = h * DK;

    if (tid < 96) {
        int k = q0 - 32 + tid;
        cand[tid] = (k >= 0 && k < S) ? k : -1;
    }
    if (tid == 0) {
        int cnt = 96, ng = g_nglob;
        for (int i = 0; i < ng; i++) {
            int g = g_globlist[i];
            if (g < q0 - 32 || g > q0 + 63) cand[cnt++] = g;
        }
        s_nc = cnt;
    }
    __syncthreads();
    int nc = s_nc;

    for (int e = tid; e < 128 * 128; e += 256) {
        int j = e >> 7, d = e & 127;
        int k = (j < nc) ? cand[j] : -1;
        float kv = 0.f, vv = 0.f;
        if (k >= 0) {
            kv = g_k[(size_t)k * DMODEL + base + d];
            vv = g_v[(size_t)k * DMODEL + base + d];
        }
        Ks[j * 129 + d] = kv;
        Vs[j * 132 + d] = vv;
    }
    for (int e = tid; e < 32 * 128; e += 256) {
        int r = e >> 7, d = e & 127;
        Qs[e] = g_q[(size_t)(q0 + r) * DMODEL + base + d];
    }
    __syncthreads();

    int warp = tid >> 5, lane = tid & 31;
    int r0 = warp * 4;
    const float NI = neg_inf();
    bool act[4];
#pragma unroll
    for (int rr = 0; rr < 4; rr++) act[rr] = (g_mask[q0 + r0 + rr] == 1);

    const float* q0p = &Qs[(r0 + 0) * 128];
    const float* q1p = &Qs[(r0 + 1) * 128];
    const float* q2p = &Qs[(r0 + 2) * 128];
    const float* q3p = &Qs[(r0 + 3) * 128];

    float sv[4][4];  // [m][rr]
#pragma unroll
    for (int mp = 0; mp < 2; mp++) {
        int ja = lane + mp * 64, jb = ja + 32;
        const float* kpa = &Ks[ja * 129];
        const float* kpb = &Ks[jb * 129];
        float a0 = 0.f, a1 = 0.f, a2 = 0.f, a3 = 0.f;
        float b0 = 0.f, b1 = 0.f, b2 = 0.f, b3 = 0.f;
#pragma unroll 8
        for (int d = 0; d < 128; d++) {
            float kva = kpa[d], kvb = kpb[d];
            float qv0 = q0p[d], qv1 = q1p[d], qv2 = q2p[d], qv3 = q3p[d];
            a0 = fmaf(kva, qv0, a0);
            a1 = fmaf(kva, qv1, a1);
            a2 = fmaf(kva, qv2, a2);
            a3 = fmaf(kva, qv3, a3);
            b0 = fmaf(kvb, qv0, b0);
            b1 = fmaf(kvb, qv1, b1);
            b2 = fmaf(kvb, qv2, b2);
            b3 = fmaf(kvb, qv3, b3);
        }
        int ka = (ja < nc) ? cand[ja] : -1;
        int kb = (jb < nc) ? cand[jb] : -1;
        int mka = (ka >= 0) ? g_mask[ka] : 0;
        int mkb = (kb >= 0) ? g_mask[kb] : 0;
        float av[4] = {a0, a1, a2, a3};
        float bv[4] = {b0, b1, b2, b3};
#pragma unroll
        for (int rr = 0; rr < 4; rr++) {
            int q = q0 + r0 + rr;
            int dda = q - ka;
            if (dda < 0) dda = -dda;
            int ddb = q - kb;
            if (ddb < 0) ddb = -ddb;
            bool oka =
                act[rr] && (ka >= 0) && (mka != 0) && ((ja >= 96) || (mka == 2) || (dda <= 32));
            bool okb =
                act[rr] && (kb >= 0) && (mkb != 0) && ((jb >= 96) || (mkb == 2) || (ddb <= 32));
            sv[mp * 2][rr] = oka ? av[rr] * SCALE_F : NI;
            sv[mp * 2 + 1][rr] = okb ? bv[rr] * SCALE_F : NI;
        }
    }
#pragma unroll
    for (int rr = 0; rr < 4; rr++) {
        int r = r0 + rr;
        float mx = fmaxf(fmaxf(sv[0][rr], sv[1][rr]), fmaxf(sv[2][rr], sv[3][rr]));
#pragma unroll
        for (int o = 16; o; o >>= 1) mx = fmaxf(mx, __shfl_xor_sync(0xffffffffu, mx, o));
        float p[4];
        float sum = 0.f;
#pragma unroll
        for (int m = 0; m < 4; m++) {
            p[m] = (sv[m][rr] == NI) ? 0.f : expf(sv[m][rr] - mx);
            sum += p[m];
        }
#pragma unroll
        for (int o = 16; o; o >>= 1) sum += __shfl_xor_sync(0xffffffffu, sum, o);
        if (act[rr]) {
            float inv = 1.f / sum;
#pragma unroll
            for (int m = 0; m < 4; m++) {
                int j = lane + (m << 5);
                probs[r * 132 + j] = p[m] * inv;
            }
        }
    }
    __syncthreads();
    // AV with float4 V: thread -> (r, 4d block); 4 blocks per thread.
    {
        int r = tid >> 3, c0 = tid & 7;
        int q = q0 + r;
        if (g_mask[q] == 1) {
            const float* pr = &probs[r * 132];
            const float4* V4 = (const float4*)Vs;
#pragma unroll
            for (int u = 0; u < 4; u++) {
                int d4 = c0 + (u << 3);
                float x0 = 0.f, x1 = 0.f, x2 = 0.f, x3 = 0.f;
                for (int j = 0; j < nc; j++) {
                    float p = pr[j];
                    float4 v = V4[j * 33 + d4];
                    x0 = fmaf(p, v.x, x0);
                    x1 = fmaf(p, v.y, x1);
                    x2 = fmaf(p, v.z, x2);
                    x3 = fmaf(p, v.w, x3);
                }
                size_t off = (size_t)q * DMODEL + base + d4 * 4;
                store_hl2(ch, cl, off, x0, x1);
                store_hl2(ch, cl, off + 2, x2, x3);
            }
        }
    }
}

// ============================ attention: global rows (slab-parallel) ========
#define SMEM_GSC ((128 * 129 + 32 * 128) * 4)
__global__ __launch_bounds__(256) void ga_scores_kernel() {
    extern __shared__ float smf[];
    float* Ks = smf;
    float* Qs = Ks + 128 * 129;
    int slab = blockIdx.x, h = blockIdx.y, tid = threadIdx.x;
    int ng = g_nglob;
    for (int e = tid; e < 128 * 128; e += 256) {
        int j = e >> 7, d = e & 127;
        Ks[j * 129 + d] = g_k[(size_t)(slab * 128 + j) * DMODEL + h * DK + d];
    }
    for (int e = tid; e < 32 * 128; e += 256) {
        int r = e >> 7, d = e & 127;
        Qs[e] = (r < ng) ? g_q[(size_t)g_globlist[r] * DMODEL + h * DK + d] : 0.f;
    }
    __syncthreads();
    int kk = tid & 127, half = tid >> 7;
    int k = slab * 128 + kk;
    bool nonpad = (g_mask[k] != 0);
    for (int qi = half; qi < ng; qi += 2) {
        float sd = 0.f;
        const float* qp = &Qs[qi * 128];
        const float* kp = &Ks[kk * 129];
#pragma unroll 16
        for (int d = 0; d < 128; d++) sd += qp[d] * kp[d];
        g_gsc[((size_t)h * 32 + qi) * S + k] = nonpad ? sd * SCALE_F : neg_inf();
    }
}
__global__ __launch_bounds__(256) void ga_softmax_kernel() {
    int qi = blockIdx.x, h = blockIdx.y, tid = threadIdx.x;
    if (qi >= g_nglob) return;
    float* row = g_gsc + ((size_t)h * 32 + qi) * S;
    const float NI = neg_inf();
    float mx = NI;
    for (int k = tid; k < S; k += 256) mx = fmaxf(mx, row[k]);
    mx = blockMax256(mx);
    float sum = 0.f;
    for (int k = tid; k < S; k += 256) {
        float v = row[k];
        float p = (v == NI) ? 0.f : expf(v - mx);
        row[k] = p;
        sum += p;
    }
    sum = blockSum256(sum);
    float inv = 1.f / sum;
    for (int k = tid; k < S; k += 256) row[k] *= inv;
}
// Vs/Ps pitch 132 for float4.
#define SMEM_GAV ((128 * 132 + 32 * 132) * 4)
__global__ __launch_bounds__(256) void ga_av_kernel() {
    extern __shared__ float smf[];
    float* Vs = smf;                // 128 x 132
    float* Ps = Vs + 128 * 132;     // 32 x 132
    int slab = blockIdx.x, h = blockIdx.y, tid = threadIdx.x;
    int ng = g_nglob;
    for (int e = tid; e < 128 * 128; e += 256) {
        int j = e >> 7, d = e & 127;
        Vs[j * 132 + d] = g_v[(size_t)(slab * 128 + j) * DMODEL + h * DK + d];
    }
    for (int e = tid; e < 32 * 128; e += 256) {
        int r = e >> 7, kk = e & 127;
        Ps[r * 132 + kk] = (r < ng) ? g_gsc[((size_t)h * 32 + r) * S + slab * 128 + kk] : 0.f;
    }
    __syncthreads();
    int qi = tid >> 3, c0 = tid & 7;
    if (qi < ng) {
        const float* pp = &Ps[qi * 132];
        const float4* V4 = (const float4*)Vs;
#pragma unroll
        for (int u = 0; u < 4; u++) {
            int d4 = c0 + (u << 3);
            float x0 = 0.f, x1 = 0.f, x2 = 0.f, x3 = 0.f;
#pragma unroll 4
            for (int kk = 0; kk < 128; kk++) {
                float p = pp[kk];
                float4 v = V4[kk * 33 + d4];
                x0 = fmaf(p, v.x, x0);
                x1 = fmaf(p, v.y, x1);
                x2 = fmaf(p, v.z, x2);
                x3 = fmaf(p, v.w, x3);
            }
            float4 o = {x0, x1, x2, x3};
            *(float4*)&g_gpart[(((size_t)slab * NH + h) * 32 + qi) * DK + d4 * 4] = o;
        }
    }
}
__global__ __launch_bounds__(128) void ga_out_kernel(__nv_bfloat16* __restrict__ ch,
                                                     __nv_bfloat16* __restrict__ cl) {
    int qi = blockIdx.x, h = blockIdx.y, d = threadIdx.x;
    if (qi >= g_nglob) return;
    float s = 0.f;
#pragma unroll
    for (int slab = 0; slab < 16; slab++)
        s += g_gpart[(((size_t)slab * NH + h) * 32 + qi) * DK + d];
    int q = g_globlist[qi];
    store_hl1(ch, cl, (size_t)q * DMODEL + h * DK + d, s);
}

// ============================ driver ========================================
extern "C" void kernel_launch(void* const* d_in, const int* in_sizes, int n_in,
                              void* d_out, int out_size) {
    const int* Tp = (const int*)d_in[0];
    const float* enc = (const float*)d_in[1];
    const int* gidx = (const int*)d_in[2];
    const float* Wq = (const float*)d_in[3];
    const float* Wk = (const float*)d_in[4];
    const float* Wv = (const float*)d_in[5];
    const float* Wo = (const float*)d_in[6];
    const float* ln1g = (const float*)d_in[7];
    const float* ln1b = (const float*)d_in[8];
    const float* W1 = (const float*)d_in[9];
    const float* W2 = (const float*)d_in[10];
    const float* ln2g = (const float*)d_in[11];
    const float* ln2b = (const float*)d_in[12];
    float* out = (float*)d_out;

    cudaFuncSetAttribute(attn_local_kernel, cudaFuncAttributeMaxDynamicSharedMemorySize,
                         SMEM_LOCAL_BYTES);
    cudaFuncSetAttribute(ga_scores_kernel, cudaFuncAttributeMaxDynamicSharedMemorySize, SMEM_GSC);
    cudaFuncSetAttribute(ga_av_kernel, cudaFuncAttributeMaxDynamicSharedMemorySize, SMEM_GAV);
    cudaFuncSetAttribute(gemm_mma, cudaFuncAttributeMaxDynamicSharedMemorySize, GEMM_SMEM);

    float *px, *pq, *pk, *pv, *py;
    __nv_bfloat16 *pwh, *pwl, *pah, *pal, *phh, *phl;
    cudaGetSymbolAddress((void**)&px, g_x);
    cudaGetSymbolAddress((void**)&pq, g_q);
    cudaGetSymbolAddress((void**)&pk, g_k);
    cudaGetSymbolAddress((void**)&pv, g_v);
    cudaGetSymbolAddress((void**)&py, g_y);
    cudaGetSymbolAddress((void**)&pwh, g_wt_hi);
    cudaGetSymbolAddress((void**)&pwl, g_wt_lo);
    cudaGetSymbolAddress((void**)&pah, g_ah);
    cudaGetSymbolAddress((void**)&pal, g_al);
    cudaGetSymbolAddress((void**)&phh, g_hh);
    cudaGetSymbolAddress((void**)&phl, g_hl);
    float* py1 = py + (size_t)S * DMODEL;

    const size_t M1 = 1024u * 1024u;

    // pediv(0), prep(1), tsplit_all(2), QKV gemm(3): profiler window -> gemm.
    pediv_kernel<<<2, 256>>>();
    prep_kernel<<<(S * DMODEL) / 256, 256>>>(enc);
    tsplit_all_kernel<<<dim3(64, 64, 24), dim3(32, 8)>>>(Wq, Wk, Wv, Wo, W1, W2, pwh, pwl);
    gemm_mma<<<dim3(DMODEL / 128, S / 128, 3), 256, GEMM_SMEM>>>(
        S, DMODEL, DMODEL, pah, pal, pwh, pwl, pq, pwh + M1, pwl + M1, pk, pwh + 2 * M1,
        pwl + 2 * M1, pv, 0, nullptr, nullptr, 0);

    mask_zero_kernel<<<8, 256>>>();
    mask_scatter_kernel<<<1, 32>>>(gidx);
    mask_build_kernel<<<8, 256>>>(Tp);
    mask_list_kernel<<<1, 32>>>();

    for (int l = 0; l < NLAYERS; l++) {
        size_t wo_ = (size_t)l * LSTRIDE;
        if (l > 0) {
            gemm_mma<<<dim3(DMODEL / 128, S / 128, 3), 256, GEMM_SMEM>>>(
                S, DMODEL, DMODEL, pah, pal, pwh + wo_, pwl + wo_, pq, pwh + wo_ + M1,
                pwl + wo_ + M1, pk, pwh + wo_ + 2 * M1, pwl + wo_ + 2 * M1, pv, 0, nullptr,
                nullptr, 0);
        }

        vmean_part_kernel<<<dim3(DMODEL / 256, 16), 256>>>();
        vmean_reduce_kernel<<<DMODEL / 256, 256>>>();
        attn_local_kernel<<<dim3(S / 32, NH), 256, SMEM_LOCAL_BYTES>>>(pah, pal);
        ga_scores_kernel<<<dim3(16, NH), 256, SMEM_GSC>>>();
        ga_softmax_kernel<<<dim3(32, NH), 256>>>();
        ga_av_kernel<<<dim3(16, NH), 256, SMEM_GAV>>>();
        ga_out_kernel<<<dim3(32, NH), 128>>>(pah, pal);
        attn_pad_kernel<<<dim3(DMODEL / 256, S), 256>>>(pah, pal);

        // output projection (split-K x2) + residual LN
        gemm_mma<<<dim3(DMODEL / 128, S / 128, 2), 256, GEMM_SMEM>>>(
            S, DMODEL, DMODEL, pah, pal, pwh + wo_ + 3 * M1, pwl + wo_ + 3 * M1, py, nullptr,
            nullptr, nullptr, nullptr, nullptr, nullptr, 0, nullptr, nullptr, 1);
        ln_kernel<<<S, 256>>>(py, py1, px, ln1g + l * DMODEL, ln1b + l * DMODEL, px, pah, pal);

        // FFN1 (hi/lo bf16 out), FFN2 (split-K x2) + residual LN
        gemm_mma<<<dim3(DFF / 128, S / 128, 1), 256, GEMM_SMEM>>>(
            S, DFF, DMODEL, pah, pal, pwh + wo_ + 4 * M1, pwl + wo_ + 4 * M1, nullptr, nullptr,
            nullptr, nullptr, nullptr, nullptr, nullptr, 1, phh, phl, 0);
        gemm_mma<<<dim3(DMODEL / 128, S / 128, 2), 256, GEMM_SMEM>>>(
            S, DMODEL, DFF, phh, phl, pwh + wo_ + 6 * M1, pwl + wo_ + 6 * M1, py, nullptr,
            nullptr, nullptr, nullptr, nullptr, nullptr, 0, nullptr, nullptr, 1);
        ln_kernel<<<S, 256>>>(py, py1, px, ln2g + l * DMODEL, ln2b + l * DMODEL,
                              (l == NLAYERS - 1) ? out : px, pah, pal);
    }
}

// round 13
// speedup vs baseline: 3.4749x; 1.2138x over previous
#include <cuda_runtime.h>
#include <cuda_fp16.h>
#include <math.h>
#include <stdint.h>

#define S 2048
#define DMODEL 1024
#define DFF 2048
#define NH 8
#define DK 128
#define NLAYERS 4

static __device__ __forceinline__ float neg_inf() { return __int_as_float(0xff800000); }
#define SCALE_F 0.08838834764831845f  // 1/sqrt(128)

// ======================= PTX helpers (base sm_80+ features only) ============
__device__ __forceinline__ uint32_t smem_u32(const void* p) {
    uint32_t a;
    asm("{ .reg .u64 t; cvta.to.shared.u64 t, %1; cvt.u32.u64 %0, t; }" : "=r"(a) : "l"(p));
    return a;
}
__device__ __forceinline__ void cp16(uint32_t dst, const void* src) {
    asm volatile("cp.async.cg.shared.global [%0], [%1], 16;" ::"r"(dst), "l"(src));
}
#define CP_COMMIT() asm volatile("cp.async.commit_group;" ::: "memory")
#define CP_WAIT2() asm volatile("cp.async.wait_group 2;" ::: "memory")
#define CP_WAIT1() asm volatile("cp.async.wait_group 1;" ::: "memory")
#define CP_WAIT0() asm volatile("cp.async.wait_group 0;" ::: "memory")

__device__ __forceinline__ void ldmx4(uint32_t* r, uint32_t addr) {
    asm volatile("ldmatrix.sync.aligned.m8n8.x4.shared.b16 {%0,%1,%2,%3}, [%4];"
                 : "=r"(r[0]), "=r"(r[1]), "=r"(r[2]), "=r"(r[3])
                 : "r"(addr));
}
__device__ __forceinline__ void mma16816(float* d, const uint32_t* a, const uint32_t* b) {
    asm volatile(
        "mma.sync.aligned.m16n8k16.row.col.f32.f16.f16.f32 "
        "{%0,%1,%2,%3}, {%4,%5,%6,%7}, {%8,%9}, {%0,%1,%2,%3};"
        : "+f"(d[0]), "+f"(d[1]), "+f"(d[2]), "+f"(d[3])
        : "r"(a[0]), "r"(a[1]), "r"(a[2]), "r"(a[3]), "r"(b[0]), "r"(b[1]));
}
__device__ __forceinline__ void store_hl2(__half* Hh, __half* Hl, size_t off, float x, float y) {
    __half hx = __float2half_rn(x), hy = __float2half_rn(y);
    __half2 h;
    h.x = hx;
    h.y = hy;
    __half2 l;
    l.x = __float2half_rn(x - __half2float(hx));
    l.y = __float2half_rn(y - __half2float(hy));
    *(__half2*)(Hh + off) = h;
    *(__half2*)(Hl + off) = l;
}
__device__ __forceinline__ void store_hl1(__half* Hh, __half* Hl, size_t off, float x) {
    __half hx = __float2half_rn(x);
    Hh[off] = hx;
    Hl[off] = __float2half_rn(x - __half2float(hx));
}

// ============================ scratch globals ===============================
__device__ float g_x[S * DMODEL];
__device__ float g_q[S * DMODEL];
__device__ float g_k[S * DMODEL];
__device__ float g_v[S * DMODEL];
__device__ float g_y[2 * S * DMODEL];  // split-K partial outputs
__device__ float g_vmean[DMODEL];
__device__ float g_vpart[16][DMODEL];
__device__ int g_isglob[S];
__device__ int g_mask[S];  // 0 pad, 1 local, 2 global
__device__ int g_globlist[64];
__device__ int g_nglob;
__device__ float g_divhi[512];
__device__ float g_divlo[512];
__device__ float g_gsc[NH * 32 * S];
__device__ float g_gpart[16 * NH * 32 * DK];

#define LSTRIDE (8 * 1024 * 1024)
__device__ __half g_wt[NLAYERS * LSTRIDE];  // weights: single rn-fp16, transposed
__device__ __half g_ah[S * DMODEL];         // activations hi
__device__ __half g_al[S * DMODEL];         // activations lo
__device__ __half g_hh[S * DFF];            // ffn hidden hi
__device__ __half g_hl[S * DFF];            // ffn hidden lo

// ============================ reductions ====================================
static __device__ __forceinline__ float warpAllSum(float v) {
#pragma unroll
    for (int o = 16; o; o >>= 1) v += __shfl_xor_sync(0xffffffffu, v, o);
    return v;
}
static __device__ __forceinline__ float warpAllMax(float v) {
#pragma unroll
    for (int o = 16; o; o >>= 1) v = fmaxf(v, __shfl_xor_sync(0xffffffffu, v, o));
    return v;
}
static __device__ __forceinline__ float blockSum256(float v) {
    __shared__ float sh[8];
    int lane = threadIdx.x & 31, w = threadIdx.x >> 5;
    v = warpAllSum(v);
    __syncthreads();
    if (lane == 0) sh[w] = v;
    __syncthreads();
    if (w == 0) {
        float t = (lane < 8) ? sh[lane] : 0.f;
        t = warpAllSum(t);
        if (lane == 0) sh[0] = t;
    }
    __syncthreads();
    return sh[0];
}
static __device__ __forceinline__ float blockMax256(float v) {
    __shared__ float sh[8];
    int lane = threadIdx.x & 31, w = threadIdx.x >> 5;
    v = warpAllMax(v);
    __syncthreads();
    if (lane == 0) sh[w] = v;
    __syncthreads();
    if (w == 0) {
        float t = (lane < 8) ? sh[lane] : neg_inf();
        t = warpAllMax(t);
        if (lane == 0) sh[0] = t;
    }
    __syncthreads();
    return sh[0];
}

// ============================ prep / mask ===================================
__global__ void pediv_kernel() {
    int i = blockIdx.x * 256 + threadIdx.x;
    if (i < 512) {
        double dv = exp(-(double)(2 * i) * (9.210340371976184 / 1024.0));
        float h = (float)dv;
        g_divhi[i] = h;
        g_divlo[i] = (float)(dv - (double)h);
    }
}
__global__ void prep_kernel(const float* __restrict__ enc) {
    int idx = blockIdx.x * 256 + threadIdx.x;
    int s = idx >> 10, d = idx & 1023;
    int i = d >> 1;
    float hi = g_divhi[i], lo = g_divlo[i];
    float sf = (float)s;
    float h = sf * hi;
    float e = fmaf(sf, hi, -h);
    float t = fmaf(sf, lo, e);
    const float P2HI = 6.28318548202514648f;
    const float P2LO = -1.74845553e-7f;
    float n = rintf(h * 0.15915494309189535f);
    float r = fmaf(-n, P2HI, h);
    r = fmaf(-n, P2LO, r);
    r += t;
    float pe = (d & 1) ? cosf(r) : sinf(r);
    float x = 2.0f * enc[idx] + pe;
    g_x[idx] = x;
    store_hl1(g_ah, g_al, idx, x);
}
__global__ void mask_zero_kernel() {
    int i = blockIdx.x * 256 + threadIdx.x;
    if (i < S) g_isglob[i] = 0;
}
__global__ void mask_scatter_kernel(const int* __restrict__ gidx) {
    int t = threadIdx.x;
    if (t < 32) {
        int g = gidx[t] / 15;
        if (g >= 0 && g < S) g_isglob[g] = 1;
    }
}
__global__ void mask_build_kernel(const int* __restrict__ Tp) {
    int i = blockIdx.x * 256 + threadIdx.x;
    if (i < S) {
        int T = *Tp;
        g_mask[i] = g_isglob[i] ? 2 : (i < T ? 1 : 0);
    }
}
__global__ void mask_list_kernel() {
    int lane = threadIdx.x;
    int cnt = 0;
    for (int base = 0; base < S; base += 32) {
        int m = (g_mask[base + lane] == 2);
        unsigned bal = __ballot_sync(0xffffffffu, m);
        if (m) g_globlist[cnt + __popc(bal & ((1u << lane) - 1u))] = base + lane;
        cnt += __popc(bal);
    }
    if (lane == 0) g_nglob = cnt;
}

// ============================ fused weight transpose (rn fp16) ==============
__global__ void tsplit_all_kernel(const float* __restrict__ Wq, const float* __restrict__ Wk,
                                  const float* __restrict__ Wv, const float* __restrict__ Wo,
                                  const float* __restrict__ W1, const float* __restrict__ W2,
                                  __half* __restrict__ dst) {
    const size_t M1 = 1024u * 1024u;
    int z = blockIdx.z;
    int l = z / 6, m = z % 6;
    const float* W;
    int K, N;
    size_t doff = (size_t)l * LSTRIDE;
    if (m == 0) { W = Wq + l * M1; K = 1024; N = 1024; }
    else if (m == 1) { W = Wk + l * M1; K = 1024; N = 1024; doff += M1; }
    else if (m == 2) { W = Wv + l * M1; K = 1024; N = 1024; doff += 2 * M1; }
    else if (m == 3) { W = Wo + l * M1; K = 1024; N = 1024; doff += 3 * M1; }
    else if (m == 4) { W = W1 + l * 2 * M1; K = 1024; N = 2048; doff += 4 * M1; }
    else { W = W2 + l * 2 * M1; K = 2048; N = 1024; doff += 6 * M1; }
    int n0 = blockIdx.x * 32, k0 = blockIdx.y * 32;
    if (n0 >= N || k0 >= K) return;
    __shared__ float t[32][33];
    int tx = threadIdx.x, ty = threadIdx.y;
#pragma unroll
    for (int i = 0; i < 32; i += 8) t[ty + i][tx] = W[(size_t)(k0 + ty + i) * N + n0 + tx];
    __syncthreads();
#pragma unroll
    for (int i = 0; i < 32; i += 8) {
        dst[doff + (size_t)(n0 + ty + i) * K + k0 + tx] = __float2half_rn(t[tx][ty + i]);
    }
}

// ============================ fp16x2 HMMA GEMM ==============================
// C = A@W; A hi/lo fp16 (MxK row-major), B = W^T single fp16 (NxK).
// 128x128 tile, BK=32, 3-stage cp.async, 8 warps (64x32), 2 CTAs/SM.
#define TSTRIDE 80
#define TILE_B (128 * TSTRIDE)
#define STAGE_B (3 * TILE_B)      // Ah, Al, B
#define GEMM_SMEM (3 * STAGE_B)   // 92160; x2 CTA = 184320 <= 227KB

__global__ __launch_bounds__(256, 2) void gemm_mma(
    int M, int N, int K, const __half* __restrict__ Ahi, const __half* __restrict__ Alo,
    const __half* B0, float* C0, const __half* B1, float* C1, const __half* B2, float* C2,
    int relu, __half* Hh, __half* Hl, int ksplit) {
    extern __shared__ char sm[];
    const __half* B;
    float* C;
    int z = blockIdx.z;
    int kbeg = 0, Keff = K;
    if (ksplit) {
        B = B0;
        Keff = K >> 1;
        kbeg = z * Keff;
        C = C0 + (size_t)z * M * N;
    } else if (z == 0) { B = B0; C = C0; }
    else if (z == 1) { B = B1; C = C1; }
    else { B = B2; C = C2; }

    uint32_t smb = smem_u32(sm);
    int tid = threadIdx.x, wid = tid >> 5, lane = tid & 31;
    int row0 = blockIdx.y * 128, col0 = blockIdx.x * 128;
    int wm = wid >> 2, wn = wid & 3;

    float acc[4][4][4];
#pragma unroll
    for (int a = 0; a < 4; a++)
#pragma unroll
        for (int b = 0; b < 4; b++)
#pragma unroll
            for (int c = 0; c < 4; c++) acc[a][b][c] = 0.f;

    int cid0 = tid * 2, cid1 = tid * 2 + 1;
    int lr0 = cid0 >> 2, lc0 = (cid0 & 3) * 16;
    int lr1 = cid1 >> 2, lc1 = (cid1 & 3) * 16;

    const __half* srcs[3] = {Ahi, Alo, B};
    int rbase[3] = {row0, row0, col0};
    const int nch = Keff / 32;

    // prologue: chunks 0,1 -> stages 0,1
#pragma unroll
    for (int pc = 0; pc < 2; pc++) {
        uint32_t sb = smb + pc * STAGE_B;
        int k0 = kbeg + pc * 32;
#pragma unroll
        for (int t = 0; t < 3; t++) {
            const __half* src = srcs[t];
            uint32_t tb = sb + t * TILE_B;
            cp16(tb + lr0 * TSTRIDE + lc0, src + (size_t)(rbase[t] + lr0) * K + k0 + (lc0 >> 1));
            cp16(tb + lr1 * TSTRIDE + lc1, src + (size_t)(rbase[t] + lr1) * K + k0 + (lc1 >> 1));
        }
        CP_COMMIT();
    }

    for (int c = 0; c < nch; c++) {
        if (c + 2 < nch) {
            int k0 = kbeg + (c + 2) * 32;
            uint32_t sb = smb + ((c + 2) % 3) * STAGE_B;
#pragma unroll
            for (int t = 0; t < 3; t++) {
                const __half* src = srcs[t];
                uint32_t tb = sb + t * TILE_B;
                cp16(tb + lr0 * TSTRIDE + lc0,
                     src + (size_t)(rbase[t] + lr0) * K + k0 + (lc0 >> 1));
                cp16(tb + lr1 * TSTRIDE + lc1,
                     src + (size_t)(rbase[t] + lr1) * K + k0 + (lc1 >> 1));
            }
            CP_COMMIT();
            CP_WAIT2();
        } else if (c + 1 < nch) {
            CP_WAIT1();
        } else {
            CP_WAIT0();
        }
        __syncthreads();

        uint32_t base = smb + (c % 3) * STAGE_B;
        uint32_t aH = base, aL = base + TILE_B, bB = base + 2 * TILE_B;
        int arow = wm * 64 + (lane & 15);
        int brow = wn * 32 + (lane & 7) + ((lane >> 4) << 3);
#pragma unroll
        for (int ks = 0; ks < 2; ks++) {
            int akb = ks * 32 + ((lane >> 4) << 4);
            int bkb = ks * 32 + (((lane >> 3) & 1) << 4);
            uint32_t ah[4][4], al[4][4], bh[4][2];
#pragma unroll
            for (int mf = 0; mf < 4; mf++)
                ldmx4(ah[mf], aH + (uint32_t)(arow + mf * 16) * TSTRIDE + akb);
#pragma unroll
            for (int np = 0; np < 2; np++) {
                uint32_t r4[4];
                ldmx4(r4, bB + (uint32_t)(brow + np * 16) * TSTRIDE + bkb);
                bh[np * 2][0] = r4[0]; bh[np * 2][1] = r4[1];
                bh[np * 2 + 1][0] = r4[2]; bh[np * 2 + 1][1] = r4[3];
            }
#pragma unroll
            for (int mf = 0; mf < 4; mf++)
                ldmx4(al[mf], aL + (uint32_t)(arow + mf * 16) * TSTRIDE + akb);
#pragma unroll
            for (int mf = 0; mf < 4; mf++)
#pragma unroll
                for (int nf = 0; nf < 4; nf++) mma16816(acc[mf][nf], ah[mf], bh[nf]);
#pragma unroll
            for (int mf = 0; mf < 4; mf++)
#pragma unroll
                for (int nf = 0; nf < 4; nf++) mma16816(acc[mf][nf], al[mf], bh[nf]);
        }
        __syncthreads();
    }

    int gr = row0 + wm * 64 + (lane >> 2);
    int gc = col0 + wn * 32 + (lane & 3) * 2;
#pragma unroll
    for (int mf = 0; mf < 4; mf++) {
#pragma unroll
        for (int nf = 0; nf < 4; nf++) {
            float* a4 = acc[mf][nf];
            if (relu) {
                a4[0] = fmaxf(a4[0], 0.f);
                a4[1] = fmaxf(a4[1], 0.f);
                a4[2] = fmaxf(a4[2], 0.f);
                a4[3] = fmaxf(a4[3], 0.f);
            }
            size_t o0 = (size_t)(gr + mf * 16) * N + gc + nf * 8;
            size_t o1 = (size_t)(gr + mf * 16 + 8) * N + gc + nf * 8;
            if (Hh) {
                store_hl2(Hh, Hl, o0, a4[0], a4[1]);
                store_hl2(Hh, Hl, o1, a4[2], a4[3]);
            } else {
                float2 v0 = {a4[0], a4[1]};
                float2 v1 = {a4[2], a4[3]};
                *(float2*)(C + o0) = v0;
                *(float2*)(C + o1) = v1;
            }
        }
    }
}

// ============================ LayerNorm (sums two partial ys) ===============
__global__ __launch_bounds__(256) void ln_kernel(const float* __restrict__ y0,
                                                 const float* __restrict__ y1,
                                                 const float* __restrict__ xin,
                                                 const float* __restrict__ g,
                                                 const float* __restrict__ b,
                                                 float* __restrict__ out,
                                                 __half* __restrict__ oh,
                                                 __half* __restrict__ ol) {
    int s = blockIdx.x, tid = threadIdx.x;
    const float* y0r = y0 + (size_t)s * DMODEL;
    const float* y1r = y1 + (size_t)s * DMODEL;
    const float* xr = xin + (size_t)s * DMODEL;
    float v[4];
    float sum = 0.f;
#pragma unroll
    for (int i = 0; i < 4; i++) {
        int d = tid + (i << 8);
        v[i] = (y0r[d] + y1r[d]) + xr[d];
        sum += v[i];
    }
    float mean = blockSum256(sum) * (1.f / 1024.f);
    float sq = 0.f;
#pragma unroll
    for (int i = 0; i < 4; i++) {
        float t = v[i] - mean;
        sq += t * t;
    }
    float var = blockSum256(sq) * (1.f / 1024.f);
    float inv = 1.f / sqrtf(var + 1e-5f);
    float* orow = out + (size_t)s * DMODEL;
#pragma unroll
    for (int i = 0; i < 4; i++) {
        int d = tid + (i << 8);
        float o = g[d] * (v[i] - mean) * inv + b[d];
        orow[d] = o;
        store_hl1(oh, ol, (size_t)s * DMODEL + d, o);
    }
}

// ============================ attention: pad rows ===========================
__global__ void vmean_part_kernel() {
    int d = blockIdx.x * 256 + threadIdx.x;
    int slab = blockIdx.y;
    float acc = 0.f;
    for (int s = slab * 128; s < (slab + 1) * 128; s++) acc += g_v[(size_t)s * DMODEL + d];
    g_vpart[slab][d] = acc;
}
__global__ void vmean_reduce_kernel() {
    int d = blockIdx.x * 256 + threadIdx.x;
    float a = 0.f;
#pragma unroll
    for (int i = 0; i < 16; i++) a += g_vpart[i][d];
    g_vmean[d] = a * (1.f / (float)S);
}
__global__ void attn_pad_kernel(__half* __restrict__ ch, __half* __restrict__ cl) {
    int s = blockIdx.y;
    if (g_mask[s] != 0) return;
    int d = blockIdx.x * 256 + threadIdx.x;
    store_hl1(ch, cl, (size_t)s * DMODEL + d, g_vmean[d]);
}

// ============================ attention: local rows =========================
#define SMEM_LOCAL_BYTES ((128 * 129 + 128 * 132 + 32 * 128 + 32 * 132) * 4 + 128 * 4)
__global__ __launch_bounds__(256) void attn_local_kernel(__half* __restrict__ ch,
                                                         __half* __restrict__ cl) {
    extern __shared__ float smf[];
    float* Ks = smf;                    // 128 x 129
    float* Vs = Ks + 128 * 129;         // 128 x 132
    float* Qs = Vs + 128 * 132;         // 32 x 128
    float* probs = Qs + 32 * 128;       // 32 x 132
    int* cand = (int*)(probs + 32 * 132);
    __shared__ int s_nc;

    int tid = threadIdx.x;
    int h = blockIdx.y, q0 = blockIdx.x * 32, base = h * DK;

    if (tid < 96) {
        int k = q0 - 32 + tid;
        cand[tid] = (k >= 0 && k < S) ? k : -1;
    }
    if (tid == 0) {
        int cnt = 96, ng = g_nglob;
        for (int i = 0; i < ng; i++) {
            int g = g_globlist[i];
            if (g < q0 - 32 || g > q0 + 63) cand[cnt++] = g;
        }
        s_nc = cnt;
    }
    __syncthreads();
    int nc = s_nc;

    for (int e = tid; e < 128 * 128; e += 256) {
        int j = e >> 7, d = e & 127;
        int k = (j < nc) ? cand[j] : -1;
        float kv = 0.f, vv = 0.f;
        if (k >= 0) {
            kv = g_k[(size_t)k * DMODEL + base + d];
            vv = g_v[(size_t)k * DMODEL + base + d];
        }
        Ks[j * 129 + d] = kv;
        Vs[j * 132 + d] = vv;
    }
    for (int e = tid; e < 32 * 128; e += 256) {
        int r = e >> 7, d = e & 127;
        Qs[e] = g_q[(size_t)(q0 + r) * DMODEL + base + d];
    }
    __syncthreads();

    int warp = tid >> 5, lane = tid & 31;
    int r0 = warp * 4;
    const float NI = neg_inf();
    bool act[4];
#pragma unroll
    for (int rr = 0; rr < 4; rr++) act[rr] = (g_mask[q0 + r0 + rr] == 1);

    const float* q0p = &Qs[(r0 + 0) * 128];
    const float* q1p = &Qs[(r0 + 1) * 128];
    const float* q2p = &Qs[(r0 + 2) * 128];
    const float* q3p = &Qs[(r0 + 3) * 128];
    const float* kp0 = &Ks[(lane) * 129];
    const float* kp1 = &Ks[(lane + 32) * 129];
    const float* kp2 = &Ks[(lane + 64) * 129];
    const float* kp3 = &Ks[(lane + 96) * 129];

    // single-pass scores: 4 K rows x 4 Q rows per lane (8 LDS / 16 FMA per d)
    float a2[4][4];
#pragma unroll
    for (int m = 0; m < 4; m++)
#pragma unroll
        for (int rr = 0; rr < 4; rr++) a2[m][rr] = 0.f;
#pragma unroll 4
    for (int d = 0; d < 128; d++) {
        float kv0 = kp0[d], kv1 = kp1[d], kv2 = kp2[d], kv3 = kp3[d];
        float qv0 = q0p[d], qv1 = q1p[d], qv2 = q2p[d], qv3 = q3p[d];
        a2[0][0] = fmaf(kv0, qv0, a2[0][0]);
        a2[0][1] = fmaf(kv0, qv1, a2[0][1]);
        a2[0][2] = fmaf(kv0, qv2, a2[0][2]);
        a2[0][3] = fmaf(kv0, qv3, a2[0][3]);
        a2[1][0] = fmaf(kv1, qv0, a2[1][0]);
        a2[1][1] = fmaf(kv1, qv1, a2[1][1]);
        a2[1][2] = fmaf(kv1, qv2, a2[1][2]);
        a2[1][3] = fmaf(kv1, qv3, a2[1][3]);
        a2[2][0] = fmaf(kv2, qv0, a2[2][0]);
        a2[2][1] = fmaf(kv2, qv1, a2[2][1]);
        a2[2][2] = fmaf(kv2, qv2, a2[2][2]);
        a2[2][3] = fmaf(kv2, qv3, a2[2][3]);
        a2[3][0] = fmaf(kv3, qv0, a2[3][0]);
        a2[3][1] = fmaf(kv3, qv1, a2[3][1]);
        a2[3][2] = fmaf(kv3, qv2, a2[3][2]);
        a2[3][3] = fmaf(kv3, qv3, a2[3][3]);
    }
    float sv[4][4];  // [m][rr]
#pragma unroll
    for (int m = 0; m < 4; m++) {
        int j = lane + (m << 5);
        int k = (j < nc) ? cand[j] : -1;
        int mk = (k >= 0) ? g_mask[k] : 0;
#pragma unroll
        for (int rr = 0; rr < 4; rr++) {
            int q = q0 + r0 + rr;
            int dd = q - k;
            if (dd < 0) dd = -dd;
            bool ok = act[rr] && (k >= 0) && (mk != 0) && ((j >= 96) || (mk == 2) || (dd <= 32));
            sv[m][rr] = ok ? a2[m][rr] * SCALE_F : NI;
        }
    }
#pragma unroll
    for (int rr = 0; rr < 4; rr++) {
        int r = r0 + rr;
        float mx = fmaxf(fmaxf(sv[0][rr], sv[1][rr]), fmaxf(sv[2][rr], sv[3][rr]));
#pragma unroll
        for (int o = 16; o; o >>= 1) mx = fmaxf(mx, __shfl_xor_sync(0xffffffffu, mx, o));
        float p[4];
        float sum = 0.f;
#pragma unroll
        for (int m = 0; m < 4; m++) {
            p[m] = (sv[m][rr] == NI) ? 0.f : expf(sv[m][rr] - mx);
            sum += p[m];
        }
#pragma unroll
        for (int o = 16; o; o >>= 1) sum += __shfl_xor_sync(0xffffffffu, sum, o);
        if (act[rr]) {
            float inv = 1.f / sum;
#pragma unroll
            for (int m = 0; m < 4; m++) {
                int j = lane + (m << 5);
                probs[r * 132 + j] = p[m] * inv;
            }
        }
    }
    __syncthreads();
    {
        int r = tid >> 3, c0 = tid & 7;
        int q = q0 + r;
        if (g_mask[q] == 1) {
            const float* pr = &probs[r * 132];
            const float4* V4 = (const float4*)Vs;
#pragma unroll
            for (int u = 0; u < 4; u++) {
                int d4 = c0 + (u << 3);
                float x0 = 0.f, x1 = 0.f, x2 = 0.f, x3 = 0.f;
                for (int j = 0; j < nc; j++) {
                    float p = pr[j];
                    float4 v = V4[j * 33 + d4];
                    x0 = fmaf(p, v.x, x0);
                    x1 = fmaf(p, v.y, x1);
                    x2 = fmaf(p, v.z, x2);
                    x3 = fmaf(p, v.w, x3);
                }
                size_t off = (size_t)q * DMODEL + base + d4 * 4;
                store_hl2(ch, cl, off, x0, x1);
                store_hl2(ch, cl, off + 2, x2, x3);
            }
        }
    }
}

// ============================ attention: global rows (slab-parallel) ========
#define SMEM_GSC ((128 * 129 + 32 * 128) * 4)
__global__ __launch_bounds__(256) void ga_scores_kernel() {
    extern __shared__ float smf[];
    float* Ks = smf;
    float* Qs = Ks + 128 * 129;
    int slab = blockIdx.x, h = blockIdx.y, tid = threadIdx.x;
    int ng = g_nglob;
    for (int e = tid; e < 128 * 128; e += 256) {
        int j = e >> 7, d = e & 127;
        Ks[j * 129 + d] = g_k[(size_t)(slab * 128 + j) * DMODEL + h * DK + d];
    }
    for (int e = tid; e < 32 * 128; e += 256) {
        int r = e >> 7, d = e & 127;
        Qs[e] = (r < ng) ? g_q[(size_t)g_globlist[r] * DMODEL + h * DK + d] : 0.f;
    }
    __syncthreads();
    int kk = tid & 127, half = tid >> 7;
    int k = slab * 128 + kk;
    bool nonpad = (g_mask[k] != 0);
    for (int qi = half; qi < ng; qi += 2) {
        float sd = 0.f;
        const float* qp = &Qs[qi * 128];
        const float* kp = &Ks[kk * 129];
#pragma unroll 16
        for (int d = 0; d < 128; d++) sd += qp[d] * kp[d];
        g_gsc[((size_t)h * 32 + qi) * S + k] = nonpad ? sd * SCALE_F : neg_inf();
    }
}
__global__ __launch_bounds__(256) void ga_softmax_kernel() {
    int qi = blockIdx.x, h = blockIdx.y, tid = threadIdx.x;
    if (qi >= g_nglob) return;
    float* row = g_gsc + ((size_t)h * 32 + qi) * S;
    const float NI = neg_inf();
    float mx = NI;
    for (int k = tid; k < S; k += 256) mx = fmaxf(mx, row[k]);
    mx = blockMax256(mx);
    float sum = 0.f;
    for (int k = tid; k < S; k += 256) {
        float v = row[k];
        float p = (v == NI) ? 0.f : expf(v - mx);
        row[k] = p;
        sum += p;
    }
    sum = blockSum256(sum);
    float inv = 1.f / sum;
    for (int k = tid; k < S; k += 256) row[k] *= inv;
}
#define SMEM_GAV ((128 * 132 + 32 * 132) * 4)
__global__ __launch_bounds__(256) void ga_av_kernel() {
    extern __shared__ float smf[];
    float* Vs = smf;                // 128 x 132
    float* Ps = Vs + 128 * 132;     // 32 x 132
    int slab = blockIdx.x, h = blockIdx.y, tid = threadIdx.x;
    int ng = g_nglob;
    for (int e = tid; e < 128 * 128; e += 256) {
        int j = e >> 7, d = e & 127;
        Vs[j * 132 + d] = g_v[(size_t)(slab * 128 + j) * DMODEL + h * DK + d];
    }
    for (int e = tid; e < 32 * 128; e += 256) {
        int r = e >> 7, kk = e & 127;
        Ps[r * 132 + kk] = (r < ng) ? g_gsc[((size_t)h * 32 + r) * S + slab * 128 + kk] : 0.f;
    }
    __syncthreads();
    int qi = tid >> 3, c0 = tid & 7;
    if (qi < ng) {
        const float* pp = &Ps[qi * 132];
        const float4* V4 = (const float4*)Vs;
#pragma unroll
        for (int u = 0; u < 4; u++) {
            int d4 = c0 + (u << 3);
            float x0 = 0.f, x1 = 0.f, x2 = 0.f, x3 = 0.f;
#pragma unroll 4
            for (int kk = 0; kk < 128; kk++) {
                float p = pp[kk];
                float4 v = V4[kk * 33 + d4];
                x0 = fmaf(p, v.x, x0);
                x1 = fmaf(p, v.y, x1);
                x2 = fmaf(p, v.z, x2);
                x3 = fmaf(p, v.w, x3);
            }
            float4 o = {x0, x1, x2, x3};
            *(float4*)&g_gpart[(((size_t)slab * NH + h) * 32 + qi) * DK + d4 * 4] = o;
        }
    }
}
__global__ __launch_bounds__(128) void ga_out_kernel(__half* __restrict__ ch,
                                                     __half* __restrict__ cl) {
    int qi = blockIdx.x, h = blockIdx.y, d = threadIdx.x;
    if (qi >= g_nglob) return;
    float s = 0.f;
#pragma unroll
    for (int slab = 0; slab < 16; slab++)
        s += g_gpart[(((size_t)slab * NH + h) * 32 + qi) * DK + d];
    int q = g_globlist[qi];
    store_hl1(ch, cl, (size_t)q * DMODEL + h * DK + d, s);
}

// ============================ driver ========================================
extern "C" void kernel_launch(void* const* d_in, const int* in_sizes, int n_in,
                              void* d_out, int out_size) {
    const int* Tp = (const int*)d_in[0];
    const float* enc = (const float*)d_in[1];
    const int* gidx = (const int*)d_in[2];
    const float* Wq = (const float*)d_in[3];
    const float* Wk = (const float*)d_in[4];
    const float* Wv = (const float*)d_in[5];
    const float* Wo = (const float*)d_in[6];
    const float* ln1g = (const float*)d_in[7];
    const float* ln1b = (const float*)d_in[8];
    const float* W1 = (const float*)d_in[9];
    const float* W2 = (const float*)d_in[10];
    const float* ln2g = (const float*)d_in[11];
    const float* ln2b = (const float*)d_in[12];
    float* out = (float*)d_out;

    cudaFuncSetAttribute(attn_local_kernel, cudaFuncAttributeMaxDynamicSharedMemorySize,
                         SMEM_LOCAL_BYTES);
    cudaFuncSetAttribute(ga_scores_kernel, cudaFuncAttributeMaxDynamicSharedMemorySize, SMEM_GSC);
    cudaFuncSetAttribute(ga_av_kernel, cudaFuncAttributeMaxDynamicSharedMemorySize, SMEM_GAV);
    cudaFuncSetAttribute(gemm_mma, cudaFuncAttributeMaxDynamicSharedMemorySize, GEMM_SMEM);

    float *px, *pq, *pk, *pv, *py;
    __half *pw, *pah, *pal, *phh, *phl;
    cudaGetSymbolAddress((void**)&px, g_x);
    cudaGetSymbolAddress((void**)&pq, g_q);
    cudaGetSymbolAddress((void**)&pk, g_k);
    cudaGetSymbolAddress((void**)&pv, g_v);
    cudaGetSymbolAddress((void**)&py, g_y);
    cudaGetSymbolAddress((void**)&pw, g_wt);
    cudaGetSymbolAddress((void**)&pah, g_ah);
    cudaGetSymbolAddress((void**)&pal, g_al);
    cudaGetSymbolAddress((void**)&phh, g_hh);
    cudaGetSymbolAddress((void**)&phl, g_hl);
    float* py1 = py + (size_t)S * DMODEL;

    const size_t M1 = 1024u * 1024u;

    // pediv(0), prep(1), tsplit_all(2), QKV gemm(3): profiler window -> gemm.
    pediv_kernel<<<2, 256>>>();
    prep_kernel<<<(S * DMODEL) / 256, 256>>>(enc);
    tsplit_all_kernel<<<dim3(64, 64, 24), dim3(32, 8)>>>(Wq, Wk, Wv, Wo, W1, W2, pw);
    gemm_mma<<<dim3(DMODEL / 128, S / 128, 3), 256, GEMM_SMEM>>>(
        S, DMODEL, DMODEL, pah, pal, pw, pq, pw + M1, pk, pw + 2 * M1, pv, 0, nullptr, nullptr,
        0);

    mask_zero_kernel<<<8, 256>>>();
    mask_scatter_kernel<<<1, 32>>>(gidx);
    mask_build_kernel<<<8, 256>>>(Tp);
    mask_list_kernel<<<1, 32>>>();

    for (int l = 0; l < NLAYERS; l++) {
        size_t wo_ = (size_t)l * LSTRIDE;
        if (l > 0) {
            gemm_mma<<<dim3(DMODEL / 128, S / 128, 3), 256, GEMM_SMEM>>>(
                S, DMODEL, DMODEL, pah, pal, pw + wo_, pq, pw + wo_ + M1, pk, pw + wo_ + 2 * M1,
                pv, 0, nullptr, nullptr, 0);
        }

        vmean_part_kernel<<<dim3(DMODEL / 256, 16), 256>>>();
        vmean_reduce_kernel<<<DMODEL / 256, 256>>>();
        attn_local_kernel<<<dim3(S / 32, NH), 256, SMEM_LOCAL_BYTES>>>(pah, pal);
        ga_scores_kernel<<<dim3(16, NH), 256, SMEM_GSC>>>();
        ga_softmax_kernel<<<dim3(32, NH), 256>>>();
        ga_av_kernel<<<dim3(16, NH), 256, SMEM_GAV>>>();
        ga_out_kernel<<<dim3(32, NH), 128>>>(pah, pal);
        attn_pad_kernel<<<dim3(DMODEL / 256, S), 256>>>(pah, pal);

        // output projection (split-K x2) + residual LN
        gemm_mma<<<dim3(DMODEL / 128, S / 128, 2), 256, GEMM_SMEM>>>(
            S, DMODEL, DMODEL, pah, pal, pw + wo_ + 3 * M1, py, nullptr, nullptr, nullptr,
            nullptr, 0, nullptr, nullptr, 1);
        ln_kernel<<<S, 256>>>(py, py1, px, ln1g + l * DMODEL, ln1b + l * DMODEL, px, pah, pal);

        // FFN1 (hi/lo fp16 out), FFN2 (split-K x2) + residual LN
        gemm_mma<<<dim3(DFF / 128, S / 128, 1), 256, GEMM_SMEM>>>(
            S, DFF, DMODEL, pah, pal, pw + wo_ + 4 * M1, nullptr, nullptr, nullptr, nullptr,
            nullptr, 1, phh, phl, 0);
        gemm_mma<<<dim3(DMODEL / 128, S / 128, 2), 256, GEMM_SMEM>>>(
            S, DMODEL, DFF, phh, phl, pw + wo_ + 6 * M1, py, nullptr, nullptr, nullptr, nullptr,
            0, nullptr, nullptr, 1);
        ln_kernel<<<S, 256>>>(py, py1, px, ln2g + l * DMODEL, ln2b + l * DMODEL,
                              (l == NLAYERS - 1) ? out : px, pah, pal);
    }
}

// round 14
// speedup vs baseline: 4.0637x; 1.1694x over previous
#include <cuda_runtime.h>
#include <cuda_fp16.h>
#include <math.h>
#include <stdint.h>

#define S 2048
#define DMODEL 1024
#define DFF 2048
#define NH 8
#define DK 128
#define NLAYERS 4

static __device__ __forceinline__ float neg_inf() { return __int_as_float(0xff800000); }
#define SCALE_F 0.08838834764831845f  // 1/sqrt(128)

// ======================= PTX helpers (base sm_80+ features only) ============
__device__ __forceinline__ uint32_t smem_u32(const void* p) {
    uint32_t a;
    asm("{ .reg .u64 t; cvta.to.shared.u64 t, %1; cvt.u32.u64 %0, t; }" : "=r"(a) : "l"(p));
    return a;
}
__device__ __forceinline__ void cp16(uint32_t dst, const void* src) {
    asm volatile("cp.async.cg.shared.global [%0], [%1], 16;" ::"r"(dst), "l"(src));
}
#define CP_COMMIT() asm volatile("cp.async.commit_group;" ::: "memory")
#define CP_WAIT1() asm volatile("cp.async.wait_group 1;" ::: "memory")
#define CP_WAIT0() asm volatile("cp.async.wait_group 0;" ::: "memory")

__device__ __forceinline__ void ldmx4(uint32_t* r, uint32_t addr) {
    asm volatile("ldmatrix.sync.aligned.m8n8.x4.shared.b16 {%0,%1,%2,%3}, [%4];"
                 : "=r"(r[0]), "=r"(r[1]), "=r"(r[2]), "=r"(r[3])
                 : "r"(addr));
}
__device__ __forceinline__ void mma16816(float* d, const uint32_t* a, const uint32_t* b) {
    asm volatile(
        "mma.sync.aligned.m16n8k16.row.col.f32.f16.f16.f32 "
        "{%0,%1,%2,%3}, {%4,%5,%6,%7}, {%8,%9}, {%0,%1,%2,%3};"
        : "+f"(d[0]), "+f"(d[1]), "+f"(d[2]), "+f"(d[3])
        : "r"(a[0]), "r"(a[1]), "r"(a[2]), "r"(a[3]), "r"(b[0]), "r"(b[1]));
}
__device__ __forceinline__ void store_hl2(__half* Hh, __half* Hl, size_t off, float x, float y) {
    __half hx = __float2half_rn(x), hy = __float2half_rn(y);
    __half2 h;
    h.x = hx;
    h.y = hy;
    __half2 l;
    l.x = __float2half_rn(x - __half2float(hx));
    l.y = __float2half_rn(y - __half2float(hy));
    *(__half2*)(Hh + off) = h;
    *(__half2*)(Hl + off) = l;
}
__device__ __forceinline__ void store_hl1(__half* Hh, __half* Hl, size_t off, float x) {
    __half hx = __float2half_rn(x);
    Hh[off] = hx;
    Hl[off] = __float2half_rn(x - __half2float(hx));
}

// ============================ scratch globals ===============================
__device__ float g_x[S * DMODEL];
__device__ float g_q[S * DMODEL];
__device__ float g_k[S * DMODEL];
__device__ float g_v[S * DMODEL];
__device__ float g_y[2 * S * DMODEL];  // split-K partial outputs
__device__ float g_vpart[16][DMODEL];
__device__ int g_mask[S];  // 0 pad, 1 local, 2 global
__device__ int g_globlist[64];
__device__ int g_nglob;
__device__ float g_divhi[512];
__device__ float g_divlo[512];
__device__ float g_gsc[NH * 32 * S];
__device__ float g_gpart[16 * NH * 32 * DK];

#define LSTRIDE (8 * 1024 * 1024)
__device__ __half g_wt[NLAYERS * LSTRIDE];  // weights: single rn-fp16, transposed
__device__ __half g_ah[S * DMODEL];         // activations hi
__device__ __half g_al[S * DMODEL];         // activations lo
__device__ __half g_hh[S * DFF];            // ffn hidden hi
__device__ __half g_hl[S * DFF];            // ffn hidden lo

// ============================ reductions ====================================
static __device__ __forceinline__ float warpAllSum(float v) {
#pragma unroll
    for (int o = 16; o; o >>= 1) v += __shfl_xor_sync(0xffffffffu, v, o);
    return v;
}
static __device__ __forceinline__ float warpAllMax(float v) {
#pragma unroll
    for (int o = 16; o; o >>= 1) v = fmaxf(v, __shfl_xor_sync(0xffffffffu, v, o));
    return v;
}
static __device__ __forceinline__ float blockSum256(float v) {
    __shared__ float sh[8];
    int lane = threadIdx.x & 31, w = threadIdx.x >> 5;
    v = warpAllSum(v);
    __syncthreads();
    if (lane == 0) sh[w] = v;
    __syncthreads();
    if (w == 0) {
        float t = (lane < 8) ? sh[lane] : 0.f;
        t = warpAllSum(t);
        if (lane == 0) sh[0] = t;
    }
    __syncthreads();
    return sh[0];
}
static __device__ __forceinline__ float blockMax256(float v) {
    __shared__ float sh[8];
    int lane = threadIdx.x & 31, w = threadIdx.x >> 5;
    v = warpAllMax(v);
    __syncthreads();
    if (lane == 0) sh[w] = v;
    __syncthreads();
    if (w == 0) {
        float t = (lane < 8) ? sh[lane] : neg_inf();
        t = warpAllMax(t);
        if (lane == 0) sh[0] = t;
    }
    __syncthreads();
    return sh[0];
}

// ============================ prep / mask ===================================
__global__ void pediv_kernel() {
    int i = blockIdx.x * 256 + threadIdx.x;
    if (i < 512) {
        double dv = exp(-(double)(2 * i) * (9.210340371976184 / 1024.0));
        float h = (float)dv;
        g_divhi[i] = h;
        g_divlo[i] = (float)(dv - (double)h);
    }
}
__global__ void prep_kernel(const float* __restrict__ enc) {
    int idx = blockIdx.x * 256 + threadIdx.x;
    int s = idx >> 10, d = idx & 1023;
    int i = d >> 1;
    float hi = g_divhi[i], lo = g_divlo[i];
    float sf = (float)s;
    float h = sf * hi;
    float e = fmaf(sf, hi, -h);
    float t = fmaf(sf, lo, e);
    const float P2HI = 6.28318548202514648f;
    const float P2LO = -1.74845553e-7f;
    float n = rintf(h * 0.15915494309189535f);
    float r = fmaf(-n, P2HI, h);
    r = fmaf(-n, P2LO, r);
    r += t;
    float pe = (d & 1) ? cosf(r) : sinf(r);
    float x = 2.0f * enc[idx] + pe;
    g_x[idx] = x;
    store_hl1(g_ah, g_al, idx, x);
}
// mask build + ordered global list, one launch
__global__ void mask_all_kernel(const int* __restrict__ gidx, const int* __restrict__ Tp) {
    __shared__ int gs[32];
    int tid = threadIdx.x;
    if (tid < 32) {
        int g = gidx[tid] / 15;
        gs[tid] = (g >= 0 && g < S) ? g : -1;
    }
    __syncthreads();
    int T = *Tp;
    for (int i = tid; i < S; i += 1024) {
        bool isg = false;
#pragma unroll
        for (int j = 0; j < 32; j++) isg |= (gs[j] == i);
        g_mask[i] = isg ? 2 : (i < T ? 1 : 0);
    }
    __syncthreads();
    if (tid < 32) {
        int lane = tid, cnt = 0;
        for (int base = 0; base < S; base += 32) {
            int m = (g_mask[base + lane] == 2);
            unsigned bal = __ballot_sync(0xffffffffu, m);
            if (m) g_globlist[cnt + __popc(bal & ((1u << lane) - 1u))] = base + lane;
            cnt += __popc(bal);
        }
        if (lane == 0) g_nglob = cnt;
    }
}

// ============================ fused weight transpose (rn fp16) ==============
__global__ void tsplit_all_kernel(const float* __restrict__ Wq, const float* __restrict__ Wk,
                                  const float* __restrict__ Wv, const float* __restrict__ Wo,
                                  const float* __restrict__ W1, const float* __restrict__ W2,
                                  __half* __restrict__ dst) {
    const size_t M1 = 1024u * 1024u;
    int z = blockIdx.z;
    int l = z / 6, m = z % 6;
    const float* W;
    int K, N;
    size_t doff = (size_t)l * LSTRIDE;
    if (m == 0) { W = Wq + l * M1; K = 1024; N = 1024; }
    else if (m == 1) { W = Wk + l * M1; K = 1024; N = 1024; doff += M1; }
    else if (m == 2) { W = Wv + l * M1; K = 1024; N = 1024; doff += 2 * M1; }
    else if (m == 3) { W = Wo + l * M1; K = 1024; N = 1024; doff += 3 * M1; }
    else if (m == 4) { W = W1 + l * 2 * M1; K = 1024; N = 2048; doff += 4 * M1; }
    else { W = W2 + l * 2 * M1; K = 2048; N = 1024; doff += 6 * M1; }
    int n0 = blockIdx.x * 32, k0 = blockIdx.y * 32;
    if (n0 >= N || k0 >= K) return;
    __shared__ float t[32][33];
    int tx = threadIdx.x, ty = threadIdx.y;
#pragma unroll
    for (int i = 0; i < 32; i += 8) t[ty + i][tx] = W[(size_t)(k0 + ty + i) * N + n0 + tx];
    __syncthreads();
#pragma unroll
    for (int i = 0; i < 32; i += 8) {
        dst[doff + (size_t)(n0 + ty + i) * K + k0 + tx] = __float2half_rn(t[tx][ty + i]);
    }
}

// ============================ fp16x2 HMMA GEMM ==============================
// C = A@W; A hi/lo fp16 (MxK row-major), B = W^T single fp16 (NxK).
// 128x128 tile, BK=32, 3-stage cp.async, single barrier per chunk, 2 CTAs/SM.
#define TSTRIDE 80
#define TILE_B (128 * TSTRIDE)
#define STAGE_B (3 * TILE_B)      // Ah, Al, B
#define GEMM_SMEM (3 * STAGE_B)   // 92160; x2 CTA = 184320 <= 227KB

__global__ __launch_bounds__(256, 2) void gemm_mma(
    int M, int N, int K, const __half* __restrict__ Ahi, const __half* __restrict__ Alo,
    const __half* B0, float* C0, const __half* B1, float* C1, const __half* B2, float* C2,
    int relu, __half* Hh, __half* Hl, int ksplit) {
    extern __shared__ char sm[];
    const __half* B;
    float* C;
    int z = blockIdx.z;
    int kbeg = 0, Keff = K;
    if (ksplit) {
        B = B0;
        Keff = K >> 1;
        kbeg = z * Keff;
        C = C0 + (size_t)z * M * N;
    } else if (z == 0) { B = B0; C = C0; }
    else if (z == 1) { B = B1; C = C1; }
    else { B = B2; C = C2; }

    uint32_t smb = smem_u32(sm);
    int tid = threadIdx.x, wid = tid >> 5, lane = tid & 31;
    int row0 = blockIdx.y * 128, col0 = blockIdx.x * 128;
    int wm = wid >> 2, wn = wid & 3;

    float acc[4][4][4];
#pragma unroll
    for (int a = 0; a < 4; a++)
#pragma unroll
        for (int b = 0; b < 4; b++)
#pragma unroll
            for (int c = 0; c < 4; c++) acc[a][b][c] = 0.f;

    int cid0 = tid * 2, cid1 = tid * 2 + 1;
    int lr0 = cid0 >> 2, lc0 = (cid0 & 3) * 16;
    int lr1 = cid1 >> 2, lc1 = (cid1 & 3) * 16;

    const __half* srcs[3] = {Ahi, Alo, B};
    int rbase[3] = {row0, row0, col0};
    const int nch = Keff / 32;

    // prologue: chunks 0,1 -> stages 0,1
#pragma unroll
    for (int pc = 0; pc < 2; pc++) {
        uint32_t sb = smb + pc * STAGE_B;
        int k0 = kbeg + pc * 32;
#pragma unroll
        for (int t = 0; t < 3; t++) {
            const __half* src = srcs[t];
            uint32_t tb = sb + t * TILE_B;
            cp16(tb + lr0 * TSTRIDE + lc0, src + (size_t)(rbase[t] + lr0) * K + k0 + (lc0 >> 1));
            cp16(tb + lr1 * TSTRIDE + lc1, src + (size_t)(rbase[t] + lr1) * K + k0 + (lc1 >> 1));
        }
        CP_COMMIT();
    }

    for (int c = 0; c < nch; c++) {
        if (c + 1 < nch) {
            CP_WAIT1();
        } else {
            CP_WAIT0();
        }
        __syncthreads();
        // safe to overwrite stage (c+2)%3 == (c-1)%3: all warps passed the
        // barrier, so compute(c-1) is globally done.
        if (c + 2 < nch) {
            int k0 = kbeg + (c + 2) * 32;
            uint32_t sb = smb + ((c + 2) % 3) * STAGE_B;
#pragma unroll
            for (int t = 0; t < 3; t++) {
                const __half* src = srcs[t];
                uint32_t tb = sb + t * TILE_B;
                cp16(tb + lr0 * TSTRIDE + lc0,
                     src + (size_t)(rbase[t] + lr0) * K + k0 + (lc0 >> 1));
                cp16(tb + lr1 * TSTRIDE + lc1,
                     src + (size_t)(rbase[t] + lr1) * K + k0 + (lc1 >> 1));
            }
            CP_COMMIT();
        }

        uint32_t base = smb + (c % 3) * STAGE_B;
        uint32_t aH = base, aL = base + TILE_B, bB = base + 2 * TILE_B;
        int arow = wm * 64 + (lane & 15);
        int brow = wn * 32 + (lane & 7) + ((lane >> 4) << 3);
#pragma unroll
        for (int ks = 0; ks < 2; ks++) {
            int akb = ks * 32 + ((lane >> 4) << 4);
            int bkb = ks * 32 + (((lane >> 3) & 1) << 4);
            uint32_t ah[4][4], al[4][4], bh[4][2];
#pragma unroll
            for (int mf = 0; mf < 4; mf++)
                ldmx4(ah[mf], aH + (uint32_t)(arow + mf * 16) * TSTRIDE + akb);
#pragma unroll
            for (int np = 0; np < 2; np++) {
                uint32_t r4[4];
                ldmx4(r4, bB + (uint32_t)(brow + np * 16) * TSTRIDE + bkb);
                bh[np * 2][0] = r4[0]; bh[np * 2][1] = r4[1];
                bh[np * 2 + 1][0] = r4[2]; bh[np * 2 + 1][1] = r4[3];
            }
#pragma unroll
            for (int mf = 0; mf < 4; mf++)
                ldmx4(al[mf], aL + (uint32_t)(arow + mf * 16) * TSTRIDE + akb);
#pragma unroll
            for (int mf = 0; mf < 4; mf++)
#pragma unroll
                for (int nf = 0; nf < 4; nf++) mma16816(acc[mf][nf], ah[mf], bh[nf]);
#pragma unroll
            for (int mf = 0; mf < 4; mf++)
#pragma unroll
                for (int nf = 0; nf < 4; nf++) mma16816(acc[mf][nf], al[mf], bh[nf]);
        }
    }

    int gr = row0 + wm * 64 + (lane >> 2);
    int gc = col0 + wn * 32 + (lane & 3) * 2;
#pragma unroll
    for (int mf = 0; mf < 4; mf++) {
#pragma unroll
        for (int nf = 0; nf < 4; nf++) {
            float* a4 = acc[mf][nf];
            if (relu) {
                a4[0] = fmaxf(a4[0], 0.f);
                a4[1] = fmaxf(a4[1], 0.f);
                a4[2] = fmaxf(a4[2], 0.f);
                a4[3] = fmaxf(a4[3], 0.f);
            }
            size_t o0 = (size_t)(gr + mf * 16) * N + gc + nf * 8;
            size_t o1 = (size_t)(gr + mf * 16 + 8) * N + gc + nf * 8;
            if (Hh) {
                store_hl2(Hh, Hl, o0, a4[0], a4[1]);
                store_hl2(Hh, Hl, o1, a4[2], a4[3]);
            } else {
                float2 v0 = {a4[0], a4[1]};
                float2 v1 = {a4[2], a4[3]};
                *(float2*)(C + o0) = v0;
                *(float2*)(C + o1) = v1;
            }
        }
    }
}

// ============================ LayerNorm (sums two partial ys) ===============
__global__ __launch_bounds__(256) void ln_kernel(const float* __restrict__ y0,
                                                 const float* __restrict__ y1,
                                                 const float* __restrict__ xin,
                                                 const float* __restrict__ g,
                                                 const float* __restrict__ b,
                                                 float* __restrict__ out,
                                                 __half* __restrict__ oh,
                                                 __half* __restrict__ ol) {
    int s = blockIdx.x, tid = threadIdx.x;
    const float* y0r = y0 + (size_t)s * DMODEL;
    const float* y1r = y1 + (size_t)s * DMODEL;
    const float* xr = xin + (size_t)s * DMODEL;
    float v[4];
    float sum = 0.f;
#pragma unroll
    for (int i = 0; i < 4; i++) {
        int d = tid + (i << 8);
        v[i] = (y0r[d] + y1r[d]) + xr[d];
        sum += v[i];
    }
    float mean = blockSum256(sum) * (1.f / 1024.f);
    float sq = 0.f;
#pragma unroll
    for (int i = 0; i < 4; i++) {
        float t = v[i] - mean;
        sq += t * t;
    }
    float var = blockSum256(sq) * (1.f / 1024.f);
    float inv = 1.f / sqrtf(var + 1e-5f);
    float* orow = out + (size_t)s * DMODEL;
#pragma unroll
    for (int i = 0; i < 4; i++) {
        int d = tid + (i << 8);
        float o = g[d] * (v[i] - mean) * inv + b[d];
        orow[d] = o;
        store_hl1(oh, ol, (size_t)s * DMODEL + d, o);
    }
}

// ============================ attention: pad rows ===========================
__global__ void vmean_part_kernel() {
    int d = blockIdx.x * 256 + threadIdx.x;
    int slab = blockIdx.y;
    float acc = 0.f;
    for (int s = slab * 128; s < (slab + 1) * 128; s++) acc += g_v[(size_t)s * DMODEL + d];
    g_vpart[slab][d] = acc;
}
__global__ void attn_pad_kernel(__half* __restrict__ ch, __half* __restrict__ cl) {
    int s = blockIdx.y;
    if (g_mask[s] != 0) return;
    int d = blockIdx.x * 256 + threadIdx.x;
    float a = 0.f;
#pragma unroll
    for (int i = 0; i < 16; i++) a += g_vpart[i][d];
    store_hl1(ch, cl, (size_t)s * DMODEL + d, a * (1.f / (float)S));
}

// ============================ attention: local rows =========================
#define SMEM_LOCAL_BYTES ((128 * 129 + 128 * 132 + 32 * 128 + 32 * 132) * 4 + 128 * 4)
__global__ __launch_bounds__(256) void attn_local_kernel(__half* __restrict__ ch,
                                                         __half* __restrict__ cl) {
    extern __shared__ float smf[];
    float* Ks = smf;                    // 128 x 129
    float* Vs = Ks + 128 * 129;         // 128 x 132
    float* Qs = Vs + 128 * 132;         // 32 x 128
    float* probs = Qs + 32 * 128;       // 32 x 132
    int* cand = (int*)(probs + 32 * 132);
    __shared__ int s_nc;

    int tid = threadIdx.x;
    int h = blockIdx.y, q0 = blockIdx.x * 32, base = h * DK;

    if (tid < 96) {
        int k = q0 - 32 + tid;
        cand[tid] = (k >= 0 && k < S) ? k : -1;
    }
    if (tid == 0) {
        int cnt = 96, ng = g_nglob;
        for (int i = 0; i < ng; i++) {
            int g = g_globlist[i];
            if (g < q0 - 32 || g > q0 + 63) cand[cnt++] = g;
        }
        s_nc = cnt;
    }
    __syncthreads();
    int nc = s_nc;

    for (int e = tid; e < 128 * 32; e += 256) {
        int j = e >> 5, d = (e & 31) << 2;
        int k = (j < nc) ? cand[j] : -1;
        float4 kv = make_float4(0.f, 0.f, 0.f, 0.f), vv = kv;
        if (k >= 0) {
            kv = *(const float4*)&g_k[(size_t)k * DMODEL + base + d];
            vv = *(const float4*)&g_v[(size_t)k * DMODEL + base + d];
        }
        Ks[j * 129 + d] = kv.x;
        Ks[j * 129 + d + 1] = kv.y;
        Ks[j * 129 + d + 2] = kv.z;
        Ks[j * 129 + d + 3] = kv.w;
        *(float4*)&Vs[j * 132 + d] = vv;
    }
    for (int e = tid; e < 32 * 32; e += 256) {
        int r = e >> 5, d = (e & 31) << 2;
        *(float4*)&Qs[r * 128 + d] = *(const float4*)&g_q[(size_t)(q0 + r) * DMODEL + base + d];
    }
    __syncthreads();

    int warp = tid >> 5, lane = tid & 31;
    int r0 = warp * 4;
    const float NI = neg_inf();
    bool act[4];
#pragma unroll
    for (int rr = 0; rr < 4; rr++) act[rr] = (g_mask[q0 + r0 + rr] == 1);

    const float* q0p = &Qs[(r0 + 0) * 128];
    const float* q1p = &Qs[(r0 + 1) * 128];
    const float* q2p = &Qs[(r0 + 2) * 128];
    const float* q3p = &Qs[(r0 + 3) * 128];
    const float* kp0 = &Ks[(lane) * 129];
    const float* kp1 = &Ks[(lane + 32) * 129];
    const float* kp2 = &Ks[(lane + 64) * 129];
    const float* kp3 = &Ks[(lane + 96) * 129];

    float a2[4][4];
#pragma unroll
    for (int m = 0; m < 4; m++)
#pragma unroll
        for (int rr = 0; rr < 4; rr++) a2[m][rr] = 0.f;
#pragma unroll 4
    for (int d = 0; d < 128; d++) {
        float kv0 = kp0[d], kv1 = kp1[d], kv2 = kp2[d], kv3 = kp3[d];
        float qv0 = q0p[d], qv1 = q1p[d], qv2 = q2p[d], qv3 = q3p[d];
        a2[0][0] = fmaf(kv0, qv0, a2[0][0]);
        a2[0][1] = fmaf(kv0, qv1, a2[0][1]);
        a2[0][2] = fmaf(kv0, qv2, a2[0][2]);
        a2[0][3] = fmaf(kv0, qv3, a2[0][3]);
        a2[1][0] = fmaf(kv1, qv0, a2[1][0]);
        a2[1][1] = fmaf(kv1, qv1, a2[1][1]);
        a2[1][2] = fmaf(kv1, qv2, a2[1][2]);
        a2[1][3] = fmaf(kv1, qv3, a2[1][3]);
        a2[2][0] = fmaf(kv2, qv0, a2[2][0]);
        a2[2][1] = fmaf(kv2, qv1, a2[2][1]);
        a2[2][2] = fmaf(kv2, qv2, a2[2][2]);
        a2[2][3] = fmaf(kv2, qv3, a2[2][3]);
        a2[3][0] = fmaf(kv3, qv0, a2[3][0]);
        a2[3][1] = fmaf(kv3, qv1, a2[3][1]);
        a2[3][2] = fmaf(kv3, qv2, a2[3][2]);
        a2[3][3] = fmaf(kv3, qv3, a2[3][3]);
    }
    float sv[4][4];  // [m][rr]
#pragma unroll
    for (int m = 0; m < 4; m++) {
        int j = lane + (m << 5);
        int k = (j < nc) ? cand[j] : -1;
        int mk = (k >= 0) ? g_mask[k] : 0;
#pragma unroll
        for (int rr = 0; rr < 4; rr++) {
            int q = q0 + r0 + rr;
            int dd = q - k;
            if (dd < 0) dd = -dd;
            bool ok = act[rr] && (k >= 0) && (mk != 0) && ((j >= 96) || (mk == 2) || (dd <= 32));
            sv[m][rr] = ok ? a2[m][rr] * SCALE_F : NI;
        }
    }
#pragma unroll
    for (int rr = 0; rr < 4; rr++) {
        int r = r0 + rr;
        float mx = fmaxf(fmaxf(sv[0][rr], sv[1][rr]), fmaxf(sv[2][rr], sv[3][rr]));
#pragma unroll
        for (int o = 16; o; o >>= 1) mx = fmaxf(mx, __shfl_xor_sync(0xffffffffu, mx, o));
        float p[4];
        float sum = 0.f;
#pragma unroll
        for (int m = 0; m < 4; m++) {
            p[m] = (sv[m][rr] == NI) ? 0.f : expf(sv[m][rr] - mx);
            sum += p[m];
        }
#pragma unroll
        for (int o = 16; o; o >>= 1) sum += __shfl_xor_sync(0xffffffffu, sum, o);
        if (act[rr]) {
            float inv = 1.f / sum;
#pragma unroll
            for (int m = 0; m < 4; m++) {
                int j = lane + (m << 5);
                probs[r * 132 + j] = p[m] * inv;
            }
        }
    }
    __syncthreads();
    {
        int r = tid >> 3, c0 = tid & 7;
        int q = q0 + r;
        if (g_mask[q] == 1) {
            const float* pr = &probs[r * 132];
            const float4* V4 = (const float4*)Vs;
#pragma unroll
            for (int u = 0; u < 4; u++) {
                int d4 = c0 + (u << 3);
                float x0 = 0.f, x1 = 0.f, x2 = 0.f, x3 = 0.f;
                for (int j = 0; j < nc; j++) {
                    float p = pr[j];
                    float4 v = V4[j * 33 + d4];
                    x0 = fmaf(p, v.x, x0);
                    x1 = fmaf(p, v.y, x1);
                    x2 = fmaf(p, v.z, x2);
                    x3 = fmaf(p, v.w, x3);
                }
                size_t off = (size_t)q * DMODEL + base + d4 * 4;
                store_hl2(ch, cl, off, x0, x1);
                store_hl2(ch, cl, off + 2, x2, x3);
            }
        }
    }
}

// ============================ attention: global rows (slab-parallel) ========
#define SMEM_GSC ((128 * 129 + 32 * 128) * 4)
__global__ __launch_bounds__(256) void ga_scores_kernel() {
    extern __shared__ float smf[];
    float* Ks = smf;
    float* Qs = Ks + 128 * 129;
    int slab = blockIdx.x, h = blockIdx.y, tid = threadIdx.x;
    int ng = g_nglob;
    for (int e = tid; e < 128 * 32; e += 256) {
        int j = e >> 5, d = (e & 31) << 2;
        float4 kv = *(const float4*)&g_k[(size_t)(slab * 128 + j) * DMODEL + h * DK + d];
        Ks[j * 129 + d] = kv.x;
        Ks[j * 129 + d + 1] = kv.y;
        Ks[j * 129 + d + 2] = kv.z;
        Ks[j * 129 + d + 3] = kv.w;
    }
    for (int e = tid; e < 32 * 32; e += 256) {
        int r = e >> 5, d = (e & 31) << 2;
        float4 qv = make_float4(0.f, 0.f, 0.f, 0.f);
        if (r < ng) qv = *(const float4*)&g_q[(size_t)g_globlist[r] * DMODEL + h * DK + d];
        *(float4*)&Qs[r * 128 + d] = qv;
    }
    __syncthreads();
    int kk = tid & 127, half = tid >> 7;
    int k = slab * 128 + kk;
    bool nonpad = (g_mask[k] != 0);
    for (int qi = half; qi < ng; qi += 2) {
        float sd = 0.f;
        const float* qp = &Qs[qi * 128];
        const float* kp = &Ks[kk * 129];
#pragma unroll 16
        for (int d = 0; d < 128; d++) sd += qp[d] * kp[d];
        g_gsc[((size_t)h * 32 + qi) * S + k] = nonpad ? sd * SCALE_F : neg_inf();
    }
}
__global__ __launch_bounds__(256) void ga_softmax_kernel() {
    int qi = blockIdx.x, h = blockIdx.y, tid = threadIdx.x;
    if (qi >= g_nglob) return;
    float* row = g_gsc + ((size_t)h * 32 + qi) * S;
    const float NI = neg_inf();
    float mx = NI;
    for (int k = tid; k < S; k += 256) mx = fmaxf(mx, row[k]);
    mx = blockMax256(mx);
    float sum = 0.f;
    for (int k = tid; k < S; k += 256) {
        float v = row[k];
        float p = (v == NI) ? 0.f : expf(v - mx);
        row[k] = p;
        sum += p;
    }
    sum = blockSum256(sum);
    float inv = 1.f / sum;
    for (int k = tid; k < S; k += 256) row[k] *= inv;
}
#define SMEM_GAV ((128 * 132 + 32 * 132) * 4)
__global__ __launch_bounds__(256) void ga_av_kernel() {
    extern __shared__ float smf[];
    float* Vs = smf;                // 128 x 132
    float* Ps = Vs + 128 * 132;     // 32 x 132
    int slab = blockIdx.x, h = blockIdx.y, tid = threadIdx.x;
    int ng = g_nglob;
    for (int e = tid; e < 128 * 32; e += 256) {
        int j = e >> 5, d = (e & 31) << 2;
        *(float4*)&Vs[j * 132 + d] =
            *(const float4*)&g_v[(size_t)(slab * 128 + j) * DMODEL + h * DK + d];
    }
    for (int e = tid; e < 32 * 32; e += 256) {
        int r = e >> 5, kk = (e & 31) << 2;
        float4 pv = make_float4(0.f, 0.f, 0.f, 0.f);
        if (r < ng) pv = *(const float4*)&g_gsc[((size_t)h * 32 + r) * S + slab * 128 + kk];
        *(float4*)&Ps[r * 132 + kk] = pv;
    }
    __syncthreads();
    int qi = tid >> 3, c0 = tid & 7;
    if (qi < ng) {
        const float* pp = &Ps[qi * 132];
        const float4* V4 = (const float4*)Vs;
#pragma unroll
        for (int u = 0; u < 4; u++) {
            int d4 = c0 + (u << 3);
            float x0 = 0.f, x1 = 0.f, x2 = 0.f, x3 = 0.f;
#pragma unroll 4
            for (int kk = 0; kk < 128; kk++) {
                float p = pp[kk];
                float4 v = V4[kk * 33 + d4];
                x0 = fmaf(p, v.x, x0);
                x1 = fmaf(p, v.y, x1);
                x2 = fmaf(p, v.z, x2);
                x3 = fmaf(p, v.w, x3);
            }
            float4 o = {x0, x1, x2, x3};
            *(float4*)&g_gpart[(((size_t)slab * NH + h) * 32 + qi) * DK + d4 * 4] = o;
        }
    }
}
__global__ __launch_bounds__(128) void ga_out_kernel(__half* __restrict__ ch,
                                                     __half* __restrict__ cl) {
    int qi = blockIdx.x, h = blockIdx.y, d = threadIdx.x;
    if (qi >= g_nglob) return;
    float s = 0.f;
#pragma unroll
    for (int slab = 0; slab < 16; slab++)
        s += g_gpart[(((size_t)slab * NH + h) * 32 + qi) * DK + d];
    int q = g_globlist[qi];
    store_hl1(ch, cl, (size_t)q * DMODEL + h * DK + d, s);
}

// ============================ driver ========================================
extern "C" void kernel_launch(void* const* d_in, const int* in_sizes, int n_in,
                              void* d_out, int out_size) {
    const int* Tp = (const int*)d_in[0];
    const float* enc = (const float*)d_in[1];
    const int* gidx = (const int*)d_in[2];
    const float* Wq = (const float*)d_in[3];
    const float* Wk = (const float*)d_in[4];
    const float* Wv = (const float*)d_in[5];
    const float* Wo = (const float*)d_in[6];
    const float* ln1g = (const float*)d_in[7];
    const float* ln1b = (const float*)d_in[8];
    const float* W1 = (const float*)d_in[9];
    const float* W2 = (const float*)d_in[10];
    const float* ln2g = (const float*)d_in[11];
    const float* ln2b = (const float*)d_in[12];
    float* out = (float*)d_out;

    cudaFuncSetAttribute(attn_local_kernel, cudaFuncAttributeMaxDynamicSharedMemorySize,
                         SMEM_LOCAL_BYTES);
    cudaFuncSetAttribute(ga_scores_kernel, cudaFuncAttributeMaxDynamicSharedMemorySize, SMEM_GSC);
    cudaFuncSetAttribute(ga_av_kernel, cudaFuncAttributeMaxDynamicSharedMemorySize, SMEM_GAV);
    cudaFuncSetAttribute(gemm_mma, cudaFuncAttributeMaxDynamicSharedMemorySize, GEMM_SMEM);

    float *px, *pq, *pk, *pv, *py;
    __half *pw, *pah, *pal, *phh, *phl;
    cudaGetSymbolAddress((void**)&px, g_x);
    cudaGetSymbolAddress((void**)&pq, g_q);
    cudaGetSymbolAddress((void**)&pk, g_k);
    cudaGetSymbolAddress((void**)&pv, g_v);
    cudaGetSymbolAddress((void**)&py, g_y);
    cudaGetSymbolAddress((void**)&pw, g_wt);
    cudaGetSymbolAddress((void**)&pah, g_ah);
    cudaGetSymbolAddress((void**)&pal, g_al);
    cudaGetSymbolAddress((void**)&phh, g_hh);
    cudaGetSymbolAddress((void**)&phl, g_hl);
    float* py1 = py + (size_t)S * DMODEL;

    const size_t M1 = 1024u * 1024u;

    // pediv(0), prep(1), tsplit_all(2), QKV gemm(3): profiler window -> gemm.
    pediv_kernel<<<2, 256>>>();
    prep_kernel<<<(S * DMODEL) / 256, 256>>>(enc);
    tsplit_all_kernel<<<dim3(64, 64, 24), dim3(32, 8)>>>(Wq, Wk, Wv, Wo, W1, W2, pw);
    gemm_mma<<<dim3(DMODEL / 128, S / 128, 3), 256, GEMM_SMEM>>>(
        S, DMODEL, DMODEL, pah, pal, pw, pq, pw + M1, pk, pw + 2 * M1, pv, 0, nullptr, nullptr,
        0);
    mask_all_kernel<<<1, 1024>>>(gidx, Tp);

    for (int l = 0; l < NLAYERS; l++) {
        size_t wo_ = (size_t)l * LSTRIDE;
        if (l > 0) {
            gemm_mma<<<dim3(DMODEL / 128, S / 128, 3), 256, GEMM_SMEM>>>(
                S, DMODEL, DMODEL, pah, pal, pw + wo_, pq, pw + wo_ + M1, pk, pw + wo_ + 2 * M1,
                pv, 0, nullptr, nullptr, 0);
        }

        vmean_part_kernel<<<dim3(DMODEL / 256, 16), 256>>>();
        attn_local_kernel<<<dim3(S / 32, NH), 256, SMEM_LOCAL_BYTES>>>(pah, pal);
        ga_scores_kernel<<<dim3(16, NH), 256, SMEM_GSC>>>();
        ga_softmax_kernel<<<dim3(32, NH), 256>>>();
        ga_av_kernel<<<dim3(16, NH), 256, SMEM_GAV>>>();
        ga_out_kernel<<<dim3(32, NH), 128>>>(pah, pal);
        attn_pad_kernel<<<dim3(DMODEL / 256, S), 256>>>(pah, pal);

        // output projection (split-K x2) + residual LN
        gemm_mma<<<dim3(DMODEL / 128, S / 128, 2), 256, GEMM_SMEM>>>(
            S, DMODEL, DMODEL, pah, pal, pw + wo_ + 3 * M1, py, nullptr, nullptr, nullptr,
            nullptr, 0, nullptr, nullptr, 1);
        ln_kernel<<<S, 256>>>(py, py1, px, ln1g + l * DMODEL, ln1b + l * DMODEL, px, pah, pal);

        // FFN1 (hi/lo fp16 out), FFN2 (split-K x2) + residual LN
        gemm_mma<<<dim3(DFF / 128, S / 128, 1), 256, GEMM_SMEM>>>(
            S, DFF, DMODEL, pah, pal, pw + wo_ + 4 * M1, nullptr, nullptr, nullptr, nullptr,
            nullptr, 1, phh, phl, 0);
        gemm_mma<<<dim3(DMODEL / 128, S / 128, 2), 256, GEMM_SMEM>>>(
            S, DMODEL, DFF, phh, phl, pw + wo_ + 6 * M1, py, nullptr, nullptr, nullptr, nullptr,
            0, nullptr, nullptr, 1);
        ln_kernel<<<S, 256>>>(py, py1, px, ln2g + l * DMODEL, ln2b + l * DMODEL,
                              (l == NLAYERS - 1) ? out : px, pah, pal);
    }
}

// round 15
// speedup vs baseline: 4.0767x; 1.0032x over previous
#include <cuda_runtime.h>
#include <cuda_fp16.h>
#include <math.h>
#include <stdint.h>

#define S 2048
#define DMODEL 1024
#define DFF 2048
#define NH 8
#define DK 128
#define NLAYERS 4

static __device__ __forceinline__ float neg_inf() { return __int_as_float(0xff800000); }
#define SCALE_F 0.08838834764831845f  // 1/sqrt(128)

// ======================= PTX helpers (base sm_80+ features only) ============
__device__ __forceinline__ uint32_t smem_u32(const void* p) {
    uint32_t a;
    asm("{ .reg .u64 t; cvta.to.shared.u64 t, %1; cvt.u32.u64 %0, t; }" : "=r"(a) : "l"(p));
    return a;
}
__device__ __forceinline__ void cp16(uint32_t dst, const void* src) {
    asm volatile("cp.async.cg.shared.global [%0], [%1], 16;" ::"r"(dst), "l"(src));
}
#define CP_COMMIT() asm volatile("cp.async.commit_group;" ::: "memory")
#define CP_WAIT1() asm volatile("cp.async.wait_group 1;" ::: "memory")
#define CP_WAIT0() asm volatile("cp.async.wait_group 0;" ::: "memory")

__device__ __forceinline__ void ldmx4(uint32_t* r, uint32_t addr) {
    asm volatile("ldmatrix.sync.aligned.m8n8.x4.shared.b16 {%0,%1,%2,%3}, [%4];"
                 : "=r"(r[0]), "=r"(r[1]), "=r"(r[2]), "=r"(r[3])
                 : "r"(addr));
}
__device__ __forceinline__ void mma16816(float* d, const uint32_t* a, const uint32_t* b) {
    asm volatile(
        "mma.sync.aligned.m16n8k16.row.col.f32.f16.f16.f32 "
        "{%0,%1,%2,%3}, {%4,%5,%6,%7}, {%8,%9}, {%0,%1,%2,%3};"
        : "+f"(d[0]), "+f"(d[1]), "+f"(d[2]), "+f"(d[3])
        : "r"(a[0]), "r"(a[1]), "r"(a[2]), "r"(a[3]), "r"(b[0]), "r"(b[1]));
}
__device__ __forceinline__ void store_hl2(__half* Hh, __half* Hl, size_t off, float x, float y) {
    __half hx = __float2half_rn(x), hy = __float2half_rn(y);
    __half2 h;
    h.x = hx;
    h.y = hy;
    __half2 l;
    l.x = __float2half_rn(x - __half2float(hx));
    l.y = __float2half_rn(y - __half2float(hy));
    *(__half2*)(Hh + off) = h;
    *(__half2*)(Hl + off) = l;
}
__device__ __forceinline__ void store_hl1(__half* Hh, __half* Hl, size_t off, float x) {
    __half hx = __float2half_rn(x);
    Hh[off] = hx;
    Hl[off] = __float2half_rn(x - __half2float(hx));
}

// ============================ scratch globals ===============================
__device__ float g_x[S * DMODEL];
__device__ float g_q[S * DMODEL];
__device__ float g_k[S * DMODEL];
__device__ float g_v[S * DMODEL];
__device__ float g_y[2 * S * DMODEL];  // split-K partial outputs
__device__ float g_vpart[16][DMODEL];
__device__ int g_mask[S];  // 0 pad, 1 local, 2 global
__device__ int g_globlist[64];
__device__ int g_nglob;
__device__ float g_divhi[512];
__device__ float g_divlo[512];
__device__ float g_gsc[NH * 32 * S];
__device__ float g_gpart[16 * NH * 32 * DK];

#define LSTRIDE (8 * 1024 * 1024)
__device__ __half g_wt[NLAYERS * LSTRIDE];  // weights: single rn-fp16, transposed
__device__ __half g_ah[S * DMODEL];         // activations hi
__device__ __half g_al[S * DMODEL];         // activations lo
__device__ __half g_hh[S * DFF];            // ffn hidden hi
__device__ __half g_hl[S * DFF];            // ffn hidden lo

// ============================ reductions ====================================
static __device__ __forceinline__ float warpAllSum(float v) {
#pragma unroll
    for (int o = 16; o; o >>= 1) v += __shfl_xor_sync(0xffffffffu, v, o);
    return v;
}
static __device__ __forceinline__ float warpAllMax(float v) {
#pragma unroll
    for (int o = 16; o; o >>= 1) v = fmaxf(v, __shfl_xor_sync(0xffffffffu, v, o));
    return v;
}
static __device__ __forceinline__ float blockSum256(float v) {
    __shared__ float sh[8];
    int lane = threadIdx.x & 31, w = threadIdx.x >> 5;
    v = warpAllSum(v);
    __syncthreads();
    if (lane == 0) sh[w] = v;
    __syncthreads();
    if (w == 0) {
        float t = (lane < 8) ? sh[lane] : 0.f;
        t = warpAllSum(t);
        if (lane == 0) sh[0] = t;
    }
    __syncthreads();
    return sh[0];
}
static __device__ __forceinline__ float blockMax256(float v) {
    __shared__ float sh[8];
    int lane = threadIdx.x & 31, w = threadIdx.x >> 5;
    v = warpAllMax(v);
    __syncthreads();
    if (lane == 0) sh[w] = v;
    __syncthreads();
    if (w == 0) {
        float t = (lane < 8) ? sh[lane] : neg_inf();
        t = warpAllMax(t);
        if (lane == 0) sh[0] = t;
    }
    __syncthreads();
    return sh[0];
}

// ============================ prep / mask ===================================
__global__ void pediv_kernel() {
    int i = blockIdx.x * 256 + threadIdx.x;
    if (i < 512) {
        double dv = exp(-(double)(2 * i) * (9.210340371976184 / 1024.0));
        float h = (float)dv;
        g_divhi[i] = h;
        g_divlo[i] = (float)(dv - (double)h);
    }
}
__global__ void prep_kernel(const float* __restrict__ enc) {
    int idx = blockIdx.x * 256 + threadIdx.x;
    int s = idx >> 10, d = idx & 1023;
    int i = d >> 1;
    float hi = g_divhi[i], lo = g_divlo[i];
    float sf = (float)s;
    float h = sf * hi;
    float e = fmaf(sf, hi, -h);
    float t = fmaf(sf, lo, e);
    const float P2HI = 6.28318548202514648f;
    const float P2LO = -1.74845553e-7f;
    float n = rintf(h * 0.15915494309189535f);
    float r = fmaf(-n, P2HI, h);
    r = fmaf(-n, P2LO, r);
    r += t;
    float pe = (d & 1) ? cosf(r) : sinf(r);
    float x = 2.0f * enc[idx] + pe;
    g_x[idx] = x;
    store_hl1(g_ah, g_al, idx, x);
}
__global__ void mask_all_kernel(const int* __restrict__ gidx, const int* __restrict__ Tp) {
    __shared__ int gs[32];
    int tid = threadIdx.x;
    if (tid < 32) {
        int g = gidx[tid] / 15;
        gs[tid] = (g >= 0 && g < S) ? g : -1;
    }
    __syncthreads();
    int T = *Tp;
    for (int i = tid; i < S; i += 1024) {
        bool isg = false;
#pragma unroll
        for (int j = 0; j < 32; j++) isg |= (gs[j] == i);
        g_mask[i] = isg ? 2 : (i < T ? 1 : 0);
    }
    __syncthreads();
    if (tid < 32) {
        int lane = tid, cnt = 0;
        for (int base = 0; base < S; base += 32) {
            int m = (g_mask[base + lane] == 2);
            unsigned bal = __ballot_sync(0xffffffffu, m);
            if (m) g_globlist[cnt + __popc(bal & ((1u << lane) - 1u))] = base + lane;
            cnt += __popc(bal);
        }
        if (lane == 0) g_nglob = cnt;
    }
}

// ============================ fused weight transpose (rn fp16) ==============
__global__ void tsplit_all_kernel(const float* __restrict__ Wq, const float* __restrict__ Wk,
                                  const float* __restrict__ Wv, const float* __restrict__ Wo,
                                  const float* __restrict__ W1, const float* __restrict__ W2,
                                  __half* __restrict__ dst) {
    const size_t M1 = 1024u * 1024u;
    int z = blockIdx.z;
    int l = z / 6, m = z % 6;
    const float* W;
    int K, N;
    size_t doff = (size_t)l * LSTRIDE;
    if (m == 0) { W = Wq + l * M1; K = 1024; N = 1024; }
    else if (m == 1) { W = Wk + l * M1; K = 1024; N = 1024; doff += M1; }
    else if (m == 2) { W = Wv + l * M1; K = 1024; N = 1024; doff += 2 * M1; }
    else if (m == 3) { W = Wo + l * M1; K = 1024; N = 1024; doff += 3 * M1; }
    else if (m == 4) { W = W1 + l * 2 * M1; K = 1024; N = 2048; doff += 4 * M1; }
    else { W = W2 + l * 2 * M1; K = 2048; N = 1024; doff += 6 * M1; }
    int n0 = blockIdx.x * 32, k0 = blockIdx.y * 32;
    if (n0 >= N || k0 >= K) return;
    __shared__ float t[32][33];
    int tx = threadIdx.x, ty = threadIdx.y;
#pragma unroll
    for (int i = 0; i < 32; i += 8) t[ty + i][tx] = W[(size_t)(k0 + ty + i) * N + n0 + tx];
    __syncthreads();
#pragma unroll
    for (int i = 0; i < 32; i += 8) {
        dst[doff + (size_t)(n0 + ty + i) * K + k0 + tx] = __float2half_rn(t[tx][ty + i]);
    }
}

// ============================ fp16x2 HMMA GEMM ==============================
// C = A@W; A hi/lo fp16 (MxK row-major), B = W^T single fp16 (NxK).
// 128x128 tile, BK=32, 3-stage cp.async, single barrier/chunk, 2 CTAs/SM.
// Warp tile 32x64 (warps 4x2): per k16 step 8 ldmx4 instead of 10.
#define TSTRIDE 80
#define TILE_B (128 * TSTRIDE)
#define STAGE_B (3 * TILE_B)      // Ah, Al, B
#define GEMM_SMEM (3 * STAGE_B)   // 92160; x2 CTA = 184320 <= 227KB

__global__ __launch_bounds__(256, 2) void gemm_mma(
    int M, int N, int K, const __half* __restrict__ Ahi, const __half* __restrict__ Alo,
    const __half* B0, float* C0, const __half* B1, float* C1, const __half* B2, float* C2,
    int relu, __half* Hh, __half* Hl, int ksplit) {
    extern __shared__ char sm[];
    const __half* B;
    float* C;
    int z = blockIdx.z;
    int kbeg = 0, Keff = K;
    if (ksplit) {
        B = B0;
        Keff = K >> 1;
        kbeg = z * Keff;
        C = C0 + (size_t)z * M * N;
    } else if (z == 0) { B = B0; C = C0; }
    else if (z == 1) { B = B1; C = C1; }
    else { B = B2; C = C2; }

    uint32_t smb = smem_u32(sm);
    int tid = threadIdx.x, wid = tid >> 5, lane = tid & 31;
    int row0 = blockIdx.y * 128, col0 = blockIdx.x * 128;
    int wm = wid >> 1, wn = wid & 1;  // 4 x 2 warps; tile 32 x 64

    float acc[2][8][4];
#pragma unroll
    for (int a = 0; a < 2; a++)
#pragma unroll
        for (int b = 0; b < 8; b++)
#pragma unroll
            for (int c = 0; c < 4; c++) acc[a][b][c] = 0.f;

    int cid0 = tid * 2, cid1 = tid * 2 + 1;
    int lr0 = cid0 >> 2, lc0 = (cid0 & 3) * 16;
    int lr1 = cid1 >> 2, lc1 = (cid1 & 3) * 16;

    const __half* srcs[3] = {Ahi, Alo, B};
    int rbase[3] = {row0, row0, col0};
    const int nch = Keff / 32;

    // prologue: chunks 0,1 -> stages 0,1
#pragma unroll
    for (int pc = 0; pc < 2; pc++) {
        uint32_t sb = smb + pc * STAGE_B;
        int k0 = kbeg + pc * 32;
#pragma unroll
        for (int t = 0; t < 3; t++) {
            const __half* src = srcs[t];
            uint32_t tb = sb + t * TILE_B;
            cp16(tb + lr0 * TSTRIDE + lc0, src + (size_t)(rbase[t] + lr0) * K + k0 + (lc0 >> 1));
            cp16(tb + lr1 * TSTRIDE + lc1, src + (size_t)(rbase[t] + lr1) * K + k0 + (lc1 >> 1));
        }
        CP_COMMIT();
    }

    for (int c = 0; c < nch; c++) {
        if (c + 1 < nch) {
            CP_WAIT1();
        } else {
            CP_WAIT0();
        }
        __syncthreads();
        // stage (c+2)%3 == (c-1)%3 is reusable: barrier proves compute(c-1) done.
        if (c + 2 < nch) {
            int k0 = kbeg + (c + 2) * 32;
            uint32_t sb = smb + ((c + 2) % 3) * STAGE_B;
#pragma unroll
            for (int t = 0; t < 3; t++) {
                const __half* src = srcs[t];
                uint32_t tb = sb + t * TILE_B;
                cp16(tb + lr0 * TSTRIDE + lc0,
                     src + (size_t)(rbase[t] + lr0) * K + k0 + (lc0 >> 1));
                cp16(tb + lr1 * TSTRIDE + lc1,
                     src + (size_t)(rbase[t] + lr1) * K + k0 + (lc1 >> 1));
            }
            CP_COMMIT();
        }

        uint32_t base = smb + (c % 3) * STAGE_B;
        uint32_t aH = base, aL = base + TILE_B, bB = base + 2 * TILE_B;
        int arow = wm * 32 + (lane & 15);
        int brow = wn * 64 + (lane & 7) + ((lane >> 4) << 3);
#pragma unroll
        for (int ks = 0; ks < 2; ks++) {
            int akb = ks * 32 + ((lane >> 4) << 4);
            int bkb = ks * 32 + (((lane >> 3) & 1) << 4);
            uint32_t ah[2][4], al[2][4], bh[8][2];
#pragma unroll
            for (int mf = 0; mf < 2; mf++)
                ldmx4(ah[mf], aH + (uint32_t)(arow + mf * 16) * TSTRIDE + akb);
#pragma unroll
            for (int np = 0; np < 4; np++) {
                uint32_t r4[4];
                ldmx4(r4, bB + (uint32_t)(brow + np * 16) * TSTRIDE + bkb);
                bh[np * 2][0] = r4[0]; bh[np * 2][1] = r4[1];
                bh[np * 2 + 1][0] = r4[2]; bh[np * 2 + 1][1] = r4[3];
            }
#pragma unroll
            for (int mf = 0; mf < 2; mf++)
                ldmx4(al[mf], aL + (uint32_t)(arow + mf * 16) * TSTRIDE + akb);
#pragma unroll
            for (int mf = 0; mf < 2; mf++)
#pragma unroll
                for (int nf = 0; nf < 8; nf++) mma16816(acc[mf][nf], ah[mf], bh[nf]);
#pragma unroll
            for (int mf = 0; mf < 2; mf++)
#pragma unroll
                for (int nf = 0; nf < 8; nf++) mma16816(acc[mf][nf], al[mf], bh[nf]);
        }
    }

    int gr = row0 + wm * 32 + (lane >> 2);
    int gc = col0 + wn * 64 + (lane & 3) * 2;
#pragma unroll
    for (int mf = 0; mf < 2; mf++) {
#pragma unroll
        for (int nf = 0; nf < 8; nf++) {
            float* a4 = acc[mf][nf];
            if (relu) {
                a4[0] = fmaxf(a4[0], 0.f);
                a4[1] = fmaxf(a4[1], 0.f);
                a4[2] = fmaxf(a4[2], 0.f);
                a4[3] = fmaxf(a4[3], 0.f);
            }
            size_t o0 = (size_t)(gr + mf * 16) * N + gc + nf * 8;
            size_t o1 = (size_t)(gr + mf * 16 + 8) * N + gc + nf * 8;
            if (Hh) {
                store_hl2(Hh, Hl, o0, a4[0], a4[1]);
                store_hl2(Hh, Hl, o1, a4[2], a4[3]);
            } else {
                float2 v0 = {a4[0], a4[1]};
                float2 v1 = {a4[2], a4[3]};
                *(float2*)(C + o0) = v0;
                *(float2*)(C + o1) = v1;
            }
        }
    }
}

// ============================ LayerNorm (warp per row) ======================
__global__ __launch_bounds__(256) void ln_kernel(const float* __restrict__ y0,
                                                 const float* __restrict__ y1,
                                                 const float* __restrict__ xin,
                                                 const float* __restrict__ g,
                                                 const float* __restrict__ b,
                                                 float* __restrict__ out,
                                                 __half* __restrict__ oh,
                                                 __half* __restrict__ ol) {
    int warp = threadIdx.x >> 5, lane = threadIdx.x & 31;
    int s = blockIdx.x * 8 + warp;
    const float* y0r = y0 + (size_t)s * DMODEL;
    const float* y1r = y1 + (size_t)s * DMODEL;
    const float* xr = xin + (size_t)s * DMODEL;
    float4 v[8];
    float sum = 0.f;
#pragma unroll
    for (int i = 0; i < 8; i++) {
        int d = lane * 4 + i * 128;
        float4 a = *(const float4*)(y0r + d);
        float4 c2 = *(const float4*)(y1r + d);
        float4 xv = *(const float4*)(xr + d);
        v[i].x = (a.x + c2.x) + xv.x;
        v[i].y = (a.y + c2.y) + xv.y;
        v[i].z = (a.z + c2.z) + xv.z;
        v[i].w = (a.w + c2.w) + xv.w;
        sum += v[i].x + v[i].y + v[i].z + v[i].w;
    }
    float mean = warpAllSum(sum) * (1.f / 1024.f);
    float sq = 0.f;
#pragma unroll
    for (int i = 0; i < 8; i++) {
        float t0 = v[i].x - mean, t1 = v[i].y - mean, t2 = v[i].z - mean, t3 = v[i].w - mean;
        sq += t0 * t0 + t1 * t1 + t2 * t2 + t3 * t3;
    }
    float var = warpAllSum(sq) * (1.f / 1024.f);
    float inv = 1.f / sqrtf(var + 1e-5f);
    float* orow = out + (size_t)s * DMODEL;
#pragma unroll
    for (int i = 0; i < 8; i++) {
        int d = lane * 4 + i * 128;
        float4 gv = *(const float4*)(g + d);
        float4 bv = *(const float4*)(b + d);
        float4 o;
        o.x = gv.x * (v[i].x - mean) * inv + bv.x;
        o.y = gv.y * (v[i].y - mean) * inv + bv.y;
        o.z = gv.z * (v[i].z - mean) * inv + bv.z;
        o.w = gv.w * (v[i].w - mean) * inv + bv.w;
        *(float4*)(orow + d) = o;
        size_t off = (size_t)s * DMODEL + d;
        store_hl2(oh, ol, off, o.x, o.y);
        store_hl2(oh, ol, off + 2, o.z, o.w);
    }
}

// ============================ attention: pad rows ===========================
__global__ void vmean_part_kernel() {
    int d = blockIdx.x * 256 + threadIdx.x;
    int slab = blockIdx.y;
    float acc = 0.f;
    for (int s = slab * 128; s < (slab + 1) * 128; s++) acc += g_v[(size_t)s * DMODEL + d];
    g_vpart[slab][d] = acc;
}
__global__ void attn_pad_kernel(__half* __restrict__ ch, __half* __restrict__ cl) {
    int s = blockIdx.y;
    if (g_mask[s] != 0) return;
    int d = blockIdx.x * 256 + threadIdx.x;
    float a = 0.f;
#pragma unroll
    for (int i = 0; i < 16; i++) a += g_vpart[i][d];
    store_hl1(ch, cl, (size_t)s * DMODEL + d, a * (1.f / (float)S));
}

// ============================ attention: local rows =========================
#define SMEM_LOCAL_BYTES ((128 * 129 + 128 * 132 + 32 * 128 + 32 * 132) * 4 + 128 * 4)
__global__ __launch_bounds__(256) void attn_local_kernel(__half* __restrict__ ch,
                                                         __half* __restrict__ cl) {
    extern __shared__ float smf[];
    float* Ks = smf;                    // 128 x 129
    float* Vs = Ks + 128 * 129;         // 128 x 132
    float* Qs = Vs + 128 * 132;         // 32 x 128
    float* probs = Qs + 32 * 128;       // 32 x 132
    int* cand = (int*)(probs + 32 * 132);
    __shared__ int s_nc;

    int tid = threadIdx.x;
    int h = blockIdx.y, q0 = blockIdx.x * 32, base = h * DK;

    if (tid < 96) {
        int k = q0 - 32 + tid;
        cand[tid] = (k >= 0 && k < S) ? k : -1;
    }
    if (tid == 0) {
        int cnt = 96, ng = g_nglob;
        for (int i = 0; i < ng; i++) {
            int g = g_globlist[i];
            if (g < q0 - 32 || g > q0 + 63) cand[cnt++] = g;
        }
        s_nc = cnt;
    }
    __syncthreads();
    int nc = s_nc;

    for (int e = tid; e < 128 * 32; e += 256) {
        int j = e >> 5, d = (e & 31) << 2;
        int k = (j < nc) ? cand[j] : -1;
        float4 kv = make_float4(0.f, 0.f, 0.f, 0.f), vv = kv;
        if (k >= 0) {
            kv = *(const float4*)&g_k[(size_t)k * DMODEL + base + d];
            vv = *(const float4*)&g_v[(size_t)k * DMODEL + base + d];
        }
        Ks[j * 129 + d] = kv.x;
        Ks[j * 129 + d + 1] = kv.y;
        Ks[j * 129 + d + 2] = kv.z;
        Ks[j * 129 + d + 3] = kv.w;
        *(float4*)&Vs[j * 132 + d] = vv;
    }
    for (int e = tid; e < 32 * 32; e += 256) {
        int r = e >> 5, d = (e & 31) << 2;
        *(float4*)&Qs[r * 128 + d] = *(const float4*)&g_q[(size_t)(q0 + r) * DMODEL + base + d];
    }
    __syncthreads();

    int warp = tid >> 5, lane = tid & 31;
    int r0 = warp * 4;
    const float NI = neg_inf();
    bool act[4];
#pragma unroll
    for (int rr = 0; rr < 4; rr++) act[rr] = (g_mask[q0 + r0 + rr] == 1);

    const float* q0p = &Qs[(r0 + 0) * 128];
    const float* q1p = &Qs[(r0 + 1) * 128];
    const float* q2p = &Qs[(r0 + 2) * 128];
    const float* q3p = &Qs[(r0 + 3) * 128];
    const float* kp0 = &Ks[(lane) * 129];
    const float* kp1 = &Ks[(lane + 32) * 129];
    const float* kp2 = &Ks[(lane + 64) * 129];
    const float* kp3 = &Ks[(lane + 96) * 129];

    float a2[4][4];
#pragma unroll
    for (int m = 0; m < 4; m++)
#pragma unroll
        for (int rr = 0; rr < 4; rr++) a2[m][rr] = 0.f;
#pragma unroll 4
    for (int d = 0; d < 128; d++) {
        float kv0 = kp0[d], kv1 = kp1[d], kv2 = kp2[d], kv3 = kp3[d];
        float qv0 = q0p[d], qv1 = q1p[d], qv2 = q2p[d], qv3 = q3p[d];
        a2[0][0] = fmaf(kv0, qv0, a2[0][0]);
        a2[0][1] = fmaf(kv0, qv1, a2[0][1]);
        a2[0][2] = fmaf(kv0, qv2, a2[0][2]);
        a2[0][3] = fmaf(kv0, qv3, a2[0][3]);
        a2[1][0] = fmaf(kv1, qv0, a2[1][0]);
        a2[1][1] = fmaf(kv1, qv1, a2[1][1]);
        a2[1][2] = fmaf(kv1, qv2, a2[1][2]);
        a2[1][3] = fmaf(kv1, qv3, a2[1][3]);
        a2[2][0] = fmaf(kv2, qv0, a2[2][0]);
        a2[2][1] = fmaf(kv2, qv1, a2[2][1]);
        a2[2][2] = fmaf(kv2, qv2, a2[2][2]);
        a2[2][3] = fmaf(kv2, qv3, a2[2][3]);
        a2[3][0] = fmaf(kv3, qv0, a2[3][0]);
        a2[3][1] = fmaf(kv3, qv1, a2[3][1]);
        a2[3][2] = fmaf(kv3, qv2, a2[3][2]);
        a2[3][3] = fmaf(kv3, qv3, a2[3][3]);
    }
    float sv[4][4];  // [m][rr]
#pragma unroll
    for (int m = 0; m < 4; m++) {
        int j = lane + (m << 5);
        int k = (j < nc) ? cand[j] : -1;
        int mk = (k >= 0) ? g_mask[k] : 0;
#pragma unroll
        for (int rr = 0; rr < 4; rr++) {
            int q = q0 + r0 + rr;
            int dd = q - k;
            if (dd < 0) dd = -dd;
            bool ok = act[rr] && (k >= 0) && (mk != 0) && ((j >= 96) || (mk == 2) || (dd <= 32));
            sv[m][rr] = ok ? a2[m][rr] * SCALE_F : NI;
        }
    }
#pragma unroll
    for (int rr = 0; rr < 4; rr++) {
        int r = r0 + rr;
        float mx = fmaxf(fmaxf(sv[0][rr], sv[1][rr]), fmaxf(sv[2][rr], sv[3][rr]));
#pragma unroll
        for (int o = 16; o; o >>= 1) mx = fmaxf(mx, __shfl_xor_sync(0xffffffffu, mx, o));
        float p[4];
        float sum = 0.f;
#pragma unroll
        for (int m = 0; m < 4; m++) {
            p[m] = (sv[m][rr] == NI) ? 0.f : expf(sv[m][rr] - mx);
            sum += p[m];
        }
#pragma unroll
        for (int o = 16; o; o >>= 1) sum += __shfl_xor_sync(0xffffffffu, sum, o);
        if (act[rr]) {
            float inv = 1.f / sum;
#pragma unroll
            for (int m = 0; m < 4; m++) {
                int j = lane + (m << 5);
                probs[r * 132 + j] = p[m] * inv;
            }
        }
    }
    __syncthreads();
    {
        int r = tid >> 3, c0 = tid & 7;
        int q = q0 + r;
        if (g_mask[q] == 1) {
            const float* pr = &probs[r * 132];
            const float4* V4 = (const float4*)Vs;
#pragma unroll
            for (int u = 0; u < 4; u++) {
                int d4 = c0 + (u << 3);
                float x0 = 0.f, x1 = 0.f, x2 = 0.f, x3 = 0.f;
                for (int j = 0; j < nc; j++) {
                    float p = pr[j];
                    float4 v = V4[j * 33 + d4];
                    x0 = fmaf(p, v.x, x0);
                    x1 = fmaf(p, v.y, x1);
                    x2 = fmaf(p, v.z, x2);
                    x3 = fmaf(p, v.w, x3);
                }
                size_t off = (size_t)q * DMODEL + base + d4 * 4;
                store_hl2(ch, cl, off, x0, x1);
                store_hl2(ch, cl, off + 2, x2, x3);
            }
        }
    }
}

// ============================ attention: global rows (slab-parallel) ========
#define SMEM_GSC ((128 * 129 + 32 * 128) * 4)
__global__ __launch_bounds__(256) void ga_scores_kernel() {
    extern __shared__ float smf[];
    float* Ks = smf;
    float* Qs = Ks + 128 * 129;
    int slab = blockIdx.x, h = blockIdx.y, tid = threadIdx.x;
    int ng = g_nglob;
    for (int e = tid; e < 128 * 32; e += 256) {
        int j = e >> 5, d = (e & 31) << 2;
        float4 kv = *(const float4*)&g_k[(size_t)(slab * 128 + j) * DMODEL + h * DK + d];
        Ks[j * 129 + d] = kv.x;
        Ks[j * 129 + d + 1] = kv.y;
        Ks[j * 129 + d + 2] = kv.z;
        Ks[j * 129 + d + 3] = kv.w;
    }
    for (int e = tid; e < 32 * 32; e += 256) {
        int r = e >> 5, d = (e & 31) << 2;
        float4 qv = make_float4(0.f, 0.f, 0.f, 0.f);
        if (r < ng) qv = *(const float4*)&g_q[(size_t)g_globlist[r] * DMODEL + h * DK + d];
        *(float4*)&Qs[r * 128 + d] = qv;
    }
    __syncthreads();
    int kk = tid & 127, half = tid >> 7;
    int k = slab * 128 + kk;
    bool nonpad = (g_mask[k] != 0);
    for (int qi = half; qi < ng; qi += 2) {
        float sd = 0.f;
        const float* qp = &Qs[qi * 128];
        const float* kp = &Ks[kk * 129];
#pragma unroll 16
        for (int d = 0; d < 128; d++) sd += qp[d] * kp[d];
        g_gsc[((size_t)h * 32 + qi) * S + k] = nonpad ? sd * SCALE_F : neg_inf();
    }
}
__global__ __launch_bounds__(256) void ga_softmax_kernel() {
    int qi = blockIdx.x, h = blockIdx.y, tid = threadIdx.x;
    if (qi >= g_nglob) return;
    float* row = g_gsc + ((size_t)h * 32 + qi) * S;
    const float NI = neg_inf();
    float mx = NI;
    for (int k = tid; k < S; k += 256) mx = fmaxf(mx, row[k]);
    mx = blockMax256(mx);
    float sum = 0.f;
    for (int k = tid; k < S; k += 256) {
        float v = row[k];
        float p = (v == NI) ? 0.f : expf(v - mx);
        row[k] = p;
        sum += p;
    }
    sum = blockSum256(sum);
    float inv = 1.f / sum;
    for (int k = tid; k < S; k += 256) row[k] *= inv;
}
#define SMEM_GAV ((128 * 132 + 32 * 132) * 4)
__global__ __launch_bounds__(256) void ga_av_kernel() {
    extern __shared__ float smf[];
    float* Vs = smf;                // 128 x 132
    float* Ps = Vs + 128 * 132;     // 32 x 132
    int slab = blockIdx.x, h = blockIdx.y, tid = threadIdx.x;
    int ng = g_nglob;
    for (int e = tid; e < 128 * 32; e += 256) {
        int j = e >> 5, d = (e & 31) << 2;
        *(float4*)&Vs[j * 132 + d] =
            *(const float4*)&g_v[(size_t)(slab * 128 + j) * DMODEL + h * DK + d];
    }
    for (int e = tid; e < 32 * 32; e += 256) {
        int r = e >> 5, kk = (e & 31) << 2;
        float4 pv = make_float4(0.f, 0.f, 0.f, 0.f);
        if (r < ng) pv = *(const float4*)&g_gsc[((size_t)h * 32 + r) * S + slab * 128 + kk];
        *(float4*)&Ps[r * 132 + kk] = pv;
    }
    __syncthreads();
    int qi = tid >> 3, c0 = tid & 7;
    if (qi < ng) {
        const float* pp = &Ps[qi * 132];
        const float4* V4 = (const float4*)Vs;
#pragma unroll
        for (int u = 0; u < 4; u++) {
            int d4 = c0 + (u << 3);
            float x0 = 0.f, x1 = 0.f, x2 = 0.f, x3 = 0.f;
#pragma unroll 4
            for (int kk = 0; kk < 128; kk++) {
                float p = pp[kk];
                float4 v = V4[kk * 33 + d4];
                x0 = fmaf(p, v.x, x0);
                x1 = fmaf(p, v.y, x1);
                x2 = fmaf(p, v.z, x2);
                x3 = fmaf(p, v.w, x3);
            }
            float4 o = {x0, x1, x2, x3};
            *(float4*)&g_gpart[(((size_t)slab * NH + h) * 32 + qi) * DK + d4 * 4] = o;
        }
    }
}
__global__ __launch_bounds__(128) void ga_out_kernel(__half* __restrict__ ch,
                                                     __half* __restrict__ cl) {
    int qi = blockIdx.x, h = blockIdx.y, d = threadIdx.x;
    if (qi >= g_nglob) return;
    float s = 0.f;
#pragma unroll
    for (int slab = 0; slab < 16; slab++)
        s += g_gpart[(((size_t)slab * NH + h) * 32 + qi) * DK + d];
    int q = g_globlist[qi];
    store_hl1(ch, cl, (size_t)q * DMODEL + h * DK + d, s);
}

// ============================ driver ========================================
extern "C" void kernel_launch(void* const* d_in, const int* in_sizes, int n_in,
                              void* d_out, int out_size) {
    const int* Tp = (const int*)d_in[0];
    const float* enc = (const float*)d_in[1];
    const int* gidx = (const int*)d_in[2];
    const float* Wq = (const float*)d_in[3];
    const float* Wk = (const float*)d_in[4];
    const float* Wv = (const float*)d_in[5];
    const float* Wo = (const float*)d_in[6];
    const float* ln1g = (const float*)d_in[7];
    const float* ln1b = (const float*)d_in[8];
    const float* W1 = (const float*)d_in[9];
    const float* W2 = (const float*)d_in[10];
    const float* ln2g = (const float*)d_in[11];
    const float* ln2b = (const float*)d_in[12];
    float* out = (float*)d_out;

    cudaFuncSetAttribute(attn_local_kernel, cudaFuncAttributeMaxDynamicSharedMemorySize,
                         SMEM_LOCAL_BYTES);
    cudaFuncSetAttribute(ga_scores_kernel, cudaFuncAttributeMaxDynamicSharedMemorySize, SMEM_GSC);
    cudaFuncSetAttribute(ga_av_kernel, cudaFuncAttributeMaxDynamicSharedMemorySize, SMEM_GAV);
    cudaFuncSetAttribute(gemm_mma, cudaFuncAttributeMaxDynamicSharedMemorySize, GEMM_SMEM);

    float *px, *pq, *pk, *pv, *py;
    __half *pw, *pah, *pal, *phh, *phl;
    cudaGetSymbolAddress((void**)&px, g_x);
    cudaGetSymbolAddress((void**)&pq, g_q);
    cudaGetSymbolAddress((void**)&pk, g_k);
    cudaGetSymbolAddress((void**)&pv, g_v);
    cudaGetSymbolAddress((void**)&py, g_y);
    cudaGetSymbolAddress((void**)&pw, g_wt);
    cudaGetSymbolAddress((void**)&pah, g_ah);
    cudaGetSymbolAddress((void**)&pal, g_al);
    cudaGetSymbolAddress((void**)&phh, g_hh);
    cudaGetSymbolAddress((void**)&phl, g_hl);
    float* py1 = py + (size_t)S * DMODEL;

    const size_t M1 = 1024u * 1024u;

    // pediv(0), prep(1), tsplit_all(2), QKV gemm(3): profiler window -> gemm.
    pediv_kernel<<<2, 256>>>();
    prep_kernel<<<(S * DMODEL) / 256, 256>>>(enc);
    tsplit_all_kernel<<<dim3(64, 64, 24), dim3(32, 8)>>>(Wq, Wk, Wv, Wo, W1, W2, pw);
    gemm_mma<<<dim3(DMODEL / 128, S / 128, 3), 256, GEMM_SMEM>>>(
        S, DMODEL, DMODEL, pah, pal, pw, pq, pw + M1, pk, pw + 2 * M1, pv, 0, nullptr, nullptr,
        0);
    mask_all_kernel<<<1, 1024>>>(gidx, Tp);

    for (int l = 0; l < NLAYERS; l++) {
        size_t wo_ = (size_t)l * LSTRIDE;
        if (l > 0) {
            gemm_mma<<<dim3(DMODEL / 128, S / 128, 3), 256, GEMM_SMEM>>>(
                S, DMODEL, DMODEL, pah, pal, pw + wo_, pq, pw + wo_ + M1, pk, pw + wo_ + 2 * M1,
                pv, 0, nullptr, nullptr, 0);
        }

        vmean_part_kernel<<<dim3(DMODEL / 256, 16), 256>>>();
        attn_local_kernel<<<dim3(S / 32, NH), 256, SMEM_LOCAL_BYTES>>>(pah, pal);
        ga_scores_kernel<<<dim3(16, NH), 256, SMEM_GSC>>>();
        ga_softmax_kernel<<<dim3(32, NH), 256>>>();
        ga_av_kernel<<<dim3(16, NH), 256, SMEM_GAV>>>();
        ga_out_kernel<<<dim3(32, NH), 128>>>(pah, pal);
        attn_pad_kernel<<<dim3(DMODEL / 256, S), 256>>>(pah, pal);

        // output projection (split-K x2) + residual LN
        gemm_mma<<<dim3(DMODEL / 128, S / 128, 2), 256, GEMM_SMEM>>>(
            S, DMODEL, DMODEL, pah, pal, pw + wo_ + 3 * M1, py, nullptr, nullptr, nullptr,
            nullptr, 0, nullptr, nullptr, 1);
        ln_kernel<<<S / 8, 256>>>(py, py1, px, ln1g + l * DMODEL, ln1b + l * DMODEL, px, pah,
                                  pal);

        // FFN1 (hi/lo fp16 out), FFN2 (split-K x2) + residual LN
        gemm_mma<<<dim3(DFF / 128, S / 128, 1), 256, GEMM_SMEM>>>(
            S, DFF, DMODEL, pah, pal, pw + wo_ + 4 * M1, nullptr, nullptr, nullptr, nullptr,
            nullptr, 1, phh, phl, 0);
        gemm_mma<<<dim3(DMODEL / 128, S / 128, 2), 256, GEMM_SMEM>>>(
            S, DMODEL, DFF, phh, phl, pw + wo_ + 6 * M1, py, nullptr, nullptr, nullptr, nullptr,
            0, nullptr, nullptr, 1);
        ln_kernel<<<S / 8, 256>>>(py, py1, px, ln2g + l * DMODEL, ln2b + l * DMODEL,
                                  (l == NLAYERS - 1) ? out : px, pah, pal);
    }
}

// round 17
// speedup vs baseline: 4.4842x; 1.1000x over previous
#include <cuda_runtime.h>
#include <cuda_fp16.h>
#include <math.h>
#include <stdint.h>

#define S 2048
#define DMODEL 1024
#define DFF 2048
#define NH 8
#define DK 128
#define NLAYERS 4

static __device__ __forceinline__ float neg_inf() { return __int_as_float(0xff800000); }
#define SCALE_F 0.08838834764831845f  // 1/sqrt(128)

// ======================= PTX helpers (base sm_80+ features only) ============
__device__ __forceinline__ uint32_t smem_u32(const void* p) {
    uint32_t a;
    asm("{ .reg .u64 t; cvta.to.shared.u64 t, %1; cvt.u32.u64 %0, t; }" : "=r"(a) : "l"(p));
    return a;
}
__device__ __forceinline__ void cp16(uint32_t dst, const void* src) {
    asm volatile("cp.async.cg.shared.global [%0], [%1], 16;" ::"r"(dst), "l"(src));
}
#define CP_COMMIT() asm volatile("cp.async.commit_group;" ::: "memory")
#define CP_WAIT1() asm volatile("cp.async.wait_group 1;" ::: "memory")
#define CP_WAIT0() asm volatile("cp.async.wait_group 0;" ::: "memory")

__device__ __forceinline__ void ldmx4(uint32_t* r, uint32_t addr) {
    asm volatile("ldmatrix.sync.aligned.m8n8.x4.shared.b16 {%0,%1,%2,%3}, [%4];"
                 : "=r"(r[0]), "=r"(r[1]), "=r"(r[2]), "=r"(r[3])
                 : "r"(addr));
}
__device__ __forceinline__ void mma16816(float* d, const uint32_t* a, const uint32_t* b) {
    asm volatile(
        "mma.sync.aligned.m16n8k16.row.col.f32.f16.f16.f32 "
        "{%0,%1,%2,%3}, {%4,%5,%6,%7}, {%8,%9}, {%0,%1,%2,%3};"
        : "+f"(d[0]), "+f"(d[1]), "+f"(d[2]), "+f"(d[3])
        : "r"(a[0]), "r"(a[1]), "r"(a[2]), "r"(a[3]), "r"(b[0]), "r"(b[1]));
}
__device__ __forceinline__ void store_hl2(__half* Hh, __half* Hl, size_t off, float x, float y) {
    __half hx = __float2half_rn(x), hy = __float2half_rn(y);
    __half2 h;
    h.x = hx;
    h.y = hy;
    __half2 l;
    l.x = __float2half_rn(x - __half2float(hx));
    l.y = __float2half_rn(y - __half2float(hy));
    *(__half2*)(Hh + off) = h;
    *(__half2*)(Hl + off) = l;
}
__device__ __forceinline__ void store_hl1(__half* Hh, __half* Hl, size_t off, float x) {
    __half hx = __float2half_rn(x);
    Hh[off] = hx;
    Hl[off] = __float2half_rn(x - __half2float(hx));
}

// ============================ scratch globals ===============================
__device__ float g_x[S * DMODEL];
__device__ float g_q[S * DMODEL];
__device__ float g_k[S * DMODEL];
__device__ float g_v[S * DMODEL];
__device__ float g_y[2 * S * DMODEL];  // split-K partial outputs
__device__ float g_vpart[16][DMODEL];
__device__ int g_mask[S];  // 0 pad, 1 local, 2 global
__device__ int g_globlist[64];
__device__ int g_nglob;
__device__ float g_divhi[512];
__device__ float g_divlo[512];
__device__ float g_gsc[NH * 32 * S];
__device__ float g_gpart[16 * NH * 32 * DK];

#define LSTRIDE (8 * 1024 * 1024)
__device__ __half g_wt[NLAYERS * LSTRIDE];  // weights: single rn-fp16, transposed
__device__ __half g_ah[S * DMODEL];         // activations hi
__device__ __half g_al[S * DMODEL];         // activations lo
__device__ __half g_hh[S * DFF];            // ffn hidden hi
__device__ __half g_hl[S * DFF];            // ffn hidden lo

// ============================ reductions ====================================
static __device__ __forceinline__ float warpAllSum(float v) {
#pragma unroll
    for (int o = 16; o; o >>= 1) v += __shfl_xor_sync(0xffffffffu, v, o);
    return v;
}
static __device__ __forceinline__ float warpAllMax(float v) {
#pragma unroll
    for (int o = 16; o; o >>= 1) v = fmaxf(v, __shfl_xor_sync(0xffffffffu, v, o));
    return v;
}
static __device__ __forceinline__ float blockSum256(float v) {
    __shared__ float sh[8];
    int lane = threadIdx.x & 31, w = threadIdx.x >> 5;
    v = warpAllSum(v);
    __syncthreads();
    if (lane == 0) sh[w] = v;
    __syncthreads();
    if (w == 0) {
        float t = (lane < 8) ? sh[lane] : 0.f;
        t = warpAllSum(t);
        if (lane == 0) sh[0] = t;
    }
    __syncthreads();
    return sh[0];
}
static __device__ __forceinline__ float blockMax256(float v) {
    __shared__ float sh[8];
    int lane = threadIdx.x & 31, w = threadIdx.x >> 5;
    v = warpAllMax(v);
    __syncthreads();
    if (lane == 0) sh[w] = v;
    __syncthreads();
    if (w == 0) {
        float t = (lane < 8) ? sh[lane] : neg_inf();
        t = warpAllMax(t);
        if (lane == 0) sh[0] = t;
    }
    __syncthreads();
    return sh[0];
}

// ============================ prep / mask ===================================
__global__ void pediv_kernel() {
    int i = blockIdx.x * 256 + threadIdx.x;
    if (i < 512) {
        double dv = exp(-(double)(2 * i) * (9.210340371976184 / 1024.0));
        float h = (float)dv;
        g_divhi[i] = h;
        g_divlo[i] = (float)(dv - (double)h);
    }
}
__global__ void prep_kernel(const float* __restrict__ enc) {
    int idx = blockIdx.x * 256 + threadIdx.x;
    int s = idx >> 10, d = idx & 1023;
    int i = d >> 1;
    float hi = g_divhi[i], lo = g_divlo[i];
    float sf = (float)s;
    float h = sf * hi;
    float e = fmaf(sf, hi, -h);
    float t = fmaf(sf, lo, e);
    const float P2HI = 6.28318548202514648f;
    const float P2LO = -1.74845553e-7f;
    float n = rintf(h * 0.15915494309189535f);
    float r = fmaf(-n, P2HI, h);
    r = fmaf(-n, P2LO, r);
    r += t;
    float pe = (d & 1) ? cosf(r) : sinf(r);
    float x = 2.0f * enc[idx] + pe;
    g_x[idx] = x;
    store_hl1(g_ah, g_al, idx, x);
}
__global__ void mask_all_kernel(const int* __restrict__ gidx, const int* __restrict__ Tp) {
    __shared__ int gs[32];
    int tid = threadIdx.x;
    if (tid < 32) {
        int g = gidx[tid] / 15;
        gs[tid] = (g >= 0 && g < S) ? g : -1;
    }
    __syncthreads();
    int T = *Tp;
    for (int i = tid; i < S; i += 1024) {
        bool isg = false;
#pragma unroll
        for (int j = 0; j < 32; j++) isg |= (gs[j] == i);
        g_mask[i] = isg ? 2 : (i < T ? 1 : 0);
    }
    __syncthreads();
    if (tid < 32) {
        int lane = tid, cnt = 0;
        for (int base = 0; base < S; base += 32) {
            int m = (g_mask[base + lane] == 2);
            unsigned bal = __ballot_sync(0xffffffffu, m);
            if (m) g_globlist[cnt + __popc(bal & ((1u << lane) - 1u))] = base + lane;
            cnt += __popc(bal);
        }
        if (lane == 0) g_nglob = cnt;
    }
}

// ============================ fused weight transpose (rn fp16) ==============
__global__ void tsplit_all_kernel(const float* __restrict__ Wq, const float* __restrict__ Wk,
                                  const float* __restrict__ Wv, const float* __restrict__ Wo,
                                  const float* __restrict__ W1, const float* __restrict__ W2,
                                  __half* __restrict__ dst) {
    const size_t M1 = 1024u * 1024u;
    int z = blockIdx.z;
    int l = z / 6, m = z % 6;
    const float* W;
    int K, N;
    size_t doff = (size_t)l * LSTRIDE;
    if (m == 0) { W = Wq + l * M1; K = 1024; N = 1024; }
    else if (m == 1) { W = Wk + l * M1; K = 1024; N = 1024; doff += M1; }
    else if (m == 2) { W = Wv + l * M1; K = 1024; N = 1024; doff += 2 * M1; }
    else if (m == 3) { W = Wo + l * M1; K = 1024; N = 1024; doff += 3 * M1; }
    else if (m == 4) { W = W1 + l * 2 * M1; K = 1024; N = 2048; doff += 4 * M1; }
    else { W = W2 + l * 2 * M1; K = 2048; N = 1024; doff += 6 * M1; }
    int n0 = blockIdx.x * 32, k0 = blockIdx.y * 32;
    if (n0 >= N || k0 >= K) return;
    __shared__ float t[32][33];
    int tx = threadIdx.x, ty = threadIdx.y;
#pragma unroll
    for (int i = 0; i < 32; i += 8) t[ty + i][tx] = W[(size_t)(k0 + ty + i) * N + n0 + tx];
    __syncthreads();
#pragma unroll
    for (int i = 0; i < 32; i += 8) {
        dst[doff + (size_t)(n0 + ty + i) * K + k0 + tx] = __float2half_rn(t[tx][ty + i]);
    }
}

// ============================ fp16x2 HMMA GEMM ==============================
#define TSTRIDE 80
#define TILE_B (128 * TSTRIDE)
#define STAGE_B (3 * TILE_B)      // Ah, Al, B
#define GEMM_SMEM (3 * STAGE_B)   // 92160; x2 CTA = 184320 <= 227KB

__global__ __launch_bounds__(256, 2) void gemm_mma(
    int M, int N, int K, const __half* __restrict__ Ahi, const __half* __restrict__ Alo,
    const __half* B0, float* C0, const __half* B1, float* C1, const __half* B2, float* C2,
    int relu, __half* Hh, __half* Hl, int ksplit) {
    extern __shared__ char sm[];
    const __half* B;
    float* C;
    int z = blockIdx.z;
    int kbeg = 0, Keff = K;
    if (ksplit) {
        B = B0;
        Keff = K >> 1;
        kbeg = z * Keff;
        C = C0 + (size_t)z * M * N;
    } else if (z == 0) { B = B0; C = C0; }
    else if (z == 1) { B = B1; C = C1; }
    else { B = B2; C = C2; }

    uint32_t smb = smem_u32(sm);
    int tid = threadIdx.x, wid = tid >> 5, lane = tid & 31;
    int row0 = blockIdx.y * 128, col0 = blockIdx.x * 128;
    int wm = wid >> 1, wn = wid & 1;  // 4 x 2 warps; tile 32 x 64

    float acc[2][8][4];
#pragma unroll
    for (int a = 0; a < 2; a++)
#pragma unroll
        for (int b = 0; b < 8; b++)
#pragma unroll
            for (int c = 0; c < 4; c++) acc[a][b][c] = 0.f;

    int cid0 = tid * 2, cid1 = tid * 2 + 1;
    int lr0 = cid0 >> 2, lc0 = (cid0 & 3) * 16;
    int lr1 = cid1 >> 2, lc1 = (cid1 & 3) * 16;

    const __half* srcs[3] = {Ahi, Alo, B};
    int rbase[3] = {row0, row0, col0};
    const int nch = Keff / 32;

#pragma unroll
    for (int pc = 0; pc < 2; pc++) {
        uint32_t sb = smb + pc * STAGE_B;
        int k0 = kbeg + pc * 32;
#pragma unroll
        for (int t = 0; t < 3; t++) {
            const __half* src = srcs[t];
            uint32_t tb = sb + t * TILE_B;
            cp16(tb + lr0 * TSTRIDE + lc0, src + (size_t)(rbase[t] + lr0) * K + k0 + (lc0 >> 1));
            cp16(tb + lr1 * TSTRIDE + lc1, src + (size_t)(rbase[t] + lr1) * K + k0 + (lc1 >> 1));
        }
        CP_COMMIT();
    }

    for (int c = 0; c < nch; c++) {
        if (c + 1 < nch) {
            CP_WAIT1();
        } else {
            CP_WAIT0();
        }
        __syncthreads();
        if (c + 2 < nch) {
            int k0 = kbeg + (c + 2) * 32;
            uint32_t sb = smb + ((c + 2) % 3) * STAGE_B;
#pragma unroll
            for (int t = 0; t < 3; t++) {
                const __half* src = srcs[t];
                uint32_t tb = sb + t * TILE_B;
                cp16(tb + lr0 * TSTRIDE + lc0,
                     src + (size_t)(rbase[t] + lr0) * K + k0 + (lc0 >> 1));
                cp16(tb + lr1 * TSTRIDE + lc1,
                     src + (size_t)(rbase[t] + lr1) * K + k0 + (lc1 >> 1));
            }
            CP_COMMIT();
        }

        uint32_t base = smb + (c % 3) * STAGE_B;
        uint32_t aH = base, aL = base + TILE_B, bB = base + 2 * TILE_B;
        int arow = wm * 32 + (lane & 15);
        int brow = wn * 64 + (lane & 7) + ((lane >> 4) << 3);
#pragma unroll
        for (int ks = 0; ks < 2; ks++) {
            int akb = ks * 32 + ((lane >> 4) << 4);
            int bkb = ks * 32 + (((lane >> 3) & 1) << 4);
            uint32_t ah[2][4], al[2][4], bh[8][2];
#pragma unroll
            for (int mf = 0; mf < 2; mf++)
                ldmx4(ah[mf], aH + (uint32_t)(arow + mf * 16) * TSTRIDE + akb);
#pragma unroll
            for (int np = 0; np < 4; np++) {
                uint32_t r4[4];
                ldmx4(r4, bB + (uint32_t)(brow + np * 16) * TSTRIDE + bkb);
                bh[np * 2][0] = r4[0]; bh[np * 2][1] = r4[1];
                bh[np * 2 + 1][0] = r4[2]; bh[np * 2 + 1][1] = r4[3];
            }
#pragma unroll
            for (int mf = 0; mf < 2; mf++)
                ldmx4(al[mf], aL + (uint32_t)(arow + mf * 16) * TSTRIDE + akb);
#pragma unroll
            for (int mf = 0; mf < 2; mf++)
#pragma unroll
                for (int nf = 0; nf < 8; nf++) mma16816(acc[mf][nf], ah[mf], bh[nf]);
#pragma unroll
            for (int mf = 0; mf < 2; mf++)
#pragma unroll
                for (int nf = 0; nf < 8; nf++) mma16816(acc[mf][nf], al[mf], bh[nf]);
        }
    }

    int gr = row0 + wm * 32 + (lane >> 2);
    int gc = col0 + wn * 64 + (lane & 3) * 2;
#pragma unroll
    for (int mf = 0; mf < 2; mf++) {
#pragma unroll
        for (int nf = 0; nf < 8; nf++) {
            float* a4 = acc[mf][nf];
            if (relu) {
                a4[0] = fmaxf(a4[0], 0.f);
                a4[1] = fmaxf(a4[1], 0.f);
                a4[2] = fmaxf(a4[2], 0.f);
                a4[3] = fmaxf(a4[3], 0.f);
            }
            size_t o0 = (size_t)(gr + mf * 16) * N + gc + nf * 8;
            size_t o1 = (size_t)(gr + mf * 16 + 8) * N + gc + nf * 8;
            if (Hh) {
                store_hl2(Hh, Hl, o0, a4[0], a4[1]);
                store_hl2(Hh, Hl, o1, a4[2], a4[3]);
            } else {
                float2 v0 = {a4[0], a4[1]};
                float2 v1 = {a4[2], a4[3]};
                *(float2*)(C + o0) = v0;
                *(float2*)(C + o1) = v1;
            }
        }
    }
}

// ============================ LayerNorm (warp per row) ======================
__global__ __launch_bounds__(256) void ln_kernel(const float* __restrict__ y0,
                                                 const float* __restrict__ y1,
                                                 const float* __restrict__ xin,
                                                 const float* __restrict__ g,
                                                 const float* __restrict__ b,
                                                 float* __restrict__ out,
                                                 __half* __restrict__ oh,
                                                 __half* __restrict__ ol) {
    int warp = threadIdx.x >> 5, lane = threadIdx.x & 31;
    int s = blockIdx.x * 8 + warp;
    const float* y0r = y0 + (size_t)s * DMODEL;
    const float* y1r = y1 + (size_t)s * DMODEL;
    const float* xr = xin + (size_t)s * DMODEL;
    float4 v[8];
    float sum = 0.f;
#pragma unroll
    for (int i = 0; i < 8; i++) {
        int d = lane * 4 + i * 128;
        float4 a = *(const float4*)(y0r + d);
        float4 c2 = *(const float4*)(y1r + d);
        float4 xv = *(const float4*)(xr + d);
        v[i].x = (a.x + c2.x) + xv.x;
        v[i].y = (a.y + c2.y) + xv.y;
        v[i].z = (a.z + c2.z) + xv.z;
        v[i].w = (a.w + c2.w) + xv.w;
        sum += v[i].x + v[i].y + v[i].z + v[i].w;
    }
    float mean = warpAllSum(sum) * (1.f / 1024.f);
    float sq = 0.f;
#pragma unroll
    for (int i = 0; i < 8; i++) {
        float t0 = v[i].x - mean, t1 = v[i].y - mean, t2 = v[i].z - mean, t3 = v[i].w - mean;
        sq += t0 * t0 + t1 * t1 + t2 * t2 + t3 * t3;
    }
    float var = warpAllSum(sq) * (1.f / 1024.f);
    float inv = 1.f / sqrtf(var + 1e-5f);
    float* orow = out + (size_t)s * DMODEL;
#pragma unroll
    for (int i = 0; i < 8; i++) {
        int d = lane * 4 + i * 128;
        float4 gv = *(const float4*)(g + d);
        float4 bv = *(const float4*)(b + d);
        float4 o;
        o.x = gv.x * (v[i].x - mean) * inv + bv.x;
        o.y = gv.y * (v[i].y - mean) * inv + bv.y;
        o.z = gv.z * (v[i].z - mean) * inv + bv.z;
        o.w = gv.w * (v[i].w - mean) * inv + bv.w;
        *(float4*)(orow + d) = o;
        size_t off = (size_t)s * DMODEL + d;
        store_hl2(oh, ol, off, o.x, o.y);
        store_hl2(oh, ol, off + 2, o.z, o.w);
    }
}

// ============================ attention: pad rows ===========================
__global__ void vmean_part_kernel() {
    int d = blockIdx.x * 256 + threadIdx.x;
    int slab = blockIdx.y;
    float acc = 0.f;
    for (int s = slab * 128; s < (slab + 1) * 128; s++) acc += g_v[(size_t)s * DMODEL + d];
    g_vpart[slab][d] = acc;
}
__global__ void attn_pad_kernel(__half* __restrict__ ch, __half* __restrict__ cl) {
    int s = blockIdx.y;
    if (g_mask[s] != 0) return;
    int d = blockIdx.x * 256 + threadIdx.x;
    float a = 0.f;
#pragma unroll
    for (int i = 0; i < 16; i++) a += g_vpart[i][d];
    store_hl1(ch, cl, (size_t)s * DMODEL + d, a * (1.f / (float)S));
}

// ============================ attention: local rows =========================
#define SMEM_LOCAL_BYTES ((128 * 129 + 128 * 132 + 32 * 128 + 32 * 132) * 4 + 128 * 4)
__global__ __launch_bounds__(256) void attn_local_kernel(__half* __restrict__ ch,
                                                         __half* __restrict__ cl) {
    extern __shared__ float smf[];
    float* Ks = smf;                    // 128 x 129
    float* Vs = Ks + 128 * 129;         // 128 x 132
    float* Qs = Vs + 128 * 132;         // 32 x 128
    float* probs = Qs + 32 * 128;       // 32 x 132
    int* cand = (int*)(probs + 32 * 132);
    __shared__ int s_nc;
    __shared__ int s_any;

    int tid = threadIdx.x;
    int h = blockIdx.y, q0 = blockIdx.x * 32, base = h * DK;

    // early exit when no query row in this tile is a local (mask==1) row
    if (tid < 32) {
        unsigned bal = __ballot_sync(0xffffffffu, g_mask[q0 + tid] == 1);
        if (tid == 0) s_any = (int)bal;
    }
    __syncthreads();
    if (s_any == 0) return;

    if (tid < 96) {
        int k = q0 - 32 + tid;
        cand[tid] = (k >= 0 && k < S) ? k : -1;
    }
    if (tid == 0) {
        int cnt = 96, ng = g_nglob;
        for (int i = 0; i < ng; i++) {
            int g = g_globlist[i];
            if (g < q0 - 32 || g > q0 + 63) cand[cnt++] = g;
        }
        s_nc = cnt;
    }
    __syncthreads();
    int nc = s_nc;

    for (int e = tid; e < 128 * 32; e += 256) {
        int j = e >> 5, d = (e & 31) << 2;
        int k = (j < nc) ? cand[j] : -1;
        float4 kv = make_float4(0.f, 0.f, 0.f, 0.f), vv = kv;
        if (k >= 0) {
            kv = *(const float4*)&g_k[(size_t)k * DMODEL + base + d];
            vv = *(const float4*)&g_v[(size_t)k * DMODEL + base + d];
        }
        Ks[j * 129 + d] = kv.x;
        Ks[j * 129 + d + 1] = kv.y;
        Ks[j * 129 + d + 2] = kv.z;
        Ks[j * 129 + d + 3] = kv.w;
        *(float4*)&Vs[j * 132 + d] = vv;
    }
    for (int e = tid; e < 32 * 32; e += 256) {
        int r = e >> 5, d = (e & 31) << 2;
        *(float4*)&Qs[r * 128 + d] = *(const float4*)&g_q[(size_t)(q0 + r) * DMODEL + base + d];
    }
    __syncthreads();

    int warp = tid >> 5, lane = tid & 31;
    int r0 = warp * 4;
    const float NI = neg_inf();
    bool act[4];
#pragma unroll
    for (int rr = 0; rr < 4; rr++) act[rr] = (g_mask[q0 + r0 + rr] == 1);

    const float* q0p = &Qs[(r0 + 0) * 128];
    const float* q1p = &Qs[(r0 + 1) * 128];
    const float* q2p = &Qs[(r0 + 2) * 128];
    const float* q3p = &Qs[(r0 + 3) * 128];
    const float* kp0 = &Ks[(lane) * 129];
    const float* kp1 = &Ks[(lane + 32) * 129];
    const float* kp2 = &Ks[(lane + 64) * 129];
    const float* kp3 = &Ks[(lane + 96) * 129];

    float a2[4][4];
#pragma unroll
    for (int m = 0; m < 4; m++)
#pragma unroll
        for (int rr = 0; rr < 4; rr++) a2[m][rr] = 0.f;
#pragma unroll 4
    for (int d = 0; d < 128; d++) {
        float kv0 = kp0[d], kv1 = kp1[d], kv2 = kp2[d], kv3 = kp3[d];
        float qv0 = q0p[d], qv1 = q1p[d], qv2 = q2p[d], qv3 = q3p[d];
        a2[0][0] = fmaf(kv0, qv0, a2[0][0]);
        a2[0][1] = fmaf(kv0, qv1, a2[0][1]);
        a2[0][2] = fmaf(kv0, qv2, a2[0][2]);
        a2[0][3] = fmaf(kv0, qv3, a2[0][3]);
        a2[1][0] = fmaf(kv1, qv0, a2[1][0]);
        a2[1][1] = fmaf(kv1, qv1, a2[1][1]);
        a2[1][2] = fmaf(kv1, qv2, a2[1][2]);
        a2[1][3] = fmaf(kv1, qv3, a2[1][3]);
        a2[2][0] = fmaf(kv2, qv0, a2[2][0]);
        a2[2][1] = fmaf(kv2, qv1, a2[2][1]);
        a2[2][2] = fmaf(kv2, qv2, a2[2][2]);
        a2[2][3] = fmaf(kv2, qv3, a2[2][3]);
        a2[3][0] = fmaf(kv3, qv0, a2[3][0]);
        a2[3][1] = fmaf(kv3, qv1, a2[3][1]);
        a2[3][2] = fmaf(kv3, qv2, a2[3][2]);
        a2[3][3] = fmaf(kv3, qv3, a2[3][3]);
    }
    float sv[4][4];  // [m][rr]
#pragma unroll
    for (int m = 0; m < 4; m++) {
        int j = lane + (m << 5);
        int k = (j < nc) ? cand[j] : -1;
        int mk = (k >= 0) ? g_mask[k] : 0;
#pragma unroll
        for (int rr = 0; rr < 4; rr++) {
            int q = q0 + r0 + rr;
            int dd = q - k;
            if (dd < 0) dd = -dd;
            bool ok = act[rr] && (k >= 0) && (mk != 0) && ((j >= 96) || (mk == 2) || (dd <= 32));
            sv[m][rr] = ok ? a2[m][rr] * SCALE_F : NI;
        }
    }
#pragma unroll
    for (int rr = 0; rr < 4; rr++) {
        int r = r0 + rr;
        float mx = fmaxf(fmaxf(sv[0][rr], sv[1][rr]), fmaxf(sv[2][rr], sv[3][rr]));
#pragma unroll
        for (int o = 16; o; o >>= 1) mx = fmaxf(mx, __shfl_xor_sync(0xffffffffu, mx, o));
        float p[4];
        float sum = 0.f;
#pragma unroll
        for (int m = 0; m < 4; m++) {
            p[m] = (sv[m][rr] == NI) ? 0.f : expf(sv[m][rr] - mx);
            sum += p[m];
        }
#pragma unroll
        for (int o = 16; o; o >>= 1) sum += __shfl_xor_sync(0xffffffffu, sum, o);
        if (act[rr]) {
            float inv = 1.f / sum;
#pragma unroll
            for (int m = 0; m < 4; m++) {
                int j = lane + (m << 5);
                probs[r * 132 + j] = p[m] * inv;
            }
        }
    }
    __syncthreads();
    // AV remap: thread = (r-quad, d4). V4[j] serves 4 query rows; probs
    // broadcast across the 32 d4 lanes. Per-(q,d) j-order unchanged.
    {
        int r4 = tid >> 5, d4 = tid & 31;
        int rb = r4 * 4;
        const float* p0 = &probs[(rb + 0) * 132];
        const float* p1 = &probs[(rb + 1) * 132];
        const float* p2 = &probs[(rb + 2) * 132];
        const float* p3 = &probs[(rb + 3) * 132];
        const float4* V4 = (const float4*)Vs;
        float4 a0 = make_float4(0.f, 0.f, 0.f, 0.f), a1 = a0, a2v = a0, a3 = a0;
        for (int j = 0; j < nc; j++) {
            float4 v = V4[j * 33 + d4];
            float pp0 = p0[j], pp1 = p1[j], pp2 = p2[j], pp3 = p3[j];
            a0.x = fmaf(pp0, v.x, a0.x);
            a0.y = fmaf(pp0, v.y, a0.y);
            a0.z = fmaf(pp0, v.z, a0.z);
            a0.w = fmaf(pp0, v.w, a0.w);
            a1.x = fmaf(pp1, v.x, a1.x);
            a1.y = fmaf(pp1, v.y, a1.y);
            a1.z = fmaf(pp1, v.z, a1.z);
            a1.w = fmaf(pp1, v.w, a1.w);
            a2v.x = fmaf(pp2, v.x, a2v.x);
            a2v.y = fmaf(pp2, v.y, a2v.y);
            a2v.z = fmaf(pp2, v.z, a2v.z);
            a2v.w = fmaf(pp2, v.w, a2v.w);
            a3.x = fmaf(pp3, v.x, a3.x);
            a3.y = fmaf(pp3, v.y, a3.y);
            a3.z = fmaf(pp3, v.z, a3.z);
            a3.w = fmaf(pp3, v.w, a3.w);
        }
        float4 accs[4] = {a0, a1, a2v, a3};
#pragma unroll
        for (int i = 0; i < 4; i++) {
            int q = q0 + rb + i;
            if (g_mask[q] == 1) {
                size_t off = (size_t)q * DMODEL + base + d4 * 4;
                store_hl2(ch, cl, off, accs[i].x, accs[i].y);
                store_hl2(ch, cl, off + 2, accs[i].z, accs[i].w);
            }
        }
    }
}

// ============================ attention: global rows (slab-parallel) ========
#define SMEM_GSC ((128 * 129 + 32 * 128) * 4)
__global__ __launch_bounds__(256) void ga_scores_kernel() {
    extern __shared__ float smf[];
    float* Ks = smf;
    float* Qs = Ks + 128 * 129;
    int slab = blockIdx.x, h = blockIdx.y, tid = threadIdx.x;
    int ng = g_nglob;
    for (int e = tid; e < 128 * 32; e += 256) {
        int j = e >> 5, d = (e & 31) << 2;
        float4 kv = *(const float4*)&g_k[(size_t)(slab * 128 + j) * DMODEL + h * DK + d];
        Ks[j * 129 + d] = kv.x;
        Ks[j * 129 + d + 1] = kv.y;
        Ks[j * 129 + d + 2] = kv.z;
        Ks[j * 129 + d + 3] = kv.w;
    }
    for (int e = tid; e < 32 * 32; e += 256) {
        int r = e >> 5, d = (e & 31) << 2;
        float4 qv = make_float4(0.f, 0.f, 0.f, 0.f);
        if (r < ng) qv = *(const float4*)&g_q[(size_t)g_globlist[r] * DMODEL + h * DK + d];
        *(float4*)&Qs[r * 128 + d] = qv;
    }
    __syncthreads();
    int kk = tid & 127, half = tid >> 7;
    int k = slab * 128 + kk;
    bool nonpad = (g_mask[k] != 0);
    for (int qi = half; qi < ng; qi += 2) {
        float sd = 0.f;
        const float* qp = &Qs[qi * 128];
        const float* kp = &Ks[kk * 129];
#pragma unroll 16
        for (int d = 0; d < 128; d++) sd += qp[d] * kp[d];
        g_gsc[((size_t)h * 32 + qi) * S + k] = nonpad ? sd * SCALE_F : neg_inf();
    }
}
__global__ __launch_bounds__(256) void ga_softmax_kernel() {
    int qi = blockIdx.x, h = blockIdx.y, tid = threadIdx.x;
    if (qi >= g_nglob) return;
    float* row = g_gsc + ((size_t)h * 32 + qi) * S;
    const float NI = neg_inf();
    float mx = NI;
    for (int k = tid; k < S; k += 256) mx = fmaxf(mx, row[k]);
    mx = blockMax256(mx);
    float sum = 0.f;
    for (int k = tid; k < S; k += 256) {
        float v = row[k];
        float p = (v == NI) ? 0.f : expf(v - mx);
        row[k] = p;
        sum += p;
    }
    sum = blockSum256(sum);
    float inv = 1.f / sum;
    for (int k = tid; k < S; k += 256) row[k] *= inv;
}
#define SMEM_GAV ((128 * 132 + 32 * 132) * 4)
__global__ __launch_bounds__(256) void ga_av_kernel() {
    extern __shared__ float smf[];
    float* Vs = smf;                // 128 x 132
    float* Ps = Vs + 128 * 132;     // 32 x 132
    int slab = blockIdx.x, h = blockIdx.y, tid = threadIdx.x;
    int ng = g_nglob;
    for (int e = tid; e < 128 * 32; e += 256) {
        int j = e >> 5, d = (e & 31) << 2;
        *(float4*)&Vs[j * 132 + d] =
            *(const float4*)&g_v[(size_t)(slab * 128 + j) * DMODEL + h * DK + d];
    }
    for (int e = tid; e < 32 * 32; e += 256) {
        int r = e >> 5, kk = (e & 31) << 2;
        float4 pv = make_float4(0.f, 0.f, 0.f, 0.f);
        if (r < ng) pv = *(const float4*)&g_gsc[((size_t)h * 32 + r) * S + slab * 128 + kk];
        *(float4*)&Ps[r * 132 + kk] = pv;
    }
    __syncthreads();
    // remap: thread = (qi-quad, d4); V4[kk] serves 4 queries, probs broadcast.
    {
        int q4 = tid >> 5, d4 = tid & 31;
        int qb = q4 * 4;
        const float* p0 = &Ps[(qb + 0) * 132];
        const float* p1 = &Ps[(qb + 1) * 132];
        const float* p2 = &Ps[(qb + 2) * 132];
        const float* p3 = &Ps[(qb + 3) * 132];
        const float4* V4 = (const float4*)Vs;
        float4 a0 = make_float4(0.f, 0.f, 0.f, 0.f), a1 = a0, a2 = a0, a3 = a0;
#pragma unroll 4
        for (int kk = 0; kk < 128; kk++) {
            float4 v = V4[kk * 33 + d4];
            float pp0 = p0[kk], pp1 = p1[kk], pp2 = p2[kk], pp3 = p3[kk];
            a0.x = fmaf(pp0, v.x, a0.x);
            a0.y = fmaf(pp0, v.y, a0.y);
            a0.z = fmaf(pp0, v.z, a0.z);
            a0.w = fmaf(pp0, v.w, a0.w);
            a1.x = fmaf(pp1, v.x, a1.x);
            a1.y = fmaf(pp1, v.y, a1.y);
            a1.z = fmaf(pp1, v.z, a1.z);
            a1.w = fmaf(pp1, v.w, a1.w);
            a2.x = fmaf(pp2, v.x, a2.x);
            a2.y = fmaf(pp2, v.y, a2.y);
            a2.z = fmaf(pp2, v.z, a2.z);
            a2.w = fmaf(pp2, v.w, a2.w);
            a3.x = fmaf(pp3, v.x, a3.x);
            a3.y = fmaf(pp3, v.y, a3.y);
            a3.z = fmaf(pp3, v.z, a3.z);
            a3.w = fmaf(pp3, v.w, a3.w);
        }
        float4 accs[4] = {a0, a1, a2, a3};
#pragma unroll
        for (int i = 0; i < 4; i++) {
            int qi = qb + i;
            if (qi < ng) {
                *(float4*)&g_gpart[(((size_t)slab * NH + h) * 32 + qi) * DK + d4 * 4] = accs[i];
            }
        }
    }
}
__global__ __launch_bounds__(128) void ga_out_kernel(__half* __restrict__ ch,
                                                     __half* __restrict__ cl) {
    int qi = blockIdx.x, h = blockIdx.y, d = threadIdx.x;
    if (qi >= g_nglob) return;
    float s = 0.f;
#pragma unroll
    for (int slab = 0; slab < 16; slab++)
        s += g_gpart[(((size_t)slab * NH + h) * 32 + qi) * DK + d];
    int q = g_globlist[qi];
    store_hl1(ch, cl, (size_t)q * DMODEL + h * DK + d, s);
}

// ============================ driver ========================================
extern "C" void kernel_launch(void* const* d_in, const int* in_sizes, int n_in,
                              void* d_out, int out_size) {
    const int* Tp = (const int*)d_in[0];
    const float* enc = (const float*)d_in[1];
    const int* gidx = (const int*)d_in[2];
    const float* Wq = (const float*)d_in[3];
    const float* Wk = (const float*)d_in[4];
    const float* Wv = (const float*)d_in[5];
    const float* Wo = (const float*)d_in[6];
    const float* ln1g = (const float*)d_in[7];
    const float* ln1b = (const float*)d_in[8];
    const float* W1 = (const float*)d_in[9];
    const float* W2 = (const float*)d_in[10];
    const float* ln2g = (const float*)d_in[11];
    const float* ln2b = (const float*)d_in[12];
    float* out = (float*)d_out;

    cudaFuncSetAttribute(attn_local_kernel, cudaFuncAttributeMaxDynamicSharedMemorySize,
                         SMEM_LOCAL_BYTES);
    cudaFuncSetAttribute(ga_scores_kernel, cudaFuncAttributeMaxDynamicSharedMemorySize, SMEM_GSC);
    cudaFuncSetAttribute(ga_av_kernel, cudaFuncAttributeMaxDynamicSharedMemorySize, SMEM_GAV);
    cudaFuncSetAttribute(gemm_mma, cudaFuncAttributeMaxDynamicSharedMemorySize, GEMM_SMEM);

    float *px, *pq, *pk, *pv, *py;
    __half *pw, *pah, *pal, *phh, *phl;
    cudaGetSymbolAddress((void**)&px, g_x);
    cudaGetSymbolAddress((void**)&pq, g_q);
    cudaGetSymbolAddress((void**)&pk, g_k);
    cudaGetSymbolAddress((void**)&pv, g_v);
    cudaGetSymbolAddress((void**)&py, g_y);
    cudaGetSymbolAddress((void**)&pw, g_wt);
    cudaGetSymbolAddress((void**)&pah, g_ah);
    cudaGetSymbolAddress((void**)&pal, g_al);
    cudaGetSymbolAddress((void**)&phh, g_hh);
    cudaGetSymbolAddress((void**)&phl, g_hl);
    float* py1 = py + (size_t)S * DMODEL;

    const size_t M1 = 1024u * 1024u;

    // pediv(0), prep(1), tsplit_all(2), QKV gemm(3): profiler window -> gemm.
    pediv_kernel<<<2, 256>>>();
    prep_kernel<<<(S * DMODEL) / 256, 256>>>(enc);
    tsplit_all_kernel<<<dim3(64, 64, 24), dim3(32, 8)>>>(Wq, Wk, Wv, Wo, W1, W2, pw);
    gemm_mma<<<dim3(DMODEL / 128, S / 128, 3), 256, GEMM_SMEM>>>(
        S, DMODEL, DMODEL, pah, pal, pw, pq, pw + M1, pk, pw + 2 * M1, pv, 0, nullptr, nullptr,
        0);
    mask_all_kernel<<<1, 1024>>>(gidx, Tp);

    for (int l = 0; l < NLAYERS; l++) {
        size_t wo_ = (size_t)l * LSTRIDE;
        if (l > 0) {
            gemm_mma<<<dim3(DMODEL / 128, S / 128, 3), 256, GEMM_SMEM>>>(
                S, DMODEL, DMODEL, pah, pal, pw + wo_, pq, pw + wo_ + M1, pk, pw + wo_ + 2 * M1,
                pv, 0, nullptr, nullptr, 0);
        }

        vmean_part_kernel<<<dim3(DMODEL / 256, 16), 256>>>();
        attn_local_kernel<<<dim3(S / 32, NH), 256, SMEM_LOCAL_BYTES>>>(pah, pal);
        ga_scores_kernel<<<dim3(16, NH), 256, SMEM_GSC>>>();
        ga_softmax_kernel<<<dim3(32, NH), 256>>>();
        ga_av_kernel<<<dim3(16, NH), 256, SMEM_GAV>>>();
        ga_out_kernel<<<dim3(32, NH), 128>>>(pah, pal);
        attn_pad_kernel<<<dim3(DMODEL / 256, S), 256>>>(pah, pal);

        // output projection (split-K x2) + residual LN
        gemm_mma<<<dim3(DMODEL / 128, S / 128, 2), 256, GEMM_SMEM>>>(
            S, DMODEL, DMODEL, pah, pal, pw + wo_ + 3 * M1, py, nullptr, nullptr, nullptr,
            nullptr, 0, nullptr, nullptr, 1);
        ln_kernel<<<S / 8, 256>>>(py, py1, px, ln1g + l * DMODEL, ln1b + l * DMODEL, px, pah,
                                  pal);

        // FFN1 (hi/lo fp16 out), FFN2 (split-K x2) + residual LN
        gemm_mma<<<dim3(DFF / 128, S / 128, 1), 256, GEMM_SMEM>>>(
            S, DFF, DMODEL, pah, pal, pw + wo_ + 4 * M1, nullptr, nullptr, nullptr, nullptr,
            nullptr, 1, phh, phl, 0);
        gemm_mma<<<dim3(DMODEL / 128, S / 128, 2), 256, GEMM_SMEM>>>(
            S, DMODEL, DFF, phh, phl, pw + wo_ + 6 * M1, py, nullptr, nullptr, nullptr, nullptr,
            0, nullptr, nullptr, 1);
        ln_kernel<<<S / 8, 256>>>(py, py1, px, ln2g + l * DMODEL, ln2b + l * DMODEL,
                                  (l == NLAYERS - 1) ? out : px, pah, pal);
    }
}